// round 10
// baseline (speedup 1.0000x reference)
#include <cuda_runtime.h>
#include <cuda_bf16.h>
#include <math.h>

#define DIMD   1024
#define HEADS  16
#define DHEAD  64
#define HIDD   2048
#define NEXP   8
#define NB     2
#define SLEN   1024
#define NTOK   (NB*SLEN)
#define INNERD (HEADS*DHEAD)
#define NEGMIN (-3.402823466e38f)
#define SCL2   0.18033688011112042f   // 0.125 * log2(e)
#define TSPART 8

typedef __nv_bfloat16 bf;

// ---------------- device scratch ----------------
__device__ float g_proj[NTOK*DIMD];
__device__ float g_x1[NTOK*DIMD];
__device__ float g_x2[NTOK*DIMD];
__device__ float g_contrib[(size_t)NEXP*NTOK*DIMD];
__device__ float g_wslot[NEXP*NTOK];
__device__ int   g_tok[NEXP*NTOK];
__device__ int   g_inv[NTOK*2];
__device__ int   g_cnt[NEXP];
__device__ float g_tsumP[NEXP*NB*TSPART*DIMD];
__device__ bf g_xh[NTOK*DIMD],  g_xl[NTOK*DIMD];
__device__ bf g_eh[NTOK*DIMD],  g_el[NTOK*DIMD];
__device__ bf g_awh[8*DIMD*INNERD], g_awl[8*DIMD*INNERD];
__device__ bf g_w13h[(size_t)NEXP*2*HIDD*DIMD], g_w13l[(size_t)NEXP*2*HIDD*DIMD];
__device__ bf g_w2h[(size_t)NEXP*HIDD*DIMD], g_w2l[(size_t)NEXP*HIDD*DIMD];
__device__ bf g_qkh[NTOK*2*INNERD], g_qkl[NTOK*2*INNERD];
__device__ bf g_vth[NTOK*INNERD], g_vtl[NTOK*INNERD];
__device__ bf g_ath[NTOK*INNERD], g_atl[NTOK*INNERD];
__device__ bf g_x1h[NTOK*DIMD], g_x1l[NTOK*DIMD];
__device__ bf g_x2h[NTOK*DIMD], g_x2l[NTOK*DIMD];
__device__ bf g_gh[(size_t)NEXP*NTOK*HIDD], g_gl[(size_t)NEXP*NTOK*HIDD];
__device__ unsigned char g_msrc[NTOK];
__device__ unsigned char g_mtgt[NTOK];
__device__ unsigned char g_mmid[NTOK];
__device__ int g_mtype;

// ---------------- PTX helpers ----------------
__device__ __forceinline__ unsigned smem_u32(const void* p) {
    return (unsigned)__cvta_generic_to_shared(p);
}
__device__ __forceinline__ void cp16(unsigned d, const void* s, bool v) {
    if (v) asm volatile("cp.async.ca.shared.global [%0], [%1], 16;\n" :: "r"(d), "l"(s) : "memory");
    else   asm volatile("cp.async.ca.shared.global [%0], [%1], 16, 0;\n" :: "r"(d), "l"(s) : "memory");
}
#define CP_COMMIT asm volatile("cp.async.commit_group;\n" ::: "memory")
#define CP_WAIT0  asm volatile("cp.async.wait_group 0;\n" ::: "memory")
#define CP_WAIT1  asm volatile("cp.async.wait_group 1;\n" ::: "memory")

#define LDSM_X4(d0, d1, d2, d3, a) \
    asm volatile("ldmatrix.sync.aligned.m8n8.x4.shared.b16 {%0,%1,%2,%3}, [%4];" \
                 : "=r"(d0), "=r"(d1), "=r"(d2), "=r"(d3) : "r"(a))

#define MMA_OP(c, a, b) \
    asm volatile("mma.sync.aligned.m16n8k16.row.col.f32.bf16.bf16.f32 " \
                 "{%0,%1,%2,%3},{%4,%5,%6,%7},{%8,%9},{%0,%1,%2,%3};" \
                 : "+f"((c)[0]), "+f"((c)[1]), "+f"((c)[2]), "+f"((c)[3]) \
                 : "r"((a)[0]), "r"((a)[1]), "r"((a)[2]), "r"((a)[3]), \
                   "r"((b)[0]), "r"((b)[1]))

__device__ __forceinline__ void pack2(float x, float y, unsigned& hi, unsigned& lo) {
    bf hx = __float2bfloat16(x), hy = __float2bfloat16(y);
    __nv_bfloat162 th; th.x = hx; th.y = hy;
    hi = *(unsigned*)&th;
    __nv_bfloat162 tl;
    tl.x = __float2bfloat16(x - __bfloat162float(hx));
    tl.y = __float2bfloat16(y - __bfloat162float(hy));
    lo = *(unsigned*)&tl;
}

// ---------------- mask detection / conversion ----------------
__global__ void k_detect(const unsigned char* __restrict__ tgt) {
    __shared__ int has_gt1, has_off;
    if (threadIdx.x == 0) { has_gt1 = 0; has_off = 0; }
    if (threadIdx.x < NEXP) g_cnt[threadIdx.x] = 0;
    __syncthreads();
    for (int j = threadIdx.x; j < NTOK; j += blockDim.x) {
        unsigned char v = tgt[j];
        if (v > 1) atomicOr(&has_gt1, 1);
        else if (v && (j & 3)) atomicOr(&has_off, 1);
    }
    __syncthreads();
    if (threadIdx.x == 0)
        g_mtype = has_gt1 ? 2 : (has_off ? 0 : 1);
}

__global__ void k_cvtmask(const void* __restrict__ s0, const void* __restrict__ s1,
                          const void* __restrict__ s2) {
    int t = g_mtype;
    int stride = gridDim.x * blockDim.x;
    for (int j = blockIdx.x * blockDim.x + threadIdx.x; j < NTOK; j += stride) {
        unsigned char a, b, c;
        if (t == 1) {
            a = ((const int*)s0)[j] != 0;
            b = ((const int*)s1)[j] != 0;
            c = ((const int*)s2)[j] != 0;
        } else if (t == 2) {
            a = ((const float*)s0)[j] != 0.f;
            b = ((const float*)s1)[j] != 0.f;
            c = ((const float*)s2)[j] != 0.f;
        } else {
            a = ((const unsigned char*)s0)[j];
            b = ((const unsigned char*)s1)[j];
            c = ((const unsigned char*)s2)[j];
        }
        g_msrc[j] = a; g_mtgt[j] = b; g_mmid[j] = c;
    }
}

// ---------------- conversion kernels ----------------
__global__ void k_cvtA(const float* __restrict__ s, bf* __restrict__ dh, bf* __restrict__ dl, int n4)
{
    int stride = gridDim.x * blockDim.x;
    for (int i = blockIdx.x * blockDim.x + threadIdx.x; i < n4; i += stride) {
        float4 v = ((const float4*)s)[i];
        float vv[4] = {v.x, v.y, v.z, v.w};
        bf h[4], l[4];
        #pragma unroll
        for (int j = 0; j < 4; j++) {
            h[j] = __float2bfloat16(vv[j]);
            l[j] = __float2bfloat16(vv[j] - __bfloat162float(h[j]));
        }
        ((ushort4*)dh)[i] = *(ushort4*)h;
        ((ushort4*)dl)[i] = *(ushort4*)l;
    }
}

// transpose-convert with optional output-row interleave:
// dst row = nn * rowMul + rowAdd
__global__ void k_cvtT(const float* __restrict__ src, bf* __restrict__ dh, bf* __restrict__ dl,
                       int Kd, int Nd, long long sSrc, long long sDst, int rowMul, int rowAdd)
{
    int z = blockIdx.z;
    src += (long long)z * sSrc; dh += (long long)z * sDst; dl += (long long)z * sDst;
    __shared__ float t[32][33];
    int k0 = blockIdx.y * 32, n0 = blockIdx.x * 32;
    #pragma unroll
    for (int i = 0; i < 4; i++) {
        int kk = k0 + threadIdx.y + i * 8;
        t[threadIdx.y + i * 8][threadIdx.x] = src[(long long)kk * Nd + n0 + threadIdx.x];
    }
    __syncthreads();
    #pragma unroll
    for (int i = 0; i < 4; i++) {
        int nn = n0 + threadIdx.y + i * 8;
        float v = t[threadIdx.x][threadIdx.y + i * 8];
        bf h = __float2bfloat16(v);
        long long dr = (long long)nn * rowMul + rowAdd;
        dh[dr * Kd + k0 + threadIdx.x] = h;
        dl[dr * Kd + k0 + threadIdx.x] = __float2bfloat16(v - __bfloat162float(h));
    }
}

// ---------------- bf16-plane tensor-core GEMM (ldmatrix + 3-stage pipeline) ----------------
#define LDS_ 40
#define NSTG 3
#define OFFA(st, pl) (((st)*2 + (pl)) * 128 * LDS_ * 2)
#define OFFB(st, pl) (NSTG*2*128*LDS_*2 + ((st)*2 + (pl)) * 128 * LDS_ * 2)
#define BG_SROW (2 * NSTG*2*128*LDS_*2)
#define BG_SMEM (BG_SROW + 512 + 64)

__global__ void __launch_bounds__(256) k_bgemm(
    const bf* __restrict__ Ah, const bf* __restrict__ Al,
    const bf* __restrict__ Bh, const bf* __restrict__ Bl,
    float* __restrict__ C, bf* __restrict__ Ch, bf* __restrict__ Cl,
    int M, int N, int K, int lda, int ldb, int ldc,
    long long sA1, long long sA2, long long sB1, long long sB2,
    long long sC1, long long sC2, int bdiv, int zmaps, int swiglu,
    const float* __restrict__ bias,
    const int* __restrict__ rowmapA, const int* __restrict__ rowmapC,
    const float* __restrict__ rowscale, const int* __restrict__ cntPtr)
{
    int z = blockIdx.z;
    long long ao = (long long)(z / bdiv) * sA2 + (long long)(z % bdiv) * sA1;
    long long bo = (long long)(z / bdiv) * sB2 + (long long)(z % bdiv) * sB1;
    long long co = (long long)(z / bdiv) * sC2 + (long long)(z % bdiv) * sC1;
    const bf* Ahp = Ah + ao; const bf* Alp = Al + ao;
    const bf* Bhp = Bh + bo; const bf* Blp = Bl + bo;
    float* Cp = C ? C + co : nullptr;
    bf* Chp = Ch ? Ch + co : nullptr;
    bf* Clp = Cl ? Cl + co : nullptr;
    if (zmaps) {
        if (rowmapA) rowmapA += z * NTOK;
        if (rowmapC) rowmapC += z * NTOK;
        if (rowscale) rowscale += z * NTOK;
        if (cntPtr) cntPtr += z;
    }
    int Meff = M;
    if (cntPtr) { int c = *cntPtr; Meff = c < M ? c : M; }
    int m0 = blockIdx.y * 128;
    if (m0 >= Meff) return;
    int n0 = blockIdx.x * 128;

    extern __shared__ __align__(16) char dyn[];
    unsigned sb = smem_u32(dyn);
    int* sRow = (int*)(dyn + BG_SROW);

    int tid = threadIdx.x, lane = tid & 31, warp = tid >> 5;
    int warp_n = warp & 3, warp_m = warp >> 2;
    int lr = lane >> 2, lk = (lane & 3) * 2;
    int quad = lane >> 3, rin = lane & 7;

    for (int r = tid; r < 128; r += 256) {
        int gm = m0 + r;
        sRow[r] = (gm < Meff) ? (rowmapA ? rowmapA[gm] : gm) : 0;
    }
    __syncthreads();

    int a_r = rin + ((quad & 1) ? 8 : 0);
    int a_c = (quad & 2) ? 8 : 0;
    int b_r = rin + ((quad >> 1) ? 8 : 0);
    int b_c = (quad & 1) ? 8 : 0;
    int aoff[4], boff[2];
    #pragma unroll
    for (int tm = 0; tm < 4; tm++)
        aoff[tm] = ((warp_m * 64 + tm * 16 + a_r) * LDS_ + a_c) * 2;
    #pragma unroll
    for (int p = 0; p < 2; p++)
        boff[p] = ((warp_n * 32 + p * 16 + b_r) * LDS_ + b_c) * 2;

    auto loadStage = [&](int st, int k0) {
        #pragma unroll
        for (int i = 0; i < 2; i++) {
            int c = tid + i * 256;
            int row = c >> 2, q = c & 3;
            bool v = (m0 + row) < Meff;
            long long so = (long long)sRow[row] * lda + k0 + q * 8;
            unsigned ds = (row * LDS_ + q * 8) * 2;
            cp16(sb + OFFA(st, 0) + ds, Ahp + so, v);
            cp16(sb + OFFA(st, 1) + ds, Alp + so, v);
        }
        #pragma unroll
        for (int i = 0; i < 2; i++) {
            int c = tid + i * 256;
            int row = c >> 2, q = c & 3;
            long long so = (long long)(n0 + row) * ldb + k0 + q * 8;
            unsigned ds = (row * LDS_ + q * 8) * 2;
            cp16(sb + OFFB(st, 0) + ds, Bhp + so, true);
            cp16(sb + OFFB(st, 1) + ds, Blp + so, true);
        }
    };

    float acc[4][4][4];
    #pragma unroll
    for (int i = 0; i < 4; i++)
        #pragma unroll
        for (int j = 0; j < 4; j++)
            #pragma unroll
            for (int q = 0; q < 4; q++) acc[i][j][q] = 0.f;

    int KT = K >> 5;
    loadStage(0, 0); CP_COMMIT;
    loadStage(1, 32); CP_COMMIT;

    for (int kt = 0; kt < KT; kt++) {
        int s = kt % NSTG;
        if (kt + 1 < KT) { CP_WAIT1; } else { CP_WAIT0; }
        __syncthreads();
        if (kt + 2 < KT) { loadStage((kt + 2) % NSTG, (kt + 2) * 32); CP_COMMIT; }

        unsigned bAh = sb + OFFA(s, 0), bAl = sb + OFFA(s, 1);
        unsigned bBh = sb + OFFB(s, 0), bBl = sb + OFFB(s, 1);
        #pragma unroll
        for (int kc = 0; kc < 2; kc++) {
            unsigned afh[4][4], afl[4][4], bfh[4][2], bfl[4][2];
            #pragma unroll
            for (int tm = 0; tm < 4; tm++) {
                LDSM_X4(afh[tm][0], afh[tm][1], afh[tm][2], afh[tm][3], bAh + aoff[tm] + kc * 32);
                LDSM_X4(afl[tm][0], afl[tm][1], afl[tm][2], afl[tm][3], bAl + aoff[tm] + kc * 32);
            }
            #pragma unroll
            for (int p = 0; p < 2; p++) {
                LDSM_X4(bfh[2*p][0], bfh[2*p][1], bfh[2*p+1][0], bfh[2*p+1][1], bBh + boff[p] + kc * 32);
                LDSM_X4(bfl[2*p][0], bfl[2*p][1], bfl[2*p+1][0], bfl[2*p+1][1], bBl + boff[p] + kc * 32);
            }
            #pragma unroll
            for (int tm = 0; tm < 4; tm++)
                #pragma unroll
                for (int tn = 0; tn < 4; tn++) {
                    MMA_OP(acc[tm][tn], afh[tm], bfh[tn]);
                    MMA_OP(acc[tm][tn], afl[tm], bfh[tn]);
                    MMA_OP(acc[tm][tn], afh[tm], bfl[tn]);
                }
        }
    }

    #pragma unroll
    for (int tm = 0; tm < 4; tm++) {
        #pragma unroll
        for (int half = 0; half < 2; half++) {
            int gm = m0 + warp_m * 64 + tm * 16 + lr + half * 8;
            if (gm >= Meff) continue;
            float scale = rowscale ? rowscale[gm] : 1.f;
            long long crow = rowmapC ? (long long)rowmapC[gm] : (long long)gm;
            #pragma unroll
            for (int tn = 0; tn < 4; tn++) {
                int col = n0 + warp_n * 32 + tn * 8 + lk;
                float v0 = acc[tm][tn][half * 2 + 0];
                float v1 = acc[tm][tn][half * 2 + 1];
                if (swiglu) {
                    float g = v0 * v1 / (1.f + expf(-v0));
                    int j = col >> 1;
                    bf h = __float2bfloat16(g);
                    Chp[crow * ldc + j] = h;
                    Clp[crow * ldc + j] = __float2bfloat16(g - __bfloat162float(h));
                    continue;
                }
                v0 *= scale; v1 *= scale;
                if (bias) { v0 += bias[col]; v1 += bias[col + 1]; }
                if (Cp) *(float2*)&Cp[crow * ldc + col] = make_float2(v0, v1);
                if (Chp) {
                    unsigned hi, lo;
                    pack2(v0, v1, hi, lo);
                    *(unsigned*)&Chp[crow * ldc + col] = hi;
                    *(unsigned*)&Clp[crow * ldc + col] = lo;
                }
            }
        }
    }
}

// ---------------- fused flash attention (64-token chunks, 2 CTAs/SM) ----------------
#define FCH 64
#define FATTN_SMEM (4*(2*FCH*72*2) + 1024)
__global__ void __launch_bounds__(256) k_fattn(
    const bf* __restrict__ qkh, const bf* __restrict__ qkl,
    const bf* __restrict__ vth, const bf* __restrict__ vtl,
    bf* __restrict__ ohp, bf* __restrict__ olp,
    const unsigned char* __restrict__ mask)
{
    int m0 = blockIdx.x * 128;
    int h  = blockIdx.y;
    int b  = blockIdx.z;
    int tid = threadIdx.x, lane = tid & 31, warp = tid >> 5;
    int lr = lane >> 2, lk = (lane & 3) * 2;
    int quad = lane >> 3, rin = lane & 7;
    int b_r = rin + ((quad >> 1) ? 8 : 0);
    int b_c = (quad & 1) ? 8 : 0;

    extern __shared__ __align__(16) char smem[];
    bf* sKh = (bf*)smem;                     // [2][FCH][72]
    bf* sKl = sKh + 2*FCH*72;
    bf* sVh = sKl + 2*FCH*72;                // [2][64 d][72]
    bf* sVl = sVh + 2*FCH*72;
    unsigned char* smask = (unsigned char*)(sVl + 2*FCH*72);
    unsigned kh_a = smem_u32(sKh);
    unsigned kl_a = smem_u32(sKl);
    unsigned vh_a = smem_u32(sVh);
    unsigned vl_a = smem_u32(sVl);

    for (int j = tid; j < SLEN; j += 256) smask[j] = mask[b*SLEN + j];

    int qrow = b*SLEN + m0 + warp*16;
    unsigned qfh[4][4], qfl[4][4];
    #pragma unroll
    for (int kc = 0; kc < 4; kc++) {
        long long b0 = (long long)(qrow + lr) * 2048 + h*64 + kc*16 + lk;
        long long b1 = b0 + 8LL*2048;
        qfh[kc][0] = *(const unsigned*)&qkh[b0];
        qfh[kc][1] = *(const unsigned*)&qkh[b1];
        qfh[kc][2] = *(const unsigned*)&qkh[b0 + 8];
        qfh[kc][3] = *(const unsigned*)&qkh[b1 + 8];
        qfl[kc][0] = *(const unsigned*)&qkl[b0];
        qfl[kc][1] = *(const unsigned*)&qkl[b1];
        qfl[kc][2] = *(const unsigned*)&qkl[b0 + 8];
        qfl[kc][3] = *(const unsigned*)&qkl[b1 + 8];
    }

    // per chunk: K rows = 64 tokens x 64 dims (8 cp16/row); V rows = 64 dims x 64 tokens
    auto loadChunk = [&](int st, int c) {
        int t0 = c * FCH;
        {
            int idx = tid;                      // 256 threads x 2 iters = 512 cp16
            #pragma unroll
            for (int i = 0; i < 2; i++) {
                int r = idx >> 3, q = idx & 7;
                long long src = (long long)(b*SLEN + t0 + r) * 2048 + 1024 + h*64 + q*8;
                cp16(kh_a + ((st*FCH + r)*72 + q*8)*2, qkh + src, true);
                cp16(kl_a + ((st*FCH + r)*72 + q*8)*2, qkl + src, true);
                idx += 256;
            }
        }
        {
            int idx = tid;
            #pragma unroll
            for (int i = 0; i < 2; i++) {
                int r = idx >> 3, q = idx & 7;
                long long src = (long long)(h*64 + r) * NTOK + b*SLEN + t0 + q*8;
                cp16(vh_a + ((st*FCH + r)*72 + q*8)*2, vth + src, true);
                cp16(vl_a + ((st*FCH + r)*72 + q*8)*2, vtl + src, true);
                idx += 256;
            }
        }
    };

    float m0_ = -1e30f, m1_ = -1e30f, l0_ = 0.f, l1_ = 0.f;
    float o[8][4];
    #pragma unroll
    for (int i = 0; i < 8; i++) { o[i][0]=0.f; o[i][1]=0.f; o[i][2]=0.f; o[i][3]=0.f; }

    loadChunk(0, 0); CP_COMMIT;

    for (int c = 0; c < SLEN/FCH; c++) {
        int st = c & 1;
        CP_WAIT0; __syncthreads();
        if (c + 1 < SLEN/FCH) { loadChunk(st ^ 1, c + 1); CP_COMMIT; }

        float s[8][4];
        #pragma unroll
        for (int t = 0; t < 8; t++) { s[t][0]=0.f; s[t][1]=0.f; s[t][2]=0.f; s[t][3]=0.f; }
        #pragma unroll
        for (int kc = 0; kc < 4; kc++) {
            #pragma unroll
            for (int p = 0; p < 4; p++) {
                unsigned off = ((unsigned)(st*FCH + p*16 + b_r)*72 + kc*16 + b_c)*2;
                unsigned bh[4], bl[4];
                LDSM_X4(bh[0], bh[1], bh[2], bh[3], kh_a + off);
                LDSM_X4(bl[0], bl[1], bl[2], bl[3], kl_a + off);
                MMA_OP(s[2*p],   qfh[kc], bh);
                MMA_OP(s[2*p],   qfl[kc], bh);
                MMA_OP(s[2*p],   qfh[kc], bl);
                MMA_OP(s[2*p+1], qfh[kc], bh + 2);
                MMA_OP(s[2*p+1], qfl[kc], bh + 2);
                MMA_OP(s[2*p+1], qfh[kc], bl + 2);
            }
        }
        #pragma unroll
        for (int t = 0; t < 8; t++) {
            int col = c*FCH + t*8 + lk;
            bool k0m = smask[col] != 0;
            bool k1m = smask[col + 1] != 0;
            s[t][0] = k0m ? -1e30f : s[t][0] * SCL2;
            s[t][1] = k1m ? -1e30f : s[t][1] * SCL2;
            s[t][2] = k0m ? -1e30f : s[t][2] * SCL2;
            s[t][3] = k1m ? -1e30f : s[t][3] * SCL2;
        }
        float mx0 = -1e30f, mx1 = -1e30f;
        #pragma unroll
        for (int t = 0; t < 8; t++) {
            mx0 = fmaxf(mx0, fmaxf(s[t][0], s[t][1]));
            mx1 = fmaxf(mx1, fmaxf(s[t][2], s[t][3]));
        }
        mx0 = fmaxf(mx0, __shfl_xor_sync(0xffffffffu, mx0, 1));
        mx0 = fmaxf(mx0, __shfl_xor_sync(0xffffffffu, mx0, 2));
        mx1 = fmaxf(mx1, __shfl_xor_sync(0xffffffffu, mx1, 1));
        mx1 = fmaxf(mx1, __shfl_xor_sync(0xffffffffu, mx1, 2));
        float mn0 = fmaxf(m0_, mx0), mn1 = fmaxf(m1_, mx1);
        float a0 = exp2f(m0_ - mn0), a1 = exp2f(m1_ - mn1);
        m0_ = mn0; m1_ = mn1;
        float rs0 = 0.f, rs1 = 0.f;
        #pragma unroll
        for (int t = 0; t < 8; t++) {
            s[t][0] = exp2f(s[t][0] - mn0);
            s[t][1] = exp2f(s[t][1] - mn0);
            s[t][2] = exp2f(s[t][2] - mn1);
            s[t][3] = exp2f(s[t][3] - mn1);
            rs0 += s[t][0] + s[t][1];
            rs1 += s[t][2] + s[t][3];
        }
        l0_ = l0_ * a0 + rs0;
        l1_ = l1_ * a1 + rs1;
        #pragma unroll
        for (int dt = 0; dt < 8; dt++) {
            o[dt][0] *= a0; o[dt][1] *= a0; o[dt][2] *= a1; o[dt][3] *= a1;
        }
        #pragma unroll
        for (int kc = 0; kc < 4; kc++) {
            unsigned pah[4], pal[4];
            pack2(s[2*kc][0],   s[2*kc][1],   pah[0], pal[0]);
            pack2(s[2*kc][2],   s[2*kc][3],   pah[1], pal[1]);
            pack2(s[2*kc+1][0], s[2*kc+1][1], pah[2], pal[2]);
            pack2(s[2*kc+1][2], s[2*kc+1][3], pah[3], pal[3]);
            #pragma unroll
            for (int p = 0; p < 4; p++) {
                unsigned off = ((unsigned)(st*FCH + p*16 + b_r)*72 + kc*16 + b_c)*2;
                unsigned bh[4], bl[4];
                LDSM_X4(bh[0], bh[1], bh[2], bh[3], vh_a + off);
                LDSM_X4(bl[0], bl[1], bl[2], bl[3], vl_a + off);
                MMA_OP(o[2*p],   pah, bh);
                MMA_OP(o[2*p],   pal, bh);
                MMA_OP(o[2*p],   pah, bl);
                MMA_OP(o[2*p+1], pah, bh + 2);
                MMA_OP(o[2*p+1], pal, bh + 2);
                MMA_OP(o[2*p+1], pah, bl + 2);
            }
        }
        __syncthreads();
    }

    l0_ += __shfl_xor_sync(0xffffffffu, l0_, 1);
    l0_ += __shfl_xor_sync(0xffffffffu, l0_, 2);
    l1_ += __shfl_xor_sync(0xffffffffu, l1_, 1);
    l1_ += __shfl_xor_sync(0xffffffffu, l1_, 2);
    float i0 = 1.f / l0_, i1 = 1.f / l1_;
    int row0 = qrow + lr, row1 = qrow + lr + 8;
    #pragma unroll
    for (int dt = 0; dt < 8; dt++) {
        int col = h*64 + dt*8 + lk;
        float v0 = o[dt][0]*i0, v1 = o[dt][1]*i0;
        float v2 = o[dt][2]*i1, v3 = o[dt][3]*i1;
        unsigned h01, l01, h23, l23;
        pack2(v0, v1, h01, l01);
        pack2(v2, v3, h23, l23);
        *(unsigned*)&ohp[(long long)row0*INNERD + col] = h01;
        *(unsigned*)&olp[(long long)row0*INNERD + col] = l01;
        *(unsigned*)&ohp[(long long)row1*INNERD + col] = h23;
        *(unsigned*)&olp[(long long)row1*INNERD + col] = l23;
    }
}

// ---------------- residual + layernorm ----------------
__global__ void k_addln(const float* __restrict__ x, const float* __restrict__ r,
                        const float* __restrict__ g, const float* __restrict__ bb,
                        float* __restrict__ out, bf* __restrict__ oh, bf* __restrict__ ol)
{
    int row = blockIdx.x;
    int tid = threadIdx.x;
    __shared__ float buf[DIMD];
    __shared__ float r1[256], r2[256];
    const float* xp = x + (size_t)row * DIMD;
    const float* rp = r + (size_t)row * DIMD;
    float s = 0.f, ss = 0.f;
    #pragma unroll
    for (int i = 0; i < 4; i++) {
        int j = tid + i * 256;
        float v = xp[j] + rp[j];
        buf[j] = v; s += v; ss += v * v;
    }
    r1[tid] = s; r2[tid] = ss; __syncthreads();
    for (int st = 128; st > 0; st >>= 1) {
        if (tid < st) { r1[tid] += r1[tid+st]; r2[tid] += r2[tid+st]; }
        __syncthreads();
    }
    float mean = r1[0] * (1.f / DIMD);
    float var  = r2[0] * (1.f / DIMD) - mean * mean;
    float inv  = rsqrtf(var + 1e-5f);
    #pragma unroll
    for (int i = 0; i < 4; i++) {
        int j = tid + i * 256;
        float v = (buf[j] - mean) * inv * g[j] + bb[j];
        out[(size_t)row * DIMD + j] = v;
        bf h = __float2bfloat16(v);
        oh[(size_t)row * DIMD + j] = h;
        ol[(size_t)row * DIMD + j] = __float2bfloat16(v - __bfloat162float(h));
    }
}

// ---------------- MoE router ----------------
__global__ void k_route(const float* __restrict__ xf, const float* __restrict__ gw,
                        float* __restrict__ probs_out)
{
    int tok = blockIdx.x;
    int tid = threadIdx.x;
    const float* xp = xf + (size_t)tok * DIMD;
    float part[NEXP] = {};
    for (int d = tid; d < DIMD; d += 256) {
        float xv = xp[d];
        #pragma unroll
        for (int e = 0; e < NEXP; e++) part[e] = fmaf(xv, gw[d*NEXP + e], part[e]);
    }
    __shared__ float sm[NEXP * 256];
    #pragma unroll
    for (int e = 0; e < NEXP; e++) sm[e*256 + tid] = part[e];
    __syncthreads();
    for (int s = 128; s > 0; s >>= 1) {
        if (tid < s) {
            #pragma unroll
            for (int e = 0; e < NEXP; e++) sm[e*256 + tid] += sm[e*256 + tid + s];
        }
        __syncthreads();
    }
    if (tid == 0) {
        float lg[NEXP], p[NEXP];
        float mx = NEGMIN;
        #pragma unroll
        for (int e = 0; e < NEXP; e++) { lg[e] = sm[e*256]; mx = fmaxf(mx, lg[e]); }
        float sum = 0.f;
        #pragma unroll
        for (int e = 0; e < NEXP; e++) { p[e] = expf(lg[e] - mx); sum += p[e]; }
        float inv = 1.f / sum;
        #pragma unroll
        for (int e = 0; e < NEXP; e++) { p[e] *= inv; probs_out[(size_t)tok*NEXP + e] = p[e]; }
        int i0 = 0;
        #pragma unroll
        for (int e = 1; e < NEXP; e++) if (p[e] > p[i0]) i0 = e;
        int i1 = (i0 == 0) ? 1 : 0;
        #pragma unroll
        for (int e = 0; e < NEXP; e++) if (e != i0 && p[e] > p[i1]) i1 = e;
        float w0 = p[i0], w1 = p[i1];
        float sw = 1.f / (w0 + w1);
        w0 *= sw; w1 *= sw;
        int pos = atomicAdd(&g_cnt[i0], 1);
        g_tok[i0*NTOK + pos] = tok; g_wslot[i0*NTOK + pos] = w0;
        g_inv[tok*2] = i0*NTOK + pos;
        pos = atomicAdd(&g_cnt[i1], 1);
        g_tok[i1*NTOK + pos] = tok; g_wslot[i1*NTOK + pos] = w1;
        g_inv[tok*2+1] = i1*NTOK + pos;
    }
}

// ---------------- final: 2 contribs + residual + LN3 ----------------
__global__ void k_moe_final(const float* __restrict__ x2, const float* __restrict__ g,
                            const float* __restrict__ bb, float* __restrict__ out)
{
    int tok = blockIdx.x;
    int tid = threadIdx.x;
    __shared__ float buf[DIMD];
    __shared__ float r1[256], r2[256];
    const float* xp = x2 + (size_t)tok * DIMD;
    int iv0 = g_inv[tok*2], iv1 = g_inv[tok*2+1];
    const float* c0 = g_contrib + (size_t)iv0 * DIMD;
    const float* c1 = g_contrib + (size_t)iv1 * DIMD;
    float s = 0.f, ss = 0.f;
    #pragma unroll
    for (int i = 0; i < 4; i++) {
        int j = tid + i * 256;
        float v = xp[j] + c0[j] + c1[j];
        buf[j] = v; s += v; ss += v * v;
    }
    r1[tid] = s; r2[tid] = ss; __syncthreads();
    for (int st = 128; st > 0; st >>= 1) {
        if (tid < st) { r1[tid] += r1[tid+st]; r2[tid] += r2[tid+st]; }
        __syncthreads();
    }
    float mean = r1[0] * (1.f / DIMD);
    float var  = r2[0] * (1.f / DIMD) - mean * mean;
    float inv  = rsqrtf(var + 1e-5f);
    float* op = out + (size_t)tok * DIMD;
    #pragma unroll
    for (int i = 0; i < 4; i++) {
        int j = tid + i * 256;
        op[j] = (buf[j] - mean) * inv * g[j] + bb[j];
    }
}

// ---------------- per-expert masked token sums (partitioned) ----------------
__global__ void k_tsum()
{
    int part = blockIdx.x % TSPART;
    int b = (blockIdx.x / TSPART) % NB;
    int e = blockIdx.x / (TSPART * NB);
    int tid = threadIdx.x;
    const int CH = SLEN / TSPART;
    __shared__ int sslot[SLEN / TSPART];
    for (int j = tid; j < CH; j += 256) {
        int t = b*SLEN + part*CH + j;
        int s = -1;
        if (!(g_mtgt[t] | g_mmid[t])) {
            int a = g_inv[2*t], c = g_inv[2*t+1];
            if ((a >> 11) == e) s = a;
            else if ((c >> 11) == e) s = c;
        }
        sslot[j] = s;
    }
    __syncthreads();
    for (int d = tid; d < DIMD; d += 256) {
        float acc = 0.f;
        for (int j = 0; j < CH; j++) {
            int s = sslot[j];
            if (s >= 0) acc += g_contrib[(size_t)s * DIMD + d];
        }
        g_tsumP[(((e*NB + b)*TSPART) + part)*DIMD + d] = acc;
    }
}

// ---------------- expert logits ----------------
__global__ void k_logits(const float* __restrict__ cls_w, const float* __restrict__ cls_b,
                         float* __restrict__ out_logits)
{
    int tid = threadIdx.x;
    __shared__ float red[256];
    __shared__ float dss[NEXP*NB];
    __shared__ float den[NB];
    for (int b = 0; b < NB; b++) {
        float c = 0.f;
        for (int j = tid; j < SLEN; j += 256)
            c += (!(g_mtgt[b*SLEN+j] | g_mmid[b*SLEN+j])) ? 1.f : 0.f;
        red[tid] = c; __syncthreads();
        for (int s = 128; s > 0; s >>= 1) { if (tid < s) red[tid] += red[tid+s]; __syncthreads(); }
        if (tid == 0) den[b] = fmaxf(red[0], 1.f);
        __syncthreads();
    }
    for (int eb = 0; eb < NEXP*NB; eb++) {
        float c = 0.f;
        for (int j = tid; j < DIMD; j += 256) {
            float t = 0.f;
            #pragma unroll
            for (int part = 0; part < TSPART; part++)
                t += g_tsumP[(eb*TSPART + part)*DIMD + j];
            c += t * cls_w[j];
        }
        red[tid] = c; __syncthreads();
        for (int s = 128; s > 0; s >>= 1) { if (tid < s) red[tid] += red[tid+s]; __syncthreads(); }
        if (tid == 0) dss[eb] = red[0];
        __syncthreads();
    }
    if (tid == 0) {
        for (int b = 0; b < NB; b++) {
            float pre = 0.f;
            for (int e = 0; e < NEXP; e++) {
                pre += dss[e*NB + b];
                out_logits[e*NB + b] = pre / den[b] + cls_b[0];
            }
        }
    }
}

// ---------------- host ----------------
struct GArg {
    const bf *Ah, *Al, *Bh, *Bl;
    float* C; bf *Ch, *Cl;
    int M, N, K, lda, ldb, ldc;
    long long sA1, sA2, sB1, sB2, sC1, sC2;
    int gz, bdiv, zmaps, swig;
    const float* bias; const int* rmA; const int* rmC;
    const float* rs; const int* cnt;
};

static void BG(const GArg& a)
{
    dim3 grid(a.N / 128, (a.M + 127) / 128, a.gz);
    k_bgemm<<<grid, 256, BG_SMEM>>>(
        a.Ah, a.Al, a.Bh, a.Bl, a.C, a.Ch, a.Cl, a.M, a.N, a.K, a.lda, a.ldb, a.ldc,
        a.sA1, a.sA2, a.sB1, a.sB2, a.sC1, a.sC2, a.bdiv, a.zmaps, a.swig,
        a.bias, a.rmA, a.rmC, a.rs, a.cnt);
}

extern "C" void kernel_launch(void* const* d_in, const int* in_sizes, int n_in,
                              void* d_out, int out_size)
{
    const float* x       = (const float*)d_in[0];
    const float* enc     = (const float*)d_in[1];
    const void*  src_mask_raw = d_in[2];
    const void*  tgt_mask_raw = d_in[3];
    const void*  tgt_mid_raw  = d_in[4];
    const float* ln1_g = (const float*)d_in[5];
    const float* ln1_b = (const float*)d_in[6];
    const float* ln2_g = (const float*)d_in[7];
    const float* ln2_b = (const float*)d_in[8];
    const float* ln3_g = (const float*)d_in[9];
    const float* ln3_b = (const float*)d_in[10];
    const float* sa_wq = (const float*)d_in[11];
    const float* sa_wk = (const float*)d_in[12];
    const float* sa_wv = (const float*)d_in[13];
    const float* sa_wo = (const float*)d_in[14];
    const float* sa_bo = (const float*)d_in[15];
    const float* ca_wq = (const float*)d_in[16];
    const float* ca_wk = (const float*)d_in[17];
    const float* ca_wv = (const float*)d_in[18];
    const float* ca_wo = (const float*)d_in[19];
    const float* ca_bo = (const float*)d_in[20];
    const float* gate_w = (const float*)d_in[21];
    const float* cls_w  = (const float*)d_in[22];
    const float* cls_b  = (const float*)d_in[23];
    const float* moe_w1 = (const float*)d_in[24];
    const float* moe_w2 = (const float*)d_in[25];
    const float* moe_w3 = (const float*)d_in[26];

    float* out = (float*)d_out;
    float* out_x      = out;
    float* out_logits = out + (size_t)NTOK * DIMD;
    float* out_probs  = out_logits + NEXP * NB;

    cudaFuncSetAttribute(k_bgemm, cudaFuncAttributeMaxDynamicSharedMemorySize, BG_SMEM);
    cudaFuncSetAttribute(k_fattn, cudaFuncAttributeMaxDynamicSharedMemorySize, FATTN_SMEM);

    float *pproj, *px1, *px2, *pcontrib, *pwslot;
    int *ptok, *pcnt;
    unsigned char *pmsrc, *pmtgt;
    bf *pxh,*pxl,*peh,*pel,*pawh,*pawl,*pw13h,*pw13l,*pw2h,*pw2l;
    bf *pqkh,*pqkl,*pvth,*pvtl,*path,*patl,*px1h,*px1l,*px2h,*px2l,*pgh,*pgl;
    cudaGetSymbolAddress((void**)&pproj, g_proj);
    cudaGetSymbolAddress((void**)&px1, g_x1);
    cudaGetSymbolAddress((void**)&px2, g_x2);
    cudaGetSymbolAddress((void**)&pcontrib, g_contrib);
    cudaGetSymbolAddress((void**)&pwslot, g_wslot);
    cudaGetSymbolAddress((void**)&ptok, g_tok);
    cudaGetSymbolAddress((void**)&pcnt, g_cnt);
    cudaGetSymbolAddress((void**)&pmsrc, g_msrc);
    cudaGetSymbolAddress((void**)&pmtgt, g_mtgt);
    cudaGetSymbolAddress((void**)&pxh, g_xh);   cudaGetSymbolAddress((void**)&pxl, g_xl);
    cudaGetSymbolAddress((void**)&peh, g_eh);   cudaGetSymbolAddress((void**)&pel, g_el);
    cudaGetSymbolAddress((void**)&pawh, g_awh); cudaGetSymbolAddress((void**)&pawl, g_awl);
    cudaGetSymbolAddress((void**)&pw13h, g_w13h); cudaGetSymbolAddress((void**)&pw13l, g_w13l);
    cudaGetSymbolAddress((void**)&pw2h, g_w2h); cudaGetSymbolAddress((void**)&pw2l, g_w2l);
    cudaGetSymbolAddress((void**)&pqkh, g_qkh); cudaGetSymbolAddress((void**)&pqkl, g_qkl);
    cudaGetSymbolAddress((void**)&pvth, g_vth); cudaGetSymbolAddress((void**)&pvtl, g_vtl);
    cudaGetSymbolAddress((void**)&path, g_ath); cudaGetSymbolAddress((void**)&patl, g_atl);
    cudaGetSymbolAddress((void**)&px1h, g_x1h); cudaGetSymbolAddress((void**)&px1l, g_x1l);
    cudaGetSymbolAddress((void**)&px2h, g_x2h); cudaGetSymbolAddress((void**)&px2l, g_x2l);
    cudaGetSymbolAddress((void**)&pgh, g_gh);   cudaGetSymbolAddress((void**)&pgl, g_gl);

    const long long WMOE = (long long)DIMD * HIDD;
    const long long MM   = (long long)DIMD * INNERD;
    const long long W13  = 2LL * HIDD * DIMD;

    k_detect<<<1, 256>>>((const unsigned char*)tgt_mask_raw);
    k_cvtmask<<<8, 256>>>(src_mask_raw, tgt_mask_raw, tgt_mid_raw);

    k_cvtA<<<512, 256>>>(x,   pxh, pxl, NTOK*DIMD/4);
    k_cvtA<<<512, 256>>>(enc, peh, pel, NTOK*DIMD/4);
    const float* aw[8] = {sa_wq, sa_wk, sa_wv, sa_wo, ca_wq, ca_wk, ca_wv, ca_wo};
    for (int i = 0; i < 8; i++)
        k_cvtT<<<dim3(INNERD/32, DIMD/32, 1), dim3(32,8)>>>(aw[i], pawh + i*MM, pawl + i*MM, DIMD, INNERD, 0, 0, 1, 0);
    k_cvtT<<<dim3(HIDD/32, DIMD/32, NEXP), dim3(32,8)>>>(moe_w1, pw13h, pw13l, DIMD, HIDD, WMOE, W13, 2, 0);
    k_cvtT<<<dim3(HIDD/32, DIMD/32, NEXP), dim3(32,8)>>>(moe_w3, pw13h, pw13l, DIMD, HIDD, WMOE, W13, 2, 1);
    k_cvtT<<<dim3(DIMD/32, HIDD/32, NEXP), dim3(32,8)>>>(moe_w2, pw2h, pw2l, HIDD, DIMD, WMOE, WMOE, 1, 0);

    GArg a{};

    for (int lam = 0; lam < 2; lam++) {
        const bf* inh = lam ? px1h : pxh;  const bf* inl = lam ? px1l : pxl;
        const bf* cth = lam ? peh : pxh;   const bf* ctl = lam ? pel : pxl;
        int wb = lam * 4;
        const float* bo = lam ? ca_bo : sa_bo;
        unsigned char* msk = lam ? pmsrc : pmtgt;

        if (lam == 0) {
            a = GArg{}; a.gz = 1; a.bdiv = 1;
            a.Ah = inh; a.Al = inl; a.Bh = pawh; a.Bl = pawl;
            a.Ch = pqkh; a.Cl = pqkl;
            a.M = NTOK; a.N = 2*INNERD; a.K = DIMD; a.lda = DIMD; a.ldb = DIMD; a.ldc = 2*INNERD;
            BG(a);
        } else {
            a = GArg{}; a.gz = 1; a.bdiv = 1;
            a.Ah = inh; a.Al = inl; a.Bh = pawh + (wb+0)*MM; a.Bl = pawl + (wb+0)*MM;
            a.Ch = pqkh; a.Cl = pqkl;
            a.M = NTOK; a.N = INNERD; a.K = DIMD; a.lda = DIMD; a.ldb = DIMD; a.ldc = 2*INNERD;
            BG(a);
            a.Ah = cth; a.Al = ctl; a.Bh = pawh + (wb+1)*MM; a.Bl = pawl + (wb+1)*MM;
            a.Ch = pqkh + INNERD; a.Cl = pqkl + INNERD;
            BG(a);
        }
        a = GArg{}; a.gz = 1; a.bdiv = 1;
        a.Ah = pawh + (wb+2)*MM; a.Al = pawl + (wb+2)*MM; a.Bh = cth; a.Bl = ctl;
        a.Ch = pvth; a.Cl = pvtl;
        a.M = INNERD; a.N = NTOK; a.K = DIMD; a.lda = DIMD; a.ldb = DIMD; a.ldc = NTOK;
        BG(a);
        k_fattn<<<dim3(SLEN/128, HEADS, NB), 256, FATTN_SMEM>>>(
            pqkh, pqkl, pvth, pvtl, path, patl, msk);
        a = GArg{}; a.gz = 1; a.bdiv = 1;
        a.Ah = path; a.Al = patl; a.Bh = pawh + (wb+3)*MM; a.Bl = pawl + (wb+3)*MM;
        a.C = pproj; a.bias = bo;
        a.M = NTOK; a.N = DIMD; a.K = INNERD; a.lda = INNERD; a.ldb = INNERD; a.ldc = DIMD;
        BG(a);
        if (lam == 0)
            k_addln<<<NTOK, 256>>>(x, pproj, ln1_g, ln1_b, px1, px1h, px1l);
        else
            k_addln<<<NTOK, 256>>>(px1, pproj, ln2_g, ln2_b, px2, px2h, px2l);
    }

    k_route<<<NTOK, 256>>>(px2, gate_w, out_probs);
    a = GArg{}; a.gz = NEXP; a.bdiv = NEXP; a.zmaps = 1; a.swig = 1;
    a.Ah = px2h; a.Al = px2l; a.Bh = pw13h; a.Bl = pw13l;
    a.Ch = pgh; a.Cl = pgl;
    a.M = NTOK; a.N = 2*HIDD; a.K = DIMD; a.lda = DIMD; a.ldb = DIMD; a.ldc = HIDD;
    a.sB1 = W13; a.sC1 = (long long)NTOK*HIDD;
    a.rmA = ptok; a.cnt = pcnt;
    BG(a);
    a = GArg{}; a.gz = NEXP; a.bdiv = NEXP; a.zmaps = 1;
    a.Ah = pgh; a.Al = pgl; a.Bh = pw2h; a.Bl = pw2l; a.C = pcontrib;
    a.M = NTOK; a.N = DIMD; a.K = HIDD; a.lda = HIDD; a.ldb = HIDD; a.ldc = DIMD;
    a.sA1 = (long long)NTOK*HIDD; a.sB1 = WMOE; a.sC1 = (long long)NTOK*DIMD;
    a.rs = pwslot; a.cnt = pcnt;
    BG(a);

    k_moe_final<<<NTOK, 256>>>(px2, ln3_g, ln3_b, out_x);
    k_tsum<<<NEXP*NB*TSPART, 256>>>();
    k_logits<<<1, 256>>>(cls_w, cls_b, out_logits);
}

// round 11
// speedup vs baseline: 1.0109x; 1.0109x over previous
#include <cuda_runtime.h>
#include <cuda_bf16.h>
#include <math.h>

#define DIMD   1024
#define HEADS  16
#define DHEAD  64
#define HIDD   2048
#define NEXP   8
#define NB     2
#define SLEN   1024
#define NTOK   (NB*SLEN)
#define INNERD (HEADS*DHEAD)
#define NEGMIN (-3.402823466e38f)
#define SCL2   0.18033688011112042f   // 0.125 * log2(e)
#define TSPART 8

typedef __nv_bfloat16 bf;

// ---------------- device scratch ----------------
__device__ float g_proj[NTOK*DIMD];
__device__ float g_x1[NTOK*DIMD];
__device__ float g_x2[NTOK*DIMD];
__device__ float g_contrib[(size_t)NEXP*NTOK*DIMD];
__device__ float g_wslot[NEXP*NTOK];
__device__ int   g_tok[NEXP*NTOK];
__device__ int   g_inv[NTOK*2];
__device__ int   g_cnt[NEXP];
__device__ float g_tsumP[NEXP*NB*TSPART*DIMD];
__device__ bf g_xh[NTOK*DIMD],  g_xl[NTOK*DIMD];
// x1 planes + enc planes in ONE array (enc at offset NTOK*DIMD) so the
// cross-attn Q/K GEMMs can be z-batched with a uniform A stride.
__device__ bf g_x1h[2*NTOK*DIMD], g_x1l[2*NTOK*DIMD];
__device__ bf g_awh[8*DIMD*INNERD], g_awl[8*DIMD*INNERD];
__device__ bf g_w13h[(size_t)NEXP*2*HIDD*DIMD], g_w13l[(size_t)NEXP*2*HIDD*DIMD];
__device__ bf g_w2h[(size_t)NEXP*HIDD*DIMD], g_w2l[(size_t)NEXP*HIDD*DIMD];
__device__ bf g_qkh[NTOK*2*INNERD], g_qkl[NTOK*2*INNERD];
__device__ bf g_vth[NTOK*INNERD], g_vtl[NTOK*INNERD];
__device__ bf g_ath[NTOK*INNERD], g_atl[NTOK*INNERD];
__device__ bf g_x2h[NTOK*DIMD], g_x2l[NTOK*DIMD];
__device__ bf g_gh[(size_t)NEXP*NTOK*HIDD], g_gl[(size_t)NEXP*NTOK*HIDD];
__device__ unsigned char g_msrc[NTOK];
__device__ unsigned char g_mtgt[NTOK];
__device__ unsigned char g_mmid[NTOK];
__device__ int g_mtype;

// ---------------- PTX helpers ----------------
__device__ __forceinline__ unsigned smem_u32(const void* p) {
    return (unsigned)__cvta_generic_to_shared(p);
}
__device__ __forceinline__ void cp16(unsigned d, const void* s, bool v) {
    if (v) asm volatile("cp.async.ca.shared.global [%0], [%1], 16;\n" :: "r"(d), "l"(s) : "memory");
    else   asm volatile("cp.async.ca.shared.global [%0], [%1], 16, 0;\n" :: "r"(d), "l"(s) : "memory");
}
#define CP_COMMIT asm volatile("cp.async.commit_group;\n" ::: "memory")
#define CP_WAIT0  asm volatile("cp.async.wait_group 0;\n" ::: "memory")
#define CP_WAIT1  asm volatile("cp.async.wait_group 1;\n" ::: "memory")

#define LDSM_X4(d0, d1, d2, d3, a) \
    asm volatile("ldmatrix.sync.aligned.m8n8.x4.shared.b16 {%0,%1,%2,%3}, [%4];" \
                 : "=r"(d0), "=r"(d1), "=r"(d2), "=r"(d3) : "r"(a))

#define MMA_OP(c, a, b) \
    asm volatile("mma.sync.aligned.m16n8k16.row.col.f32.bf16.bf16.f32 " \
                 "{%0,%1,%2,%3},{%4,%5,%6,%7},{%8,%9},{%0,%1,%2,%3};" \
                 : "+f"((c)[0]), "+f"((c)[1]), "+f"((c)[2]), "+f"((c)[3]) \
                 : "r"((a)[0]), "r"((a)[1]), "r"((a)[2]), "r"((a)[3]), \
                   "r"((b)[0]), "r"((b)[1]))

__device__ __forceinline__ void pack2(float x, float y, unsigned& hi, unsigned& lo) {
    bf hx = __float2bfloat16(x), hy = __float2bfloat16(y);
    __nv_bfloat162 th; th.x = hx; th.y = hy;
    hi = *(unsigned*)&th;
    __nv_bfloat162 tl;
    tl.x = __float2bfloat16(x - __bfloat162float(hx));
    tl.y = __float2bfloat16(y - __bfloat162float(hy));
    lo = *(unsigned*)&tl;
}

// ---------------- mask detection / conversion ----------------
__global__ void k_detect(const unsigned char* __restrict__ tgt) {
    __shared__ int has_gt1, has_off;
    if (threadIdx.x == 0) { has_gt1 = 0; has_off = 0; }
    if (threadIdx.x < NEXP) g_cnt[threadIdx.x] = 0;
    __syncthreads();
    for (int j = threadIdx.x; j < NTOK; j += blockDim.x) {
        unsigned char v = tgt[j];
        if (v > 1) atomicOr(&has_gt1, 1);
        else if (v && (j & 3)) atomicOr(&has_off, 1);
    }
    __syncthreads();
    if (threadIdx.x == 0)
        g_mtype = has_gt1 ? 2 : (has_off ? 0 : 1);
}

__global__ void k_cvtmask(const void* __restrict__ s0, const void* __restrict__ s1,
                          const void* __restrict__ s2) {
    int t = g_mtype;
    int stride = gridDim.x * blockDim.x;
    for (int j = blockIdx.x * blockDim.x + threadIdx.x; j < NTOK; j += stride) {
        unsigned char a, b, c;
        if (t == 1) {
            a = ((const int*)s0)[j] != 0;
            b = ((const int*)s1)[j] != 0;
            c = ((const int*)s2)[j] != 0;
        } else if (t == 2) {
            a = ((const float*)s0)[j] != 0.f;
            b = ((const float*)s1)[j] != 0.f;
            c = ((const float*)s2)[j] != 0.f;
        } else {
            a = ((const unsigned char*)s0)[j];
            b = ((const unsigned char*)s1)[j];
            c = ((const unsigned char*)s2)[j];
        }
        g_msrc[j] = a; g_mtgt[j] = b; g_mmid[j] = c;
    }
}

// ---------------- conversion kernels ----------------
__global__ void k_cvtA(const float* __restrict__ s, bf* __restrict__ dh, bf* __restrict__ dl, int n4)
{
    int stride = gridDim.x * blockDim.x;
    for (int i = blockIdx.x * blockDim.x + threadIdx.x; i < n4; i += stride) {
        float4 v = ((const float4*)s)[i];
        float vv[4] = {v.x, v.y, v.z, v.w};
        bf h[4], l[4];
        #pragma unroll
        for (int j = 0; j < 4; j++) {
            h[j] = __float2bfloat16(vv[j]);
            l[j] = __float2bfloat16(vv[j] - __bfloat162float(h[j]));
        }
        ((ushort4*)dh)[i] = *(ushort4*)h;
        ((ushort4*)dl)[i] = *(ushort4*)l;
    }
}

// transpose-convert with optional output-row interleave: dst row = nn*rowMul + rowAdd
__global__ void k_cvtT(const float* __restrict__ src, bf* __restrict__ dh, bf* __restrict__ dl,
                       int Kd, int Nd, long long sSrc, long long sDst, int rowMul, int rowAdd)
{
    int z = blockIdx.z;
    src += (long long)z * sSrc; dh += (long long)z * sDst; dl += (long long)z * sDst;
    __shared__ float t[32][33];
    int k0 = blockIdx.y * 32, n0 = blockIdx.x * 32;
    #pragma unroll
    for (int i = 0; i < 4; i++) {
        int kk = k0 + threadIdx.y + i * 8;
        t[threadIdx.y + i * 8][threadIdx.x] = src[(long long)kk * Nd + n0 + threadIdx.x];
    }
    __syncthreads();
    #pragma unroll
    for (int i = 0; i < 4; i++) {
        int nn = n0 + threadIdx.y + i * 8;
        float v = t[threadIdx.x][threadIdx.y + i * 8];
        bf h = __float2bfloat16(v);
        long long dr = (long long)nn * rowMul + rowAdd;
        dh[dr * Kd + k0 + threadIdx.x] = h;
        dl[dr * Kd + k0 + threadIdx.x] = __float2bfloat16(v - __bfloat162float(h));
    }
}

// ---------------- bf16-plane tensor-core GEMM (ldmatrix + 3-stage pipeline) ----------------
#define LDS_ 40
#define NSTG 3
#define OFFA(st, pl) (((st)*2 + (pl)) * 128 * LDS_ * 2)
#define OFFB(st, pl) (NSTG*2*128*LDS_*2 + ((st)*2 + (pl)) * 128 * LDS_ * 2)
#define BG_SROW (2 * NSTG*2*128*LDS_*2)
#define BG_SMEM (BG_SROW + 512 + 64)

__global__ void __launch_bounds__(256) k_bgemm(
    const bf* __restrict__ Ah, const bf* __restrict__ Al,
    const bf* __restrict__ Bh, const bf* __restrict__ Bl,
    float* __restrict__ C, bf* __restrict__ Ch, bf* __restrict__ Cl,
    int M, int N, int K, int lda, int ldb, int ldc,
    long long sA1, long long sA2, long long sB1, long long sB2,
    long long sC1, long long sC2, int bdiv, int zmaps, int swiglu,
    const float* __restrict__ bias,
    const int* __restrict__ rowmapA, const int* __restrict__ rowmapC,
    const float* __restrict__ rowscale, const int* __restrict__ cntPtr)
{
    int z = blockIdx.z;
    long long ao = (long long)(z / bdiv) * sA2 + (long long)(z % bdiv) * sA1;
    long long bo = (long long)(z / bdiv) * sB2 + (long long)(z % bdiv) * sB1;
    long long co = (long long)(z / bdiv) * sC2 + (long long)(z % bdiv) * sC1;
    const bf* Ahp = Ah + ao; const bf* Alp = Al + ao;
    const bf* Bhp = Bh + bo; const bf* Blp = Bl + bo;
    float* Cp = C ? C + co : nullptr;
    bf* Chp = Ch ? Ch + co : nullptr;
    bf* Clp = Cl ? Cl + co : nullptr;
    if (zmaps) {
        if (rowmapA) rowmapA += z * NTOK;
        if (rowmapC) rowmapC += z * NTOK;
        if (rowscale) rowscale += z * NTOK;
        if (cntPtr) cntPtr += z;
    }
    int Meff = M;
    if (cntPtr) { int c = *cntPtr; Meff = c < M ? c : M; }
    int m0 = blockIdx.y * 128;
    if (m0 >= Meff) return;
    int n0 = blockIdx.x * 128;

    extern __shared__ __align__(16) char dyn[];
    unsigned sb = smem_u32(dyn);
    int* sRow = (int*)(dyn + BG_SROW);

    int tid = threadIdx.x, lane = tid & 31, warp = tid >> 5;
    int warp_n = warp & 3, warp_m = warp >> 2;
    int lr = lane >> 2, lk = (lane & 3) * 2;
    int quad = lane >> 3, rin = lane & 7;

    for (int r = tid; r < 128; r += 256) {
        int gm = m0 + r;
        sRow[r] = (gm < Meff) ? (rowmapA ? rowmapA[gm] : gm) : 0;
    }
    __syncthreads();

    int a_r = rin + ((quad & 1) ? 8 : 0);
    int a_c = (quad & 2) ? 8 : 0;
    int b_r = rin + ((quad >> 1) ? 8 : 0);
    int b_c = (quad & 1) ? 8 : 0;
    int aoff[4], boff[2];
    #pragma unroll
    for (int tm = 0; tm < 4; tm++)
        aoff[tm] = ((warp_m * 64 + tm * 16 + a_r) * LDS_ + a_c) * 2;
    #pragma unroll
    for (int p = 0; p < 2; p++)
        boff[p] = ((warp_n * 32 + p * 16 + b_r) * LDS_ + b_c) * 2;

    auto loadStage = [&](int st, int k0) {
        #pragma unroll
        for (int i = 0; i < 2; i++) {
            int c = tid + i * 256;
            int row = c >> 2, q = c & 3;
            bool v = (m0 + row) < Meff;
            long long so = (long long)sRow[row] * lda + k0 + q * 8;
            unsigned ds = (row * LDS_ + q * 8) * 2;
            cp16(sb + OFFA(st, 0) + ds, Ahp + so, v);
            cp16(sb + OFFA(st, 1) + ds, Alp + so, v);
        }
        #pragma unroll
        for (int i = 0; i < 2; i++) {
            int c = tid + i * 256;
            int row = c >> 2, q = c & 3;
            long long so = (long long)(n0 + row) * ldb + k0 + q * 8;
            unsigned ds = (row * LDS_ + q * 8) * 2;
            cp16(sb + OFFB(st, 0) + ds, Bhp + so, true);
            cp16(sb + OFFB(st, 1) + ds, Blp + so, true);
        }
    };

    float acc[4][4][4];
    #pragma unroll
    for (int i = 0; i < 4; i++)
        #pragma unroll
        for (int j = 0; j < 4; j++)
            #pragma unroll
            for (int q = 0; q < 4; q++) acc[i][j][q] = 0.f;

    int KT = K >> 5;
    loadStage(0, 0); CP_COMMIT;
    loadStage(1, 32); CP_COMMIT;

    for (int kt = 0; kt < KT; kt++) {
        int s = kt % NSTG;
        if (kt + 1 < KT) { CP_WAIT1; } else { CP_WAIT0; }
        __syncthreads();
        if (kt + 2 < KT) { loadStage((kt + 2) % NSTG, (kt + 2) * 32); CP_COMMIT; }

        unsigned bAh = sb + OFFA(s, 0), bAl = sb + OFFA(s, 1);
        unsigned bBh = sb + OFFB(s, 0), bBl = sb + OFFB(s, 1);
        #pragma unroll
        for (int kc = 0; kc < 2; kc++) {
            unsigned afh[4][4], afl[4][4], bfh[4][2], bfl[4][2];
            #pragma unroll
            for (int tm = 0; tm < 4; tm++) {
                LDSM_X4(afh[tm][0], afh[tm][1], afh[tm][2], afh[tm][3], bAh + aoff[tm] + kc * 32);
                LDSM_X4(afl[tm][0], afl[tm][1], afl[tm][2], afl[tm][3], bAl + aoff[tm] + kc * 32);
            }
            #pragma unroll
            for (int p = 0; p < 2; p++) {
                LDSM_X4(bfh[2*p][0], bfh[2*p][1], bfh[2*p+1][0], bfh[2*p+1][1], bBh + boff[p] + kc * 32);
                LDSM_X4(bfl[2*p][0], bfl[2*p][1], bfl[2*p+1][0], bfl[2*p+1][1], bBl + boff[p] + kc * 32);
            }
            #pragma unroll
            for (int tm = 0; tm < 4; tm++)
                #pragma unroll
                for (int tn = 0; tn < 4; tn++) {
                    MMA_OP(acc[tm][tn], afh[tm], bfh[tn]);
                    MMA_OP(acc[tm][tn], afl[tm], bfh[tn]);
                    MMA_OP(acc[tm][tn], afh[tm], bfl[tn]);
                }
        }
    }

    #pragma unroll
    for (int tm = 0; tm < 4; tm++) {
        #pragma unroll
        for (int half = 0; half < 2; half++) {
            int gm = m0 + warp_m * 64 + tm * 16 + lr + half * 8;
            if (gm >= Meff) continue;
            float scale = rowscale ? rowscale[gm] : 1.f;
            long long crow = rowmapC ? (long long)rowmapC[gm] : (long long)gm;
            #pragma unroll
            for (int tn = 0; tn < 4; tn++) {
                int col = n0 + warp_n * 32 + tn * 8 + lk;
                float v0 = acc[tm][tn][half * 2 + 0];
                float v1 = acc[tm][tn][half * 2 + 1];
                if (swiglu) {
                    float g = v0 * v1 / (1.f + expf(-v0));
                    int j = col >> 1;
                    bf h = __float2bfloat16(g);
                    Chp[crow * ldc + j] = h;
                    Clp[crow * ldc + j] = __float2bfloat16(g - __bfloat162float(h));
                    continue;
                }
                v0 *= scale; v1 *= scale;
                if (bias) { v0 += bias[col]; v1 += bias[col + 1]; }
                if (Cp) *(float2*)&Cp[crow * ldc + col] = make_float2(v0, v1);
                if (Chp) {
                    unsigned hi, lo;
                    pack2(v0, v1, hi, lo);
                    *(unsigned*)&Chp[crow * ldc + col] = hi;
                    *(unsigned*)&Clp[crow * ldc + col] = lo;
                }
            }
        }
    }
}

// ---------------- fused flash attention (128-token chunks — round-9 version) ----------------
#define FATTN_SMEM (2*128*72*2*2 + 2*64*136*2*2 + 1024)
__global__ void __launch_bounds__(256) k_fattn(
    const bf* __restrict__ qkh, const bf* __restrict__ qkl,
    const bf* __restrict__ vth, const bf* __restrict__ vtl,
    bf* __restrict__ ohp, bf* __restrict__ olp,
    const unsigned char* __restrict__ mask)
{
    int m0 = blockIdx.x * 128;
    int h  = blockIdx.y;
    int b  = blockIdx.z;
    int tid = threadIdx.x, lane = tid & 31, warp = tid >> 5;
    int lr = lane >> 2, lk = (lane & 3) * 2;
    int quad = lane >> 3, rin = lane & 7;
    int b_r = rin + ((quad >> 1) ? 8 : 0);
    int b_c = (quad & 1) ? 8 : 0;

    extern __shared__ __align__(16) char smem[];
    bf* sKh = (bf*)smem;
    bf* sKl = sKh + 2*128*72;
    bf* sVh = sKl + 2*128*72;
    bf* sVl = sVh + 2*64*136;
    unsigned char* smask = (unsigned char*)(sVl + 2*64*136);
    unsigned kh_a = smem_u32(sKh);
    unsigned kl_a = smem_u32(sKl);
    unsigned vh_a = smem_u32(sVh);
    unsigned vl_a = smem_u32(sVl);

    for (int j = tid; j < SLEN; j += 256) smask[j] = mask[b*SLEN + j];

    int qrow = b*SLEN + m0 + warp*16;
    unsigned qfh[4][4], qfl[4][4];
    #pragma unroll
    for (int kc = 0; kc < 4; kc++) {
        long long b0 = (long long)(qrow + lr) * 2048 + h*64 + kc*16 + lk;
        long long b1 = b0 + 8LL*2048;
        qfh[kc][0] = *(const unsigned*)&qkh[b0];
        qfh[kc][1] = *(const unsigned*)&qkh[b1];
        qfh[kc][2] = *(const unsigned*)&qkh[b0 + 8];
        qfh[kc][3] = *(const unsigned*)&qkh[b1 + 8];
        qfl[kc][0] = *(const unsigned*)&qkl[b0];
        qfl[kc][1] = *(const unsigned*)&qkl[b1];
        qfl[kc][2] = *(const unsigned*)&qkl[b0 + 8];
        qfl[kc][3] = *(const unsigned*)&qkl[b1 + 8];
    }

    auto loadChunk = [&](int st, int c) {
        int t0 = c * 128;
        #pragma unroll
        for (int i = 0; i < 4; i++) {
            int idx = tid + i*256;
            int r = idx >> 3, q = idx & 7;
            long long src = (long long)(b*SLEN + t0 + r) * 2048 + 1024 + h*64 + q*8;
            cp16(kh_a + ((st*128 + r)*72 + q*8)*2, qkh + src, true);
            cp16(kl_a + ((st*128 + r)*72 + q*8)*2, qkl + src, true);
        }
        #pragma unroll
        for (int i = 0; i < 4; i++) {
            int idx = tid + i*256;
            int r = idx >> 4, q = idx & 15;
            long long src = (long long)(h*64 + r) * NTOK + b*SLEN + t0 + q*8;
            cp16(vh_a + ((st*64 + r)*136 + q*8)*2, vth + src, true);
            cp16(vl_a + ((st*64 + r)*136 + q*8)*2, vtl + src, true);
        }
    };

    float m0_ = -1e30f, m1_ = -1e30f, l0_ = 0.f, l1_ = 0.f;
    float o[8][4];
    #pragma unroll
    for (int i = 0; i < 8; i++) { o[i][0]=0.f; o[i][1]=0.f; o[i][2]=0.f; o[i][3]=0.f; }

    loadChunk(0, 0); CP_COMMIT;

    for (int c = 0; c < 8; c++) {
        int st = c & 1;
        CP_WAIT0; __syncthreads();
        if (c + 1 < 8) { loadChunk(st ^ 1, c + 1); CP_COMMIT; }

        float s[16][4];
        #pragma unroll
        for (int t = 0; t < 16; t++) { s[t][0]=0.f; s[t][1]=0.f; s[t][2]=0.f; s[t][3]=0.f; }
        #pragma unroll
        for (int kc = 0; kc < 4; kc++) {
            #pragma unroll
            for (int p = 0; p < 8; p++) {
                unsigned off = ((unsigned)(st*128 + p*16 + b_r)*72 + kc*16 + b_c)*2;
                unsigned bh[4], bl[4];
                LDSM_X4(bh[0], bh[1], bh[2], bh[3], kh_a + off);
                LDSM_X4(bl[0], bl[1], bl[2], bl[3], kl_a + off);
                MMA_OP(s[2*p],   qfh[kc], bh);
                MMA_OP(s[2*p],   qfl[kc], bh);
                MMA_OP(s[2*p],   qfh[kc], bl);
                MMA_OP(s[2*p+1], qfh[kc], bh + 2);
                MMA_OP(s[2*p+1], qfl[kc], bh + 2);
                MMA_OP(s[2*p+1], qfh[kc], bl + 2);
            }
        }
        #pragma unroll
        for (int t = 0; t < 16; t++) {
            int col = c*128 + t*8 + lk;
            bool k0m = smask[col] != 0;
            bool k1m = smask[col + 1] != 0;
            s[t][0] = k0m ? -1e30f : s[t][0] * SCL2;
            s[t][1] = k1m ? -1e30f : s[t][1] * SCL2;
            s[t][2] = k0m ? -1e30f : s[t][2] * SCL2;
            s[t][3] = k1m ? -1e30f : s[t][3] * SCL2;
        }
        float mx0 = -1e30f, mx1 = -1e30f;
        #pragma unroll
        for (int t = 0; t < 16; t++) {
            mx0 = fmaxf(mx0, fmaxf(s[t][0], s[t][1]));
            mx1 = fmaxf(mx1, fmaxf(s[t][2], s[t][3]));
        }
        mx0 = fmaxf(mx0, __shfl_xor_sync(0xffffffffu, mx0, 1));
        mx0 = fmaxf(mx0, __shfl_xor_sync(0xffffffffu, mx0, 2));
        mx1 = fmaxf(mx1, __shfl_xor_sync(0xffffffffu, mx1, 1));
        mx1 = fmaxf(mx1, __shfl_xor_sync(0xffffffffu, mx1, 2));
        float mn0 = fmaxf(m0_, mx0), mn1 = fmaxf(m1_, mx1);
        float a0 = exp2f(m0_ - mn0), a1 = exp2f(m1_ - mn1);
        m0_ = mn0; m1_ = mn1;
        float rs0 = 0.f, rs1 = 0.f;
        #pragma unroll
        for (int t = 0; t < 16; t++) {
            s[t][0] = exp2f(s[t][0] - mn0);
            s[t][1] = exp2f(s[t][1] - mn0);
            s[t][2] = exp2f(s[t][2] - mn1);
            s[t][3] = exp2f(s[t][3] - mn1);
            rs0 += s[t][0] + s[t][1];
            rs1 += s[t][2] + s[t][3];
        }
        l0_ = l0_ * a0 + rs0;
        l1_ = l1_ * a1 + rs1;
        #pragma unroll
        for (int dt = 0; dt < 8; dt++) {
            o[dt][0] *= a0; o[dt][1] *= a0; o[dt][2] *= a1; o[dt][3] *= a1;
        }
        #pragma unroll
        for (int kc = 0; kc < 8; kc++) {
            unsigned pah[4], pal[4];
            pack2(s[2*kc][0],   s[2*kc][1],   pah[0], pal[0]);
            pack2(s[2*kc][2],   s[2*kc][3],   pah[1], pal[1]);
            pack2(s[2*kc+1][0], s[2*kc+1][1], pah[2], pal[2]);
            pack2(s[2*kc+1][2], s[2*kc+1][3], pah[3], pal[3]);
            #pragma unroll
            for (int p = 0; p < 4; p++) {
                unsigned off = ((unsigned)(st*64 + p*16 + b_r)*136 + kc*16 + b_c)*2;
                unsigned bh[4], bl[4];
                LDSM_X4(bh[0], bh[1], bh[2], bh[3], vh_a + off);
                LDSM_X4(bl[0], bl[1], bl[2], bl[3], vl_a + off);
                MMA_OP(o[2*p],   pah, bh);
                MMA_OP(o[2*p],   pal, bh);
                MMA_OP(o[2*p],   pah, bl);
                MMA_OP(o[2*p+1], pah, bh + 2);
                MMA_OP(o[2*p+1], pal, bh + 2);
                MMA_OP(o[2*p+1], pah, bl + 2);
            }
        }
        __syncthreads();
    }

    l0_ += __shfl_xor_sync(0xffffffffu, l0_, 1);
    l0_ += __shfl_xor_sync(0xffffffffu, l0_, 2);
    l1_ += __shfl_xor_sync(0xffffffffu, l1_, 1);
    l1_ += __shfl_xor_sync(0xffffffffu, l1_, 2);
    float i0 = 1.f / l0_, i1 = 1.f / l1_;
    int row0 = qrow + lr, row1 = qrow + lr + 8;
    #pragma unroll
    for (int dt = 0; dt < 8; dt++) {
        int col = h*64 + dt*8 + lk;
        float v0 = o[dt][0]*i0, v1 = o[dt][1]*i0;
        float v2 = o[dt][2]*i1, v3 = o[dt][3]*i1;
        unsigned h01, l01, h23, l23;
        pack2(v0, v1, h01, l01);
        pack2(v2, v3, h23, l23);
        *(unsigned*)&ohp[(long long)row0*INNERD + col] = h01;
        *(unsigned*)&olp[(long long)row0*INNERD + col] = l01;
        *(unsigned*)&ohp[(long long)row1*INNERD + col] = h23;
        *(unsigned*)&olp[(long long)row1*INNERD + col] = l23;
    }
}

// ---------------- residual + layernorm ----------------
__global__ void k_addln(const float* __restrict__ x, const float* __restrict__ r,
                        const float* __restrict__ g, const float* __restrict__ bb,
                        float* __restrict__ out, bf* __restrict__ oh, bf* __restrict__ ol)
{
    int row = blockIdx.x;
    int tid = threadIdx.x;
    __shared__ float buf[DIMD];
    __shared__ float r1[256], r2[256];
    const float* xp = x + (size_t)row * DIMD;
    const float* rp = r + (size_t)row * DIMD;
    float s = 0.f, ss = 0.f;
    #pragma unroll
    for (int i = 0; i < 4; i++) {
        int j = tid + i * 256;
        float v = xp[j] + rp[j];
        buf[j] = v; s += v; ss += v * v;
    }
    r1[tid] = s; r2[tid] = ss; __syncthreads();
    for (int st = 128; st > 0; st >>= 1) {
        if (tid < st) { r1[tid] += r1[tid+st]; r2[tid] += r2[tid+st]; }
        __syncthreads();
    }
    float mean = r1[0] * (1.f / DIMD);
    float var  = r2[0] * (1.f / DIMD) - mean * mean;
    float inv  = rsqrtf(var + 1e-5f);
    #pragma unroll
    for (int i = 0; i < 4; i++) {
        int j = tid + i * 256;
        float v = (buf[j] - mean) * inv * g[j] + bb[j];
        out[(size_t)row * DIMD + j] = v;
        bf h = __float2bfloat16(v);
        oh[(size_t)row * DIMD + j] = h;
        ol[(size_t)row * DIMD + j] = __float2bfloat16(v - __bfloat162float(h));
    }
}

// ---------------- MoE router ----------------
__global__ void k_route(const float* __restrict__ xf, const float* __restrict__ gw,
                        float* __restrict__ probs_out)
{
    int tok = blockIdx.x;
    int tid = threadIdx.x;
    const float* xp = xf + (size_t)tok * DIMD;
    float part[NEXP] = {};
    for (int d = tid; d < DIMD; d += 256) {
        float xv = xp[d];
        #pragma unroll
        for (int e = 0; e < NEXP; e++) part[e] = fmaf(xv, gw[d*NEXP + e], part[e]);
    }
    __shared__ float sm[NEXP * 256];
    #pragma unroll
    for (int e = 0; e < NEXP; e++) sm[e*256 + tid] = part[e];
    __syncthreads();
    for (int s = 128; s > 0; s >>= 1) {
        if (tid < s) {
            #pragma unroll
            for (int e = 0; e < NEXP; e++) sm[e*256 + tid] += sm[e*256 + tid + s];
        }
        __syncthreads();
    }
    if (tid == 0) {
        float lg[NEXP], p[NEXP];
        float mx = NEGMIN;
        #pragma unroll
        for (int e = 0; e < NEXP; e++) { lg[e] = sm[e*256]; mx = fmaxf(mx, lg[e]); }
        float sum = 0.f;
        #pragma unroll
        for (int e = 0; e < NEXP; e++) { p[e] = expf(lg[e] - mx); sum += p[e]; }
        float inv = 1.f / sum;
        #pragma unroll
        for (int e = 0; e < NEXP; e++) { p[e] *= inv; probs_out[(size_t)tok*NEXP + e] = p[e]; }
        int i0 = 0;
        #pragma unroll
        for (int e = 1; e < NEXP; e++) if (p[e] > p[i0]) i0 = e;
        int i1 = (i0 == 0) ? 1 : 0;
        #pragma unroll
        for (int e = 0; e < NEXP; e++) if (e != i0 && p[e] > p[i1]) i1 = e;
        float w0 = p[i0], w1 = p[i1];
        float sw = 1.f / (w0 + w1);
        w0 *= sw; w1 *= sw;
        int pos = atomicAdd(&g_cnt[i0], 1);
        g_tok[i0*NTOK + pos] = tok; g_wslot[i0*NTOK + pos] = w0;
        g_inv[tok*2] = i0*NTOK + pos;
        pos = atomicAdd(&g_cnt[i1], 1);
        g_tok[i1*NTOK + pos] = tok; g_wslot[i1*NTOK + pos] = w1;
        g_inv[tok*2+1] = i1*NTOK + pos;
    }
}

// ---------------- final: 2 contribs + residual + LN3 ----------------
__global__ void k_moe_final(const float* __restrict__ x2, const float* __restrict__ g,
                            const float* __restrict__ bb, float* __restrict__ out)
{
    int tok = blockIdx.x;
    int tid = threadIdx.x;
    __shared__ float buf[DIMD];
    __shared__ float r1[256], r2[256];
    const float* xp = x2 + (size_t)tok * DIMD;
    int iv0 = g_inv[tok*2], iv1 = g_inv[tok*2+1];
    const float* c0 = g_contrib + (size_t)iv0 * DIMD;
    const float* c1 = g_contrib + (size_t)iv1 * DIMD;
    float s = 0.f, ss = 0.f;
    #pragma unroll
    for (int i = 0; i < 4; i++) {
        int j = tid + i * 256;
        float v = xp[j] + c0[j] + c1[j];
        buf[j] = v; s += v; ss += v * v;
    }
    r1[tid] = s; r2[tid] = ss; __syncthreads();
    for (int st = 128; st > 0; st >>= 1) {
        if (tid < st) { r1[tid] += r1[tid+st]; r2[tid] += r2[tid+st]; }
        __syncthreads();
    }
    float mean = r1[0] * (1.f / DIMD);
    float var  = r2[0] * (1.f / DIMD) - mean * mean;
    float inv  = rsqrtf(var + 1e-5f);
    float* op = out + (size_t)tok * DIMD;
    #pragma unroll
    for (int i = 0; i < 4; i++) {
        int j = tid + i * 256;
        op[j] = (buf[j] - mean) * inv * g[j] + bb[j];
    }
}

// ---------------- per-expert masked token sums (partitioned) ----------------
__global__ void k_tsum()
{
    int part = blockIdx.x % TSPART;
    int b = (blockIdx.x / TSPART) % NB;
    int e = blockIdx.x / (TSPART * NB);
    int tid = threadIdx.x;
    const int CH = SLEN / TSPART;
    __shared__ int sslot[SLEN / TSPART];
    for (int j = tid; j < CH; j += 256) {
        int t = b*SLEN + part*CH + j;
        int s = -1;
        if (!(g_mtgt[t] | g_mmid[t])) {
            int a = g_inv[2*t], c = g_inv[2*t+1];
            if ((a >> 11) == e) s = a;
            else if ((c >> 11) == e) s = c;
        }
        sslot[j] = s;
    }
    __syncthreads();
    for (int d = tid; d < DIMD; d += 256) {
        float acc = 0.f;
        for (int j = 0; j < CH; j++) {
            int s = sslot[j];
            if (s >= 0) acc += g_contrib[(size_t)s * DIMD + d];
        }
        g_tsumP[(((e*NB + b)*TSPART) + part)*DIMD + d] = acc;
    }
}

// ---------------- expert logits ----------------
__global__ void k_logits(const float* __restrict__ cls_w, const float* __restrict__ cls_b,
                         float* __restrict__ out_logits)
{
    int tid = threadIdx.x;
    __shared__ float red[256];
    __shared__ float dss[NEXP*NB];
    __shared__ float den[NB];
    for (int b = 0; b < NB; b++) {
        float c = 0.f;
        for (int j = tid; j < SLEN; j += 256)
            c += (!(g_mtgt[b*SLEN+j] | g_mmid[b*SLEN+j])) ? 1.f : 0.f;
        red[tid] = c; __syncthreads();
        for (int s = 128; s > 0; s >>= 1) { if (tid < s) red[tid] += red[tid+s]; __syncthreads(); }
        if (tid == 0) den[b] = fmaxf(red[0], 1.f);
        __syncthreads();
    }
    for (int eb = 0; eb < NEXP*NB; eb++) {
        float c = 0.f;
        for (int j = tid; j < DIMD; j += 256) {
            float t = 0.f;
            #pragma unroll
            for (int part = 0; part < TSPART; part++)
                t += g_tsumP[(eb*TSPART + part)*DIMD + j];
            c += t * cls_w[j];
        }
        red[tid] = c; __syncthreads();
        for (int s = 128; s > 0; s >>= 1) { if (tid < s) red[tid] += red[tid+s]; __syncthreads(); }
        if (tid == 0) dss[eb] = red[0];
        __syncthreads();
    }
    if (tid == 0) {
        for (int b = 0; b < NB; b++) {
            float pre = 0.f;
            for (int e = 0; e < NEXP; e++) {
                pre += dss[e*NB + b];
                out_logits[e*NB + b] = pre / den[b] + cls_b[0];
            }
        }
    }
}

// ---------------- host ----------------
struct GArg {
    const bf *Ah, *Al, *Bh, *Bl;
    float* C; bf *Ch, *Cl;
    int M, N, K, lda, ldb, ldc;
    long long sA1, sA2, sB1, sB2, sC1, sC2;
    int gz, bdiv, zmaps, swig;
    const float* bias; const int* rmA; const int* rmC;
    const float* rs; const int* cnt;
};

static void BG(const GArg& a)
{
    dim3 grid(a.N / 128, (a.M + 127) / 128, a.gz);
    k_bgemm<<<grid, 256, BG_SMEM>>>(
        a.Ah, a.Al, a.Bh, a.Bl, a.C, a.Ch, a.Cl, a.M, a.N, a.K, a.lda, a.ldb, a.ldc,
        a.sA1, a.sA2, a.sB1, a.sB2, a.sC1, a.sC2, a.bdiv, a.zmaps, a.swig,
        a.bias, a.rmA, a.rmC, a.rs, a.cnt);
}

extern "C" void kernel_launch(void* const* d_in, const int* in_sizes, int n_in,
                              void* d_out, int out_size)
{
    const float* x       = (const float*)d_in[0];
    const float* enc     = (const float*)d_in[1];
    const void*  src_mask_raw = d_in[2];
    const void*  tgt_mask_raw = d_in[3];
    const void*  tgt_mid_raw  = d_in[4];
    const float* ln1_g = (const float*)d_in[5];
    const float* ln1_b = (const float*)d_in[6];
    const float* ln2_g = (const float*)d_in[7];
    const float* ln2_b = (const float*)d_in[8];
    const float* ln3_g = (const float*)d_in[9];
    const float* ln3_b = (const float*)d_in[10];
    const float* sa_wq = (const float*)d_in[11];
    const float* sa_wk = (const float*)d_in[12];
    const float* sa_wv = (const float*)d_in[13];
    const float* sa_wo = (const float*)d_in[14];
    const float* sa_bo = (const float*)d_in[15];
    const float* ca_wq = (const float*)d_in[16];
    const float* ca_wk = (const float*)d_in[17];
    const float* ca_wv = (const float*)d_in[18];
    const float* ca_wo = (const float*)d_in[19];
    const float* ca_bo = (const float*)d_in[20];
    const float* gate_w = (const float*)d_in[21];
    const float* cls_w  = (const float*)d_in[22];
    const float* cls_b  = (const float*)d_in[23];
    const float* moe_w1 = (const float*)d_in[24];
    const float* moe_w2 = (const float*)d_in[25];
    const float* moe_w3 = (const float*)d_in[26];

    float* out = (float*)d_out;
    float* out_x      = out;
    float* out_logits = out + (size_t)NTOK * DIMD;
    float* out_probs  = out_logits + NEXP * NB;

    cudaFuncSetAttribute(k_bgemm, cudaFuncAttributeMaxDynamicSharedMemorySize, BG_SMEM);
    cudaFuncSetAttribute(k_fattn, cudaFuncAttributeMaxDynamicSharedMemorySize, FATTN_SMEM);

    float *pproj, *px1, *px2, *pcontrib, *pwslot;
    int *ptok, *pcnt;
    unsigned char *pmsrc, *pmtgt;
    bf *pxh,*pxl,*pawh,*pawl,*pw13h,*pw13l,*pw2h,*pw2l;
    bf *pqkh,*pqkl,*pvth,*pvtl,*path,*patl,*px1h,*px1l,*px2h,*px2l,*pgh,*pgl;
    cudaGetSymbolAddress((void**)&pproj, g_proj);
    cudaGetSymbolAddress((void**)&px1, g_x1);
    cudaGetSymbolAddress((void**)&px2, g_x2);
    cudaGetSymbolAddress((void**)&pcontrib, g_contrib);
    cudaGetSymbolAddress((void**)&pwslot, g_wslot);
    cudaGetSymbolAddress((void**)&ptok, g_tok);
    cudaGetSymbolAddress((void**)&pcnt, g_cnt);
    cudaGetSymbolAddress((void**)&pmsrc, g_msrc);
    cudaGetSymbolAddress((void**)&pmtgt, g_mtgt);
    cudaGetSymbolAddress((void**)&pxh, g_xh);   cudaGetSymbolAddress((void**)&pxl, g_xl);
    cudaGetSymbolAddress((void**)&pawh, g_awh); cudaGetSymbolAddress((void**)&pawl, g_awl);
    cudaGetSymbolAddress((void**)&pw13h, g_w13h); cudaGetSymbolAddress((void**)&pw13l, g_w13l);
    cudaGetSymbolAddress((void**)&pw2h, g_w2h); cudaGetSymbolAddress((void**)&pw2l, g_w2l);
    cudaGetSymbolAddress((void**)&pqkh, g_qkh); cudaGetSymbolAddress((void**)&pqkl, g_qkl);
    cudaGetSymbolAddress((void**)&pvth, g_vth); cudaGetSymbolAddress((void**)&pvtl, g_vtl);
    cudaGetSymbolAddress((void**)&path, g_ath); cudaGetSymbolAddress((void**)&patl, g_atl);
    cudaGetSymbolAddress((void**)&px1h, g_x1h); cudaGetSymbolAddress((void**)&px1l, g_x1l);
    cudaGetSymbolAddress((void**)&px2h, g_x2h); cudaGetSymbolAddress((void**)&px2l, g_x2l);
    cudaGetSymbolAddress((void**)&pgh, g_gh);   cudaGetSymbolAddress((void**)&pgl, g_gl);

    // enc planes live inside the x1 plane array at offset NTOK*DIMD
    bf* peh = px1h + (size_t)NTOK * DIMD;
    bf* pel = px1l + (size_t)NTOK * DIMD;

    const long long WMOE = (long long)DIMD * HIDD;
    const long long MM   = (long long)DIMD * INNERD;
    const long long W13  = 2LL * HIDD * DIMD;

    k_detect<<<1, 256>>>((const unsigned char*)tgt_mask_raw);
    k_cvtmask<<<8, 256>>>(src_mask_raw, tgt_mask_raw, tgt_mid_raw);

    k_cvtA<<<512, 256>>>(x,   pxh, pxl, NTOK*DIMD/4);
    k_cvtA<<<512, 256>>>(enc, peh, pel, NTOK*DIMD/4);
    const float* aw[8] = {sa_wq, sa_wk, sa_wv, sa_wo, ca_wq, ca_wk, ca_wv, ca_wo};
    for (int i = 0; i < 8; i++)
        k_cvtT<<<dim3(INNERD/32, DIMD/32, 1), dim3(32,8)>>>(aw[i], pawh + i*MM, pawl + i*MM, DIMD, INNERD, 0, 0, 1, 0);
    k_cvtT<<<dim3(HIDD/32, DIMD/32, NEXP), dim3(32,8)>>>(moe_w1, pw13h, pw13l, DIMD, HIDD, WMOE, W13, 2, 0);
    k_cvtT<<<dim3(HIDD/32, DIMD/32, NEXP), dim3(32,8)>>>(moe_w3, pw13h, pw13l, DIMD, HIDD, WMOE, W13, 2, 1);
    k_cvtT<<<dim3(DIMD/32, HIDD/32, NEXP), dim3(32,8)>>>(moe_w2, pw2h, pw2l, HIDD, DIMD, WMOE, WMOE, 1, 0);

    GArg a{};

    for (int lam = 0; lam < 2; lam++) {
        const bf* cth = lam ? peh : pxh;   const bf* ctl = lam ? pel : pxl;
        int wb = lam * 4;
        const float* bo = lam ? ca_bo : sa_bo;
        unsigned char* msk = lam ? pmsrc : pmtgt;

        if (lam == 0) {
            // self: Q|K in one N=2048 launch (wq,wk contiguous)
            a = GArg{}; a.gz = 1; a.bdiv = 1;
            a.Ah = pxh; a.Al = pxl; a.Bh = pawh; a.Bl = pawl;
            a.Ch = pqkh; a.Cl = pqkl;
            a.M = NTOK; a.N = 2*INNERD; a.K = DIMD; a.lda = DIMD; a.ldb = DIMD; a.ldc = 2*INNERD;
            BG(a);
        } else {
            // cross: Q (A=x1, B=ca_wq) and K (A=enc, B=ca_wk) z-batched in one launch
            a = GArg{}; a.gz = 2; a.bdiv = 1;
            a.Ah = px1h; a.Al = px1l;
            a.Bh = pawh + 4*MM; a.Bl = pawl + 4*MM;
            a.Ch = pqkh; a.Cl = pqkl;
            a.M = NTOK; a.N = INNERD; a.K = DIMD; a.lda = DIMD; a.ldb = DIMD; a.ldc = 2*INNERD;
            a.sA2 = (long long)NTOK * DIMD;     // z=1 -> enc region
            a.sB2 = MM;                          // z=1 -> ca_wk
            a.sC2 = INNERD;                      // z=1 -> K columns
            BG(a);
        }
        // vT = Wv' @ ctxT
        a = GArg{}; a.gz = 1; a.bdiv = 1;
        a.Ah = pawh + (wb+2)*MM; a.Al = pawl + (wb+2)*MM; a.Bh = cth; a.Bl = ctl;
        a.Ch = pvth; a.Cl = pvtl;
        a.M = INNERD; a.N = NTOK; a.K = DIMD; a.lda = DIMD; a.ldb = DIMD; a.ldc = NTOK;
        BG(a);
        k_fattn<<<dim3(SLEN/128, HEADS, NB), 256, FATTN_SMEM>>>(
            pqkh, pqkl, pvth, pvtl, path, patl, msk);
        a = GArg{}; a.gz = 1; a.bdiv = 1;
        a.Ah = path; a.Al = patl; a.Bh = pawh + (wb+3)*MM; a.Bl = pawl + (wb+3)*MM;
        a.C = pproj; a.bias = bo;
        a.M = NTOK; a.N = DIMD; a.K = INNERD; a.lda = INNERD; a.ldb = INNERD; a.ldc = DIMD;
        BG(a);
        if (lam == 0)
            k_addln<<<NTOK, 256>>>(x, pproj, ln1_g, ln1_b, px1, px1h, px1l);
        else
            k_addln<<<NTOK, 256>>>(px1, pproj, ln2_g, ln2_b, px2, px2h, px2l);
    }

    k_route<<<NTOK, 256>>>(px2, gate_w, out_probs);
    a = GArg{}; a.gz = NEXP; a.bdiv = NEXP; a.zmaps = 1; a.swig = 1;
    a.Ah = px2h; a.Al = px2l; a.Bh = pw13h; a.Bl = pw13l;
    a.Ch = pgh; a.Cl = pgl;
    a.M = NTOK; a.N = 2*HIDD; a.K = DIMD; a.lda = DIMD; a.ldb = DIMD; a.ldc = HIDD;
    a.sB1 = W13; a.sC1 = (long long)NTOK*HIDD;
    a.rmA = ptok; a.cnt = pcnt;
    BG(a);
    a = GArg{}; a.gz = NEXP; a.bdiv = NEXP; a.zmaps = 1;
    a.Ah = pgh; a.Al = pgl; a.Bh = pw2h; a.Bl = pw2l; a.C = pcontrib;
    a.M = NTOK; a.N = DIMD; a.K = HIDD; a.lda = HIDD; a.ldb = HIDD; a.ldc = DIMD;
    a.sA1 = (long long)NTOK*HIDD; a.sB1 = WMOE; a.sC1 = (long long)NTOK*DIMD;
    a.rs = pwslot; a.cnt = pcnt;
    BG(a);

    k_moe_final<<<NTOK, 256>>>(px2, ln3_g, ln3_b, out_x);
    k_tsum<<<NEXP*NB*TSPART, 256>>>();
    k_logits<<<1, 256>>>(cls_w, cls_b, out_logits);
}

// round 12
// speedup vs baseline: 1.0221x; 1.0111x over previous
#include <cuda_runtime.h>
#include <cuda_bf16.h>
#include <math.h>

#define DIMD   1024
#define HEADS  16
#define DHEAD  64
#define HIDD   2048
#define NEXP   8
#define NB     2
#define SLEN   1024
#define NTOK   (NB*SLEN)
#define INNERD (HEADS*DHEAD)
#define NEGMIN (-3.402823466e38f)
#define SCL2   0.18033688011112042f   // 0.125 * log2(e)
#define TSPART 8

typedef __nv_bfloat16 bf;

// ---------------- device scratch ----------------
__device__ float g_proj[NTOK*DIMD];
__device__ float g_x1[NTOK*DIMD];
__device__ float g_x2[NTOK*DIMD];
__device__ float g_contrib[(size_t)NEXP*NTOK*DIMD];
__device__ float g_wslot[NEXP*NTOK];
__device__ int   g_tok[NEXP*NTOK];
__device__ int   g_inv[NTOK*2];
__device__ int   g_cnt[NEXP];
__device__ float g_tsumP[NEXP*NB*TSPART*DIMD];
__device__ bf g_xh[NTOK*DIMD],  g_xl[NTOK*DIMD];
__device__ bf g_x1h[2*NTOK*DIMD], g_x1l[2*NTOK*DIMD];   // x1 | enc planes
__device__ bf g_awh[8*DIMD*INNERD], g_awl[8*DIMD*INNERD];
__device__ bf g_w13h[(size_t)NEXP*2*HIDD*DIMD], g_w13l[(size_t)NEXP*2*HIDD*DIMD];
__device__ bf g_w2h[(size_t)NEXP*HIDD*DIMD], g_w2l[(size_t)NEXP*HIDD*DIMD];
__device__ bf g_qkh[NTOK*2*INNERD], g_qkl[NTOK*2*INNERD];
__device__ bf g_vth[NTOK*INNERD], g_vtl[NTOK*INNERD];
__device__ bf g_ath[NTOK*INNERD], g_atl[NTOK*INNERD];
__device__ bf g_x2h[NTOK*DIMD], g_x2l[NTOK*DIMD];
__device__ bf g_gh[(size_t)NEXP*NTOK*HIDD], g_gl[(size_t)NEXP*NTOK*HIDD];
__device__ unsigned char g_msrc[NTOK];
__device__ unsigned char g_mtgt[NTOK];
__device__ unsigned char g_mmid[NTOK];
__device__ int g_mtype;

// ---------------- PTX helpers ----------------
__device__ __forceinline__ unsigned smem_u32(const void* p) {
    return (unsigned)__cvta_generic_to_shared(p);
}
__device__ __forceinline__ void cp16(unsigned d, const void* s, bool v) {
    if (v) asm volatile("cp.async.ca.shared.global [%0], [%1], 16;\n" :: "r"(d), "l"(s) : "memory");
    else   asm volatile("cp.async.ca.shared.global [%0], [%1], 16, 0;\n" :: "r"(d), "l"(s) : "memory");
}
#define CP_COMMIT asm volatile("cp.async.commit_group;\n" ::: "memory")
#define CP_WAIT0  asm volatile("cp.async.wait_group 0;\n" ::: "memory")
#define CP_WAIT1  asm volatile("cp.async.wait_group 1;\n" ::: "memory")

#define LDSM_X4(d0, d1, d2, d3, a) \
    asm volatile("ldmatrix.sync.aligned.m8n8.x4.shared.b16 {%0,%1,%2,%3}, [%4];" \
                 : "=r"(d0), "=r"(d1), "=r"(d2), "=r"(d3) : "r"(a))

#define MMA_OP(c, a, b) \
    asm volatile("mma.sync.aligned.m16n8k16.row.col.f32.bf16.bf16.f32 " \
                 "{%0,%1,%2,%3},{%4,%5,%6,%7},{%8,%9},{%0,%1,%2,%3};" \
                 : "+f"((c)[0]), "+f"((c)[1]), "+f"((c)[2]), "+f"((c)[3]) \
                 : "r"((a)[0]), "r"((a)[1]), "r"((a)[2]), "r"((a)[3]), \
                   "r"((b)[0]), "r"((b)[1]))

__device__ __forceinline__ void pack2(float x, float y, unsigned& hi, unsigned& lo) {
    bf hx = __float2bfloat16(x), hy = __float2bfloat16(y);
    __nv_bfloat162 th; th.x = hx; th.y = hy;
    hi = *(unsigned*)&th;
    __nv_bfloat162 tl;
    tl.x = __float2bfloat16(x - __bfloat162float(hx));
    tl.y = __float2bfloat16(y - __bfloat162float(hy));
    lo = *(unsigned*)&tl;
}

// ---------------- mask detection / conversion ----------------
__global__ void k_detect(const unsigned char* __restrict__ tgt) {
    __shared__ int has_gt1, has_off;
    if (threadIdx.x == 0) { has_gt1 = 0; has_off = 0; }
    if (threadIdx.x < NEXP) g_cnt[threadIdx.x] = 0;
    __syncthreads();
    for (int j = threadIdx.x; j < NTOK; j += blockDim.x) {
        unsigned char v = tgt[j];
        if (v > 1) atomicOr(&has_gt1, 1);
        else if (v && (j & 3)) atomicOr(&has_off, 1);
    }
    __syncthreads();
    if (threadIdx.x == 0)
        g_mtype = has_gt1 ? 2 : (has_off ? 0 : 1);
}

__global__ void k_cvtmask(const void* __restrict__ s0, const void* __restrict__ s1,
                          const void* __restrict__ s2) {
    int t = g_mtype;
    int stride = gridDim.x * blockDim.x;
    for (int j = blockIdx.x * blockDim.x + threadIdx.x; j < NTOK; j += stride) {
        unsigned char a, b, c;
        if (t == 1) {
            a = ((const int*)s0)[j] != 0;
            b = ((const int*)s1)[j] != 0;
            c = ((const int*)s2)[j] != 0;
        } else if (t == 2) {
            a = ((const float*)s0)[j] != 0.f;
            b = ((const float*)s1)[j] != 0.f;
            c = ((const float*)s2)[j] != 0.f;
        } else {
            a = ((const unsigned char*)s0)[j];
            b = ((const unsigned char*)s1)[j];
            c = ((const unsigned char*)s2)[j];
        }
        g_msrc[j] = a; g_mtgt[j] = b; g_mmid[j] = c;
    }
}

// ---------------- conversion kernels ----------------
__global__ void k_cvtA(const float* __restrict__ s, bf* __restrict__ dh, bf* __restrict__ dl, int n4)
{
    int stride = gridDim.x * blockDim.x;
    for (int i = blockIdx.x * blockDim.x + threadIdx.x; i < n4; i += stride) {
        float4 v = ((const float4*)s)[i];
        float vv[4] = {v.x, v.y, v.z, v.w};
        bf h[4], l[4];
        #pragma unroll
        for (int j = 0; j < 4; j++) {
            h[j] = __float2bfloat16(vv[j]);
            l[j] = __float2bfloat16(vv[j] - __bfloat162float(h[j]));
        }
        ((ushort4*)dh)[i] = *(ushort4*)h;
        ((ushort4*)dl)[i] = *(ushort4*)l;
    }
}

// transpose-convert, 64x64 tile, vectorized: src fp32 [Kd][Nd] -> planes [Nd][Kd]
// dst row = nn*rowMul + rowAdd; writes are ushort4 (8B) per plane.
__global__ void k_cvtT(const float* __restrict__ src, bf* __restrict__ dh, bf* __restrict__ dl,
                       int Kd, int Nd, long long sSrc, long long sDst, int rowMul, int rowAdd)
{
    int z = blockIdx.z;
    src += (long long)z * sSrc; dh += (long long)z * sDst; dl += (long long)z * sDst;
    __shared__ float t[64][65];
    int k0 = blockIdx.y * 64, n0 = blockIdx.x * 64;
    int tx = threadIdx.x;   // 16
    int ty = threadIdx.y;   // 16
    #pragma unroll
    for (int i = 0; i < 4; i++) {
        int kk = k0 + ty + i * 16;
        float4 v = *(const float4*)&src[(long long)kk * Nd + n0 + tx * 4];
        t[ty + i * 16][tx * 4 + 0] = v.x;
        t[ty + i * 16][tx * 4 + 1] = v.y;
        t[ty + i * 16][tx * 4 + 2] = v.z;
        t[ty + i * 16][tx * 4 + 3] = v.w;
    }
    __syncthreads();
    #pragma unroll
    for (int j = 0; j < 4; j++) {
        int nn = n0 + ty + j * 16;
        bf h[4], l[4];
        #pragma unroll
        for (int c = 0; c < 4; c++) {
            float v = t[tx * 4 + c][ty + j * 16];
            h[c] = __float2bfloat16(v);
            l[c] = __float2bfloat16(v - __bfloat162float(h[c]));
        }
        long long dr = (long long)nn * rowMul + rowAdd;
        *(ushort4*)&dh[dr * Kd + k0 + tx * 4] = *(ushort4*)h;
        *(ushort4*)&dl[dr * Kd + k0 + tx * 4] = *(ushort4*)l;
    }
}

// ---------------- bf16-plane tensor-core GEMM (ldmatrix + 3-stage pipeline) ----------------
#define LDS_ 40
#define NSTG 3
#define OFFA(st, pl) (((st)*2 + (pl)) * 128 * LDS_ * 2)
#define OFFB(st, pl) (NSTG*2*128*LDS_*2 + ((st)*2 + (pl)) * 128 * LDS_ * 2)
#define BG_SROW (2 * NSTG*2*128*LDS_*2)
#define BG_SMEM (BG_SROW + 512 + 64)

__global__ void __launch_bounds__(256) k_bgemm(
    const bf* __restrict__ Ah, const bf* __restrict__ Al,
    const bf* __restrict__ Bh, const bf* __restrict__ Bl,
    float* __restrict__ C, bf* __restrict__ Ch, bf* __restrict__ Cl,
    int M, int N, int K, int lda, int ldb, int ldc,
    long long sA1, long long sA2, long long sB1, long long sB2,
    long long sC1, long long sC2, int bdiv, int zmaps, int swiglu,
    const float* __restrict__ bias,
    const int* __restrict__ rowmapA, const int* __restrict__ rowmapC,
    const float* __restrict__ rowscale, const int* __restrict__ cntPtr)
{
    int z = blockIdx.z;
    long long ao = (long long)(z / bdiv) * sA2 + (long long)(z % bdiv) * sA1;
    long long bo = (long long)(z / bdiv) * sB2 + (long long)(z % bdiv) * sB1;
    long long co = (long long)(z / bdiv) * sC2 + (long long)(z % bdiv) * sC1;
    const bf* Ahp = Ah + ao; const bf* Alp = Al + ao;
    const bf* Bhp = Bh + bo; const bf* Blp = Bl + bo;
    float* Cp = C ? C + co : nullptr;
    bf* Chp = Ch ? Ch + co : nullptr;
    bf* Clp = Cl ? Cl + co : nullptr;
    if (zmaps) {
        if (rowmapA) rowmapA += z * NTOK;
        if (rowmapC) rowmapC += z * NTOK;
        if (rowscale) rowscale += z * NTOK;
        if (cntPtr) cntPtr += z;
    }
    int Meff = M;
    if (cntPtr) { int c = *cntPtr; Meff = c < M ? c : M; }
    int m0 = blockIdx.y * 128;
    if (m0 >= Meff) return;
    int n0 = blockIdx.x * 128;

    extern __shared__ __align__(16) char dyn[];
    unsigned sb = smem_u32(dyn);
    int* sRow = (int*)(dyn + BG_SROW);

    int tid = threadIdx.x, lane = tid & 31, warp = tid >> 5;
    int warp_n = warp & 3, warp_m = warp >> 2;
    int lr = lane >> 2, lk = (lane & 3) * 2;
    int quad = lane >> 3, rin = lane & 7;

    for (int r = tid; r < 128; r += 256) {
        int gm = m0 + r;
        sRow[r] = (gm < Meff) ? (rowmapA ? rowmapA[gm] : gm) : 0;
    }
    __syncthreads();

    int a_r = rin + ((quad & 1) ? 8 : 0);
    int a_c = (quad & 2) ? 8 : 0;
    int b_r = rin + ((quad >> 1) ? 8 : 0);
    int b_c = (quad & 1) ? 8 : 0;
    int aoff[4], boff[2];
    #pragma unroll
    for (int tm = 0; tm < 4; tm++)
        aoff[tm] = ((warp_m * 64 + tm * 16 + a_r) * LDS_ + a_c) * 2;
    #pragma unroll
    for (int p = 0; p < 2; p++)
        boff[p] = ((warp_n * 32 + p * 16 + b_r) * LDS_ + b_c) * 2;

    auto loadStage = [&](int st, int k0) {
        #pragma unroll
        for (int i = 0; i < 2; i++) {
            int c = tid + i * 256;
            int row = c >> 2, q = c & 3;
            bool v = (m0 + row) < Meff;
            long long so = (long long)sRow[row] * lda + k0 + q * 8;
            unsigned ds = (row * LDS_ + q * 8) * 2;
            cp16(sb + OFFA(st, 0) + ds, Ahp + so, v);
            cp16(sb + OFFA(st, 1) + ds, Alp + so, v);
        }
        #pragma unroll
        for (int i = 0; i < 2; i++) {
            int c = tid + i * 256;
            int row = c >> 2, q = c & 3;
            long long so = (long long)(n0 + row) * ldb + k0 + q * 8;
            unsigned ds = (row * LDS_ + q * 8) * 2;
            cp16(sb + OFFB(st, 0) + ds, Bhp + so, true);
            cp16(sb + OFFB(st, 1) + ds, Blp + so, true);
        }
    };

    float acc[4][4][4];
    #pragma unroll
    for (int i = 0; i < 4; i++)
        #pragma unroll
        for (int j = 0; j < 4; j++)
            #pragma unroll
            for (int q = 0; q < 4; q++) acc[i][j][q] = 0.f;

    int KT = K >> 5;
    loadStage(0, 0); CP_COMMIT;
    loadStage(1, 32); CP_COMMIT;

    for (int kt = 0; kt < KT; kt++) {
        int s = kt % NSTG;
        if (kt + 1 < KT) { CP_WAIT1; } else { CP_WAIT0; }
        __syncthreads();
        if (kt + 2 < KT) { loadStage((kt + 2) % NSTG, (kt + 2) * 32); CP_COMMIT; }

        unsigned bAh = sb + OFFA(s, 0), bAl = sb + OFFA(s, 1);
        unsigned bBh = sb + OFFB(s, 0), bBl = sb + OFFB(s, 1);
        #pragma unroll
        for (int kc = 0; kc < 2; kc++) {
            unsigned afh[4][4], afl[4][4], bfh[4][2], bfl[4][2];
            #pragma unroll
            for (int tm = 0; tm < 4; tm++) {
                LDSM_X4(afh[tm][0], afh[tm][1], afh[tm][2], afh[tm][3], bAh + aoff[tm] + kc * 32);
                LDSM_X4(afl[tm][0], afl[tm][1], afl[tm][2], afl[tm][3], bAl + aoff[tm] + kc * 32);
            }
            #pragma unroll
            for (int p = 0; p < 2; p++) {
                LDSM_X4(bfh[2*p][0], bfh[2*p][1], bfh[2*p+1][0], bfh[2*p+1][1], bBh + boff[p] + kc * 32);
                LDSM_X4(bfl[2*p][0], bfl[2*p][1], bfl[2*p+1][0], bfl[2*p+1][1], bBl + boff[p] + kc * 32);
            }
            #pragma unroll
            for (int tm = 0; tm < 4; tm++)
                #pragma unroll
                for (int tn = 0; tn < 4; tn++) {
                    MMA_OP(acc[tm][tn], afh[tm], bfh[tn]);
                    MMA_OP(acc[tm][tn], afl[tm], bfh[tn]);
                    MMA_OP(acc[tm][tn], afh[tm], bfl[tn]);
                }
        }
    }

    #pragma unroll
    for (int tm = 0; tm < 4; tm++) {
        #pragma unroll
        for (int half = 0; half < 2; half++) {
            int gm = m0 + warp_m * 64 + tm * 16 + lr + half * 8;
            if (gm >= Meff) continue;
            float scale = rowscale ? rowscale[gm] : 1.f;
            long long crow = rowmapC ? (long long)rowmapC[gm] : (long long)gm;
            #pragma unroll
            for (int tn = 0; tn < 4; tn++) {
                int col = n0 + warp_n * 32 + tn * 8 + lk;
                float v0 = acc[tm][tn][half * 2 + 0];
                float v1 = acc[tm][tn][half * 2 + 1];
                if (swiglu) {
                    float g = v0 * v1 / (1.f + expf(-v0));
                    int j = col >> 1;
                    bf h = __float2bfloat16(g);
                    Chp[crow * ldc + j] = h;
                    Clp[crow * ldc + j] = __float2bfloat16(g - __bfloat162float(h));
                    continue;
                }
                v0 *= scale; v1 *= scale;
                if (bias) { v0 += bias[col]; v1 += bias[col + 1]; }
                if (Cp) *(float2*)&Cp[crow * ldc + col] = make_float2(v0, v1);
                if (Chp) {
                    unsigned hi, lo;
                    pack2(v0, v1, hi, lo);
                    *(unsigned*)&Chp[crow * ldc + col] = hi;
                    *(unsigned*)&Clp[crow * ldc + col] = lo;
                }
            }
        }
    }
}

// ---------------- fused flash attention (128-token chunks) ----------------
#define FATTN_SMEM (2*128*72*2*2 + 2*64*136*2*2 + 1024)
__global__ void __launch_bounds__(256) k_fattn(
    const bf* __restrict__ qkh, const bf* __restrict__ qkl,
    const bf* __restrict__ vth, const bf* __restrict__ vtl,
    bf* __restrict__ ohp, bf* __restrict__ olp,
    const unsigned char* __restrict__ mask)
{
    int m0 = blockIdx.x * 128;
    int h  = blockIdx.y;
    int b  = blockIdx.z;
    int tid = threadIdx.x, lane = tid & 31, warp = tid >> 5;
    int lr = lane >> 2, lk = (lane & 3) * 2;
    int quad = lane >> 3, rin = lane & 7;
    int b_r = rin + ((quad >> 1) ? 8 : 0);
    int b_c = (quad & 1) ? 8 : 0;

    extern __shared__ __align__(16) char smem[];
    bf* sKh = (bf*)smem;
    bf* sKl = sKh + 2*128*72;
    bf* sVh = sKl + 2*128*72;
    bf* sVl = sVh + 2*64*136;
    unsigned char* smask = (unsigned char*)(sVl + 2*64*136);
    unsigned kh_a = smem_u32(sKh);
    unsigned kl_a = smem_u32(sKl);
    unsigned vh_a = smem_u32(sVh);
    unsigned vl_a = smem_u32(sVl);

    for (int j = tid; j < SLEN; j += 256) smask[j] = mask[b*SLEN + j];

    int qrow = b*SLEN + m0 + warp*16;
    unsigned qfh[4][4], qfl[4][4];
    #pragma unroll
    for (int kc = 0; kc < 4; kc++) {
        long long b0 = (long long)(qrow + lr) * 2048 + h*64 + kc*16 + lk;
        long long b1 = b0 + 8LL*2048;
        qfh[kc][0] = *(const unsigned*)&qkh[b0];
        qfh[kc][1] = *(const unsigned*)&qkh[b1];
        qfh[kc][2] = *(const unsigned*)&qkh[b0 + 8];
        qfh[kc][3] = *(const unsigned*)&qkh[b1 + 8];
        qfl[kc][0] = *(const unsigned*)&qkl[b0];
        qfl[kc][1] = *(const unsigned*)&qkl[b1];
        qfl[kc][2] = *(const unsigned*)&qkl[b0 + 8];
        qfl[kc][3] = *(const unsigned*)&qkl[b1 + 8];
    }

    auto loadChunk = [&](int st, int c) {
        int t0 = c * 128;
        #pragma unroll
        for (int i = 0; i < 4; i++) {
            int idx = tid + i*256;
            int r = idx >> 3, q = idx & 7;
            long long src = (long long)(b*SLEN + t0 + r) * 2048 + 1024 + h*64 + q*8;
            cp16(kh_a + ((st*128 + r)*72 + q*8)*2, qkh + src, true);
            cp16(kl_a + ((st*128 + r)*72 + q*8)*2, qkl + src, true);
        }
        #pragma unroll
        for (int i = 0; i < 4; i++) {
            int idx = tid + i*256;
            int r = idx >> 4, q = idx & 15;
            long long src = (long long)(h*64 + r) * NTOK + b*SLEN + t0 + q*8;
            cp16(vh_a + ((st*64 + r)*136 + q*8)*2, vth + src, true);
            cp16(vl_a + ((st*64 + r)*136 + q*8)*2, vtl + src, true);
        }
    };

    float m0_ = -1e30f, m1_ = -1e30f, l0_ = 0.f, l1_ = 0.f;
    float o[8][4];
    #pragma unroll
    for (int i = 0; i < 8; i++) { o[i][0]=0.f; o[i][1]=0.f; o[i][2]=0.f; o[i][3]=0.f; }

    loadChunk(0, 0); CP_COMMIT;

    for (int c = 0; c < 8; c++) {
        int st = c & 1;
        CP_WAIT0; __syncthreads();
        if (c + 1 < 8) { loadChunk(st ^ 1, c + 1); CP_COMMIT; }

        float s[16][4];
        #pragma unroll
        for (int t = 0; t < 16; t++) { s[t][0]=0.f; s[t][1]=0.f; s[t][2]=0.f; s[t][3]=0.f; }
        #pragma unroll
        for (int kc = 0; kc < 4; kc++) {
            #pragma unroll
            for (int p = 0; p < 8; p++) {
                unsigned off = ((unsigned)(st*128 + p*16 + b_r)*72 + kc*16 + b_c)*2;
                unsigned bh[4], bl[4];
                LDSM_X4(bh[0], bh[1], bh[2], bh[3], kh_a + off);
                LDSM_X4(bl[0], bl[1], bl[2], bl[3], kl_a + off);
                MMA_OP(s[2*p],   qfh[kc], bh);
                MMA_OP(s[2*p],   qfl[kc], bh);
                MMA_OP(s[2*p],   qfh[kc], bl);
                MMA_OP(s[2*p+1], qfh[kc], bh + 2);
                MMA_OP(s[2*p+1], qfl[kc], bh + 2);
                MMA_OP(s[2*p+1], qfh[kc], bl + 2);
            }
        }
        #pragma unroll
        for (int t = 0; t < 16; t++) {
            int col = c*128 + t*8 + lk;
            bool k0m = smask[col] != 0;
            bool k1m = smask[col + 1] != 0;
            s[t][0] = k0m ? -1e30f : s[t][0] * SCL2;
            s[t][1] = k1m ? -1e30f : s[t][1] * SCL2;
            s[t][2] = k0m ? -1e30f : s[t][2] * SCL2;
            s[t][3] = k1m ? -1e30f : s[t][3] * SCL2;
        }
        float mx0 = -1e30f, mx1 = -1e30f;
        #pragma unroll
        for (int t = 0; t < 16; t++) {
            mx0 = fmaxf(mx0, fmaxf(s[t][0], s[t][1]));
            mx1 = fmaxf(mx1, fmaxf(s[t][2], s[t][3]));
        }
        mx0 = fmaxf(mx0, __shfl_xor_sync(0xffffffffu, mx0, 1));
        mx0 = fmaxf(mx0, __shfl_xor_sync(0xffffffffu, mx0, 2));
        mx1 = fmaxf(mx1, __shfl_xor_sync(0xffffffffu, mx1, 1));
        mx1 = fmaxf(mx1, __shfl_xor_sync(0xffffffffu, mx1, 2));
        float mn0 = fmaxf(m0_, mx0), mn1 = fmaxf(m1_, mx1);
        float a0 = exp2f(m0_ - mn0), a1 = exp2f(m1_ - mn1);
        m0_ = mn0; m1_ = mn1;
        float rs0 = 0.f, rs1 = 0.f;
        #pragma unroll
        for (int t = 0; t < 16; t++) {
            s[t][0] = exp2f(s[t][0] - mn0);
            s[t][1] = exp2f(s[t][1] - mn0);
            s[t][2] = exp2f(s[t][2] - mn1);
            s[t][3] = exp2f(s[t][3] - mn1);
            rs0 += s[t][0] + s[t][1];
            rs1 += s[t][2] + s[t][3];
        }
        l0_ = l0_ * a0 + rs0;
        l1_ = l1_ * a1 + rs1;
        #pragma unroll
        for (int dt = 0; dt < 8; dt++) {
            o[dt][0] *= a0; o[dt][1] *= a0; o[dt][2] *= a1; o[dt][3] *= a1;
        }
        #pragma unroll
        for (int kc = 0; kc < 8; kc++) {
            unsigned pah[4], pal[4];
            pack2(s[2*kc][0],   s[2*kc][1],   pah[0], pal[0]);
            pack2(s[2*kc][2],   s[2*kc][3],   pah[1], pal[1]);
            pack2(s[2*kc+1][0], s[2*kc+1][1], pah[2], pal[2]);
            pack2(s[2*kc+1][2], s[2*kc+1][3], pah[3], pal[3]);
            #pragma unroll
            for (int p = 0; p < 4; p++) {
                unsigned off = ((unsigned)(st*64 + p*16 + b_r)*136 + kc*16 + b_c)*2;
                unsigned bh[4], bl[4];
                LDSM_X4(bh[0], bh[1], bh[2], bh[3], vh_a + off);
                LDSM_X4(bl[0], bl[1], bl[2], bl[3], vl_a + off);
                MMA_OP(o[2*p],   pah, bh);
                MMA_OP(o[2*p],   pal, bh);
                MMA_OP(o[2*p],   pah, bl);
                MMA_OP(o[2*p+1], pah, bh + 2);
                MMA_OP(o[2*p+1], pal, bh + 2);
                MMA_OP(o[2*p+1], pah, bl + 2);
            }
        }
        __syncthreads();
    }

    l0_ += __shfl_xor_sync(0xffffffffu, l0_, 1);
    l0_ += __shfl_xor_sync(0xffffffffu, l0_, 2);
    l1_ += __shfl_xor_sync(0xffffffffu, l1_, 1);
    l1_ += __shfl_xor_sync(0xffffffffu, l1_, 2);
    float i0 = 1.f / l0_, i1 = 1.f / l1_;
    int row0 = qrow + lr, row1 = qrow + lr + 8;
    #pragma unroll
    for (int dt = 0; dt < 8; dt++) {
        int col = h*64 + dt*8 + lk;
        float v0 = o[dt][0]*i0, v1 = o[dt][1]*i0;
        float v2 = o[dt][2]*i1, v3 = o[dt][3]*i1;
        unsigned h01, l01, h23, l23;
        pack2(v0, v1, h01, l01);
        pack2(v2, v3, h23, l23);
        *(unsigned*)&ohp[(long long)row0*INNERD + col] = h01;
        *(unsigned*)&olp[(long long)row0*INNERD + col] = l01;
        *(unsigned*)&ohp[(long long)row1*INNERD + col] = h23;
        *(unsigned*)&olp[(long long)row1*INNERD + col] = l23;
    }
}

// ---------------- residual + layernorm ----------------
__global__ void k_addln(const float* __restrict__ x, const float* __restrict__ r,
                        const float* __restrict__ g, const float* __restrict__ bb,
                        float* __restrict__ out, bf* __restrict__ oh, bf* __restrict__ ol)
{
    int row = blockIdx.x;
    int tid = threadIdx.x;
    __shared__ float buf[DIMD];
    __shared__ float r1[256], r2[256];
    const float* xp = x + (size_t)row * DIMD;
    const float* rp = r + (size_t)row * DIMD;
    float s = 0.f, ss = 0.f;
    #pragma unroll
    for (int i = 0; i < 4; i++) {
        int j = tid + i * 256;
        float v = xp[j] + rp[j];
        buf[j] = v; s += v; ss += v * v;
    }
    r1[tid] = s; r2[tid] = ss; __syncthreads();
    for (int st = 128; st > 0; st >>= 1) {
        if (tid < st) { r1[tid] += r1[tid+st]; r2[tid] += r2[tid+st]; }
        __syncthreads();
    }
    float mean = r1[0] * (1.f / DIMD);
    float var  = r2[0] * (1.f / DIMD) - mean * mean;
    float inv  = rsqrtf(var + 1e-5f);
    #pragma unroll
    for (int i = 0; i < 4; i++) {
        int j = tid + i * 256;
        float v = (buf[j] - mean) * inv * g[j] + bb[j];
        out[(size_t)row * DIMD + j] = v;
        bf h = __float2bfloat16(v);
        oh[(size_t)row * DIMD + j] = h;
        ol[(size_t)row * DIMD + j] = __float2bfloat16(v - __bfloat162float(h));
    }
}

// ---------------- MoE router ----------------
__global__ void k_route(const float* __restrict__ xf, const float* __restrict__ gw,
                        float* __restrict__ probs_out)
{
    int tok = blockIdx.x;
    int tid = threadIdx.x;
    const float* xp = xf + (size_t)tok * DIMD;
    float part[NEXP] = {};
    for (int d = tid; d < DIMD; d += 256) {
        float xv = xp[d];
        #pragma unroll
        for (int e = 0; e < NEXP; e++) part[e] = fmaf(xv, gw[d*NEXP + e], part[e]);
    }
    __shared__ float sm[NEXP * 256];
    #pragma unroll
    for (int e = 0; e < NEXP; e++) sm[e*256 + tid] = part[e];
    __syncthreads();
    for (int s = 128; s > 0; s >>= 1) {
        if (tid < s) {
            #pragma unroll
            for (int e = 0; e < NEXP; e++) sm[e*256 + tid] += sm[e*256 + tid + s];
        }
        __syncthreads();
    }
    if (tid == 0) {
        float lg[NEXP], p[NEXP];
        float mx = NEGMIN;
        #pragma unroll
        for (int e = 0; e < NEXP; e++) { lg[e] = sm[e*256]; mx = fmaxf(mx, lg[e]); }
        float sum = 0.f;
        #pragma unroll
        for (int e = 0; e < NEXP; e++) { p[e] = expf(lg[e] - mx); sum += p[e]; }
        float inv = 1.f / sum;
        #pragma unroll
        for (int e = 0; e < NEXP; e++) { p[e] *= inv; probs_out[(size_t)tok*NEXP + e] = p[e]; }
        int i0 = 0;
        #pragma unroll
        for (int e = 1; e < NEXP; e++) if (p[e] > p[i0]) i0 = e;
        int i1 = (i0 == 0) ? 1 : 0;
        #pragma unroll
        for (int e = 0; e < NEXP; e++) if (e != i0 && p[e] > p[i1]) i1 = e;
        float w0 = p[i0], w1 = p[i1];
        float sw = 1.f / (w0 + w1);
        w0 *= sw; w1 *= sw;
        int pos = atomicAdd(&g_cnt[i0], 1);
        g_tok[i0*NTOK + pos] = tok; g_wslot[i0*NTOK + pos] = w0;
        g_inv[tok*2] = i0*NTOK + pos;
        pos = atomicAdd(&g_cnt[i1], 1);
        g_tok[i1*NTOK + pos] = tok; g_wslot[i1*NTOK + pos] = w1;
        g_inv[tok*2+1] = i1*NTOK + pos;
    }
}

// ---------------- final: 2 contribs + residual + LN3 ----------------
__global__ void k_moe_final(const float* __restrict__ x2, const float* __restrict__ g,
                            const float* __restrict__ bb, float* __restrict__ out)
{
    int tok = blockIdx.x;
    int tid = threadIdx.x;
    __shared__ float buf[DIMD];
    __shared__ float r1[256], r2[256];
    const float* xp = x2 + (size_t)tok * DIMD;
    int iv0 = g_inv[tok*2], iv1 = g_inv[tok*2+1];
    const float* c0 = g_contrib + (size_t)iv0 * DIMD;
    const float* c1 = g_contrib + (size_t)iv1 * DIMD;
    float s = 0.f, ss = 0.f;
    #pragma unroll
    for (int i = 0; i < 4; i++) {
        int j = tid + i * 256;
        float v = xp[j] + c0[j] + c1[j];
        buf[j] = v; s += v; ss += v * v;
    }
    r1[tid] = s; r2[tid] = ss; __syncthreads();
    for (int st = 128; st > 0; st >>= 1) {
        if (tid < st) { r1[tid] += r1[tid+st]; r2[tid] += r2[tid+st]; }
        __syncthreads();
    }
    float mean = r1[0] * (1.f / DIMD);
    float var  = r2[0] * (1.f / DIMD) - mean * mean;
    float inv  = rsqrtf(var + 1e-5f);
    float* op = out + (size_t)tok * DIMD;
    #pragma unroll
    for (int i = 0; i < 4; i++) {
        int j = tid + i * 256;
        op[j] = (buf[j] - mean) * inv * g[j] + bb[j];
    }
}

// ---------------- per-expert masked token sums (partitioned) ----------------
__global__ void k_tsum()
{
    int part = blockIdx.x % TSPART;
    int b = (blockIdx.x / TSPART) % NB;
    int e = blockIdx.x / (TSPART * NB);
    int tid = threadIdx.x;
    const int CH = SLEN / TSPART;
    __shared__ int sslot[SLEN / TSPART];
    for (int j = tid; j < CH; j += 256) {
        int t = b*SLEN + part*CH + j;
        int s = -1;
        if (!(g_mtgt[t] | g_mmid[t])) {
            int a = g_inv[2*t], c = g_inv[2*t+1];
            if ((a >> 11) == e) s = a;
            else if ((c >> 11) == e) s = c;
        }
        sslot[j] = s;
    }
    __syncthreads();
    for (int d = tid; d < DIMD; d += 256) {
        float acc = 0.f;
        for (int j = 0; j < CH; j++) {
            int s = sslot[j];
            if (s >= 0) acc += g_contrib[(size_t)s * DIMD + d];
        }
        g_tsumP[(((e*NB + b)*TSPART) + part)*DIMD + d] = acc;
    }
}

// ---------------- expert logits ----------------
__global__ void k_logits(const float* __restrict__ cls_w, const float* __restrict__ cls_b,
                         float* __restrict__ out_logits)
{
    int tid = threadIdx.x;
    __shared__ float red[256];
    __shared__ float dss[NEXP*NB];
    __shared__ float den[NB];
    for (int b = 0; b < NB; b++) {
        float c = 0.f;
        for (int j = tid; j < SLEN; j += 256)
            c += (!(g_mtgt[b*SLEN+j] | g_mmid[b*SLEN+j])) ? 1.f : 0.f;
        red[tid] = c; __syncthreads();
        for (int s = 128; s > 0; s >>= 1) { if (tid < s) red[tid] += red[tid+s]; __syncthreads(); }
        if (tid == 0) den[b] = fmaxf(red[0], 1.f);
        __syncthreads();
    }
    for (int eb = 0; eb < NEXP*NB; eb++) {
        float c = 0.f;
        for (int j = tid; j < DIMD; j += 256) {
            float t = 0.f;
            #pragma unroll
            for (int part = 0; part < TSPART; part++)
                t += g_tsumP[(eb*TSPART + part)*DIMD + j];
            c += t * cls_w[j];
        }
        red[tid] = c; __syncthreads();
        for (int s = 128; s > 0; s >>= 1) { if (tid < s) red[tid] += red[tid+s]; __syncthreads(); }
        if (tid == 0) dss[eb] = red[0];
        __syncthreads();
    }
    if (tid == 0) {
        for (int b = 0; b < NB; b++) {
            float pre = 0.f;
            for (int e = 0; e < NEXP; e++) {
                pre += dss[e*NB + b];
                out_logits[e*NB + b] = pre / den[b] + cls_b[0];
            }
        }
    }
}

// ---------------- host ----------------
struct GArg {
    const bf *Ah, *Al, *Bh, *Bl;
    float* C; bf *Ch, *Cl;
    int M, N, K, lda, ldb, ldc;
    long long sA1, sA2, sB1, sB2, sC1, sC2;
    int gz, bdiv, zmaps, swig;
    const float* bias; const int* rmA; const int* rmC;
    const float* rs; const int* cnt;
};

static void BG(const GArg& a)
{
    dim3 grid(a.N / 128, (a.M + 127) / 128, a.gz);
    k_bgemm<<<grid, 256, BG_SMEM>>>(
        a.Ah, a.Al, a.Bh, a.Bl, a.C, a.Ch, a.Cl, a.M, a.N, a.K, a.lda, a.ldb, a.ldc,
        a.sA1, a.sA2, a.sB1, a.sB2, a.sC1, a.sC2, a.bdiv, a.zmaps, a.swig,
        a.bias, a.rmA, a.rmC, a.rs, a.cnt);
}

extern "C" void kernel_launch(void* const* d_in, const int* in_sizes, int n_in,
                              void* d_out, int out_size)
{
    const float* x       = (const float*)d_in[0];
    const float* enc     = (const float*)d_in[1];
    const void*  src_mask_raw = d_in[2];
    const void*  tgt_mask_raw = d_in[3];
    const void*  tgt_mid_raw  = d_in[4];
    const float* ln1_g = (const float*)d_in[5];
    const float* ln1_b = (const float*)d_in[6];
    const float* ln2_g = (const float*)d_in[7];
    const float* ln2_b = (const float*)d_in[8];
    const float* ln3_g = (const float*)d_in[9];
    const float* ln3_b = (const float*)d_in[10];
    const float* sa_wq = (const float*)d_in[11];
    const float* sa_wk = (const float*)d_in[12];
    const float* sa_wv = (const float*)d_in[13];
    const float* sa_wo = (const float*)d_in[14];
    const float* sa_bo = (const float*)d_in[15];
    const float* ca_wq = (const float*)d_in[16];
    const float* ca_wk = (const float*)d_in[17];
    const float* ca_wv = (const float*)d_in[18];
    const float* ca_wo = (const float*)d_in[19];
    const float* ca_bo = (const float*)d_in[20];
    const float* gate_w = (const float*)d_in[21];
    const float* cls_w  = (const float*)d_in[22];
    const float* cls_b  = (const float*)d_in[23];
    const float* moe_w1 = (const float*)d_in[24];
    const float* moe_w2 = (const float*)d_in[25];
    const float* moe_w3 = (const float*)d_in[26];

    float* out = (float*)d_out;
    float* out_x      = out;
    float* out_logits = out + (size_t)NTOK * DIMD;
    float* out_probs  = out_logits + NEXP * NB;

    cudaFuncSetAttribute(k_bgemm, cudaFuncAttributeMaxDynamicSharedMemorySize, BG_SMEM);
    cudaFuncSetAttribute(k_fattn, cudaFuncAttributeMaxDynamicSharedMemorySize, FATTN_SMEM);

    float *pproj, *px1, *px2, *pcontrib, *pwslot;
    int *ptok, *pcnt;
    unsigned char *pmsrc, *pmtgt;
    bf *pxh,*pxl,*pawh,*pawl,*pw13h,*pw13l,*pw2h,*pw2l;
    bf *pqkh,*pqkl,*pvth,*pvtl,*path,*patl,*px1h,*px1l,*px2h,*px2l,*pgh,*pgl;
    cudaGetSymbolAddress((void**)&pproj, g_proj);
    cudaGetSymbolAddress((void**)&px1, g_x1);
    cudaGetSymbolAddress((void**)&px2, g_x2);
    cudaGetSymbolAddress((void**)&pcontrib, g_contrib);
    cudaGetSymbolAddress((void**)&pwslot, g_wslot);
    cudaGetSymbolAddress((void**)&ptok, g_tok);
    cudaGetSymbolAddress((void**)&pcnt, g_cnt);
    cudaGetSymbolAddress((void**)&pmsrc, g_msrc);
    cudaGetSymbolAddress((void**)&pmtgt, g_mtgt);
    cudaGetSymbolAddress((void**)&pxh, g_xh);   cudaGetSymbolAddress((void**)&pxl, g_xl);
    cudaGetSymbolAddress((void**)&pawh, g_awh); cudaGetSymbolAddress((void**)&pawl, g_awl);
    cudaGetSymbolAddress((void**)&pw13h, g_w13h); cudaGetSymbolAddress((void**)&pw13l, g_w13l);
    cudaGetSymbolAddress((void**)&pw2h, g_w2h); cudaGetSymbolAddress((void**)&pw2l, g_w2l);
    cudaGetSymbolAddress((void**)&pqkh, g_qkh); cudaGetSymbolAddress((void**)&pqkl, g_qkl);
    cudaGetSymbolAddress((void**)&pvth, g_vth); cudaGetSymbolAddress((void**)&pvtl, g_vtl);
    cudaGetSymbolAddress((void**)&path, g_ath); cudaGetSymbolAddress((void**)&patl, g_atl);
    cudaGetSymbolAddress((void**)&px1h, g_x1h); cudaGetSymbolAddress((void**)&px1l, g_x1l);
    cudaGetSymbolAddress((void**)&px2h, g_x2h); cudaGetSymbolAddress((void**)&px2l, g_x2l);
    cudaGetSymbolAddress((void**)&pgh, g_gh);   cudaGetSymbolAddress((void**)&pgl, g_gl);

    bf* peh = px1h + (size_t)NTOK * DIMD;
    bf* pel = px1l + (size_t)NTOK * DIMD;

    const long long WMOE = (long long)DIMD * HIDD;
    const long long MM   = (long long)DIMD * INNERD;
    const long long W13  = 2LL * HIDD * DIMD;

    k_detect<<<1, 256>>>((const unsigned char*)tgt_mask_raw);
    k_cvtmask<<<8, 256>>>(src_mask_raw, tgt_mask_raw, tgt_mid_raw);

    k_cvtA<<<512, 256>>>(x,   pxh, pxl, NTOK*DIMD/4);
    k_cvtA<<<512, 256>>>(enc, peh, pel, NTOK*DIMD/4);
    const float* aw[8] = {sa_wq, sa_wk, sa_wv, sa_wo, ca_wq, ca_wk, ca_wv, ca_wo};
    for (int i = 0; i < 8; i++)
        k_cvtT<<<dim3(INNERD/64, DIMD/64, 1), dim3(16,16)>>>(aw[i], pawh + i*MM, pawl + i*MM, DIMD, INNERD, 0, 0, 1, 0);
    k_cvtT<<<dim3(HIDD/64, DIMD/64, NEXP), dim3(16,16)>>>(moe_w1, pw13h, pw13l, DIMD, HIDD, WMOE, W13, 2, 0);
    k_cvtT<<<dim3(HIDD/64, DIMD/64, NEXP), dim3(16,16)>>>(moe_w3, pw13h, pw13l, DIMD, HIDD, WMOE, W13, 2, 1);
    k_cvtT<<<dim3(DIMD/64, HIDD/64, NEXP), dim3(16,16)>>>(moe_w2, pw2h, pw2l, HIDD, DIMD, WMOE, WMOE, 1, 0);

    GArg a{};

    for (int lam = 0; lam < 2; lam++) {
        const bf* cth = lam ? peh : pxh;   const bf* ctl = lam ? pel : pxl;
        int wb = lam * 4;
        const float* bo = lam ? ca_bo : sa_bo;
        unsigned char* msk = lam ? pmsrc : pmtgt;

        if (lam == 0) {
            a = GArg{}; a.gz = 1; a.bdiv = 1;
            a.Ah = pxh; a.Al = pxl; a.Bh = pawh; a.Bl = pawl;
            a.Ch = pqkh; a.Cl = pqkl;
            a.M = NTOK; a.N = 2*INNERD; a.K = DIMD; a.lda = DIMD; a.ldb = DIMD; a.ldc = 2*INNERD;
            BG(a);
        } else {
            a = GArg{}; a.gz = 2; a.bdiv = 1;
            a.Ah = px1h; a.Al = px1l;
            a.Bh = pawh + 4*MM; a.Bl = pawl + 4*MM;
            a.Ch = pqkh; a.Cl = pqkl;
            a.M = NTOK; a.N = INNERD; a.K = DIMD; a.lda = DIMD; a.ldb = DIMD; a.ldc = 2*INNERD;
            a.sA2 = (long long)NTOK * DIMD;
            a.sB2 = MM;
            a.sC2 = INNERD;
            BG(a);
        }
        a = GArg{}; a.gz = 1; a.bdiv = 1;
        a.Ah = pawh + (wb+2)*MM; a.Al = pawl + (wb+2)*MM; a.Bh = cth; a.Bl = ctl;
        a.Ch = pvth; a.Cl = pvtl;
        a.M = INNERD; a.N = NTOK; a.K = DIMD; a.lda = DIMD; a.ldb = DIMD; a.ldc = NTOK;
        BG(a);
        k_fattn<<<dim3(SLEN/128, HEADS, NB), 256, FATTN_SMEM>>>(
            pqkh, pqkl, pvth, pvtl, path, patl, msk);
        a = GArg{}; a.gz = 1; a.bdiv = 1;
        a.Ah = path; a.Al = patl; a.Bh = pawh + (wb+3)*MM; a.Bl = pawl + (wb+3)*MM;
        a.C = pproj; a.bias = bo;
        a.M = NTOK; a.N = DIMD; a.K = INNERD; a.lda = INNERD; a.ldb = INNERD; a.ldc = DIMD;
        BG(a);
        if (lam == 0)
            k_addln<<<NTOK, 256>>>(x, pproj, ln1_g, ln1_b, px1, px1h, px1l);
        else
            k_addln<<<NTOK, 256>>>(px1, pproj, ln2_g, ln2_b, px2, px2h, px2l);
    }

    k_route<<<NTOK, 256>>>(px2, gate_w, out_probs);
    a = GArg{}; a.gz = NEXP; a.bdiv = NEXP; a.zmaps = 1; a.swig = 1;
    a.Ah = px2h; a.Al = px2l; a.Bh = pw13h; a.Bl = pw13l;
    a.Ch = pgh; a.Cl = pgl;
    a.M = NTOK; a.N = 2*HIDD; a.K = DIMD; a.lda = DIMD; a.ldb = DIMD; a.ldc = HIDD;
    a.sB1 = W13; a.sC1 = (long long)NTOK*HIDD;
    a.rmA = ptok; a.cnt = pcnt;
    BG(a);
    a = GArg{}; a.gz = NEXP; a.bdiv = NEXP; a.zmaps = 1;
    a.Ah = pgh; a.Al = pgl; a.Bh = pw2h; a.Bl = pw2l; a.C = pcontrib;
    a.M = NTOK; a.N = DIMD; a.K = HIDD; a.lda = HIDD; a.ldb = HIDD; a.ldc = DIMD;
    a.sA1 = (long long)NTOK*HIDD; a.sB1 = WMOE; a.sC1 = (long long)NTOK*DIMD;
    a.rs = pwslot; a.cnt = pcnt;
    BG(a);

    k_moe_final<<<NTOK, 256>>>(px2, ln3_g, ln3_b, out_x);
    k_tsum<<<NEXP*NB*TSPART, 256>>>();
    k_logits<<<1, 256>>>(cls_w, cls_b, out_logits);
}

// round 13
// speedup vs baseline: 1.0338x; 1.0114x over previous
#include <cuda_runtime.h>
#include <cuda_bf16.h>
#include <math.h>

#define DIMD   1024
#define HEADS  16
#define DHEAD  64
#define HIDD   2048
#define NEXP   8
#define NB     2
#define SLEN   1024
#define NTOK   (NB*SLEN)
#define INNERD (HEADS*DHEAD)
#define QKVW   (3*INNERD)
#define NEGMIN (-3.402823466e38f)
#define SCL2   0.18033688011112042f   // 0.125 * log2(e)
#define TSPART 8

typedef __nv_bfloat16 bf;

// ---------------- device scratch ----------------
__device__ float g_proj[NTOK*DIMD];
__device__ float g_x1[NTOK*DIMD];
__device__ float g_x2[NTOK*DIMD];
__device__ float g_contrib[(size_t)NEXP*NTOK*DIMD];
__device__ float g_wslot[NEXP*NTOK];
__device__ int   g_tok[NEXP*NTOK];
__device__ int   g_inv[NTOK*2];
__device__ int   g_cnt[NEXP];
__device__ float g_tsumP[NEXP*NB*TSPART*DIMD];
__device__ bf g_xh[NTOK*DIMD],  g_xl[NTOK*DIMD];
__device__ bf g_x1h[2*NTOK*DIMD], g_x1l[2*NTOK*DIMD];   // x1 | enc planes
__device__ bf g_awh[8*DIMD*INNERD], g_awl[8*DIMD*INNERD];
__device__ bf g_w13h[(size_t)NEXP*2*HIDD*DIMD], g_w13l[(size_t)NEXP*2*HIDD*DIMD];
__device__ bf g_w2h[(size_t)NEXP*HIDD*DIMD], g_w2l[(size_t)NEXP*HIDD*DIMD];
__device__ bf g_qkvh[(size_t)NTOK*QKVW], g_qkvl[(size_t)NTOK*QKVW];  // [tok][q|k|v]
__device__ bf g_ath[NTOK*INNERD], g_atl[NTOK*INNERD];
__device__ bf g_x2h[NTOK*DIMD], g_x2l[NTOK*DIMD];
__device__ bf g_gh[(size_t)NEXP*NTOK*HIDD], g_gl[(size_t)NEXP*NTOK*HIDD];
__device__ unsigned char g_msrc[NTOK];
__device__ unsigned char g_mtgt[NTOK];
__device__ unsigned char g_mmid[NTOK];
__device__ int g_mtype;

// ---------------- PTX helpers ----------------
__device__ __forceinline__ unsigned smem_u32(const void* p) {
    return (unsigned)__cvta_generic_to_shared(p);
}
__device__ __forceinline__ void cp16(unsigned d, const void* s, bool v) {
    if (v) asm volatile("cp.async.ca.shared.global [%0], [%1], 16;\n" :: "r"(d), "l"(s) : "memory");
    else   asm volatile("cp.async.ca.shared.global [%0], [%1], 16, 0;\n" :: "r"(d), "l"(s) : "memory");
}
#define CP_COMMIT asm volatile("cp.async.commit_group;\n" ::: "memory")
#define CP_WAIT0  asm volatile("cp.async.wait_group 0;\n" ::: "memory")
#define CP_WAIT1  asm volatile("cp.async.wait_group 1;\n" ::: "memory")

#define LDSM_X4(d0, d1, d2, d3, a) \
    asm volatile("ldmatrix.sync.aligned.m8n8.x4.shared.b16 {%0,%1,%2,%3}, [%4];" \
                 : "=r"(d0), "=r"(d1), "=r"(d2), "=r"(d3) : "r"(a))

#define LDSM_X4T(d0, d1, d2, d3, a) \
    asm volatile("ldmatrix.sync.aligned.m8n8.x4.trans.shared.b16 {%0,%1,%2,%3}, [%4];" \
                 : "=r"(d0), "=r"(d1), "=r"(d2), "=r"(d3) : "r"(a))

#define MMA_OP(c, a, b) \
    asm volatile("mma.sync.aligned.m16n8k16.row.col.f32.bf16.bf16.f32 " \
                 "{%0,%1,%2,%3},{%4,%5,%6,%7},{%8,%9},{%0,%1,%2,%3};" \
                 : "+f"((c)[0]), "+f"((c)[1]), "+f"((c)[2]), "+f"((c)[3]) \
                 : "r"((a)[0]), "r"((a)[1]), "r"((a)[2]), "r"((a)[3]), \
                   "r"((b)[0]), "r"((b)[1]))

__device__ __forceinline__ void pack2(float x, float y, unsigned& hi, unsigned& lo) {
    bf hx = __float2bfloat16(x), hy = __float2bfloat16(y);
    __nv_bfloat162 th; th.x = hx; th.y = hy;
    hi = *(unsigned*)&th;
    __nv_bfloat162 tl;
    tl.x = __float2bfloat16(x - __bfloat162float(hx));
    tl.y = __float2bfloat16(y - __bfloat162float(hy));
    lo = *(unsigned*)&tl;
}

// ---------------- mask detection / conversion ----------------
__global__ void k_detect(const unsigned char* __restrict__ tgt) {
    __shared__ int has_gt1, has_off;
    if (threadIdx.x == 0) { has_gt1 = 0; has_off = 0; }
    if (threadIdx.x < NEXP) g_cnt[threadIdx.x] = 0;
    __syncthreads();
    for (int j = threadIdx.x; j < NTOK; j += blockDim.x) {
        unsigned char v = tgt[j];
        if (v > 1) atomicOr(&has_gt1, 1);
        else if (v && (j & 3)) atomicOr(&has_off, 1);
    }
    __syncthreads();
    if (threadIdx.x == 0)
        g_mtype = has_gt1 ? 2 : (has_off ? 0 : 1);
}

__global__ void k_cvtmask(const void* __restrict__ s0, const void* __restrict__ s1,
                          const void* __restrict__ s2) {
    int t = g_mtype;
    int stride = gridDim.x * blockDim.x;
    for (int j = blockIdx.x * blockDim.x + threadIdx.x; j < NTOK; j += stride) {
        unsigned char a, b, c;
        if (t == 1) {
            a = ((const int*)s0)[j] != 0;
            b = ((const int*)s1)[j] != 0;
            c = ((const int*)s2)[j] != 0;
        } else if (t == 2) {
            a = ((const float*)s0)[j] != 0.f;
            b = ((const float*)s1)[j] != 0.f;
            c = ((const float*)s2)[j] != 0.f;
        } else {
            a = ((const unsigned char*)s0)[j];
            b = ((const unsigned char*)s1)[j];
            c = ((const unsigned char*)s2)[j];
        }
        g_msrc[j] = a; g_mtgt[j] = b; g_mmid[j] = c;
    }
}

// ---------------- conversion kernels ----------------
__global__ void k_cvtA(const float* __restrict__ s, bf* __restrict__ dh, bf* __restrict__ dl, int n4)
{
    int stride = gridDim.x * blockDim.x;
    for (int i = blockIdx.x * blockDim.x + threadIdx.x; i < n4; i += stride) {
        float4 v = ((const float4*)s)[i];
        float vv[4] = {v.x, v.y, v.z, v.w};
        bf h[4], l[4];
        #pragma unroll
        for (int j = 0; j < 4; j++) {
            h[j] = __float2bfloat16(vv[j]);
            l[j] = __float2bfloat16(vv[j] - __bfloat162float(h[j]));
        }
        ((ushort4*)dh)[i] = *(ushort4*)h;
        ((ushort4*)dl)[i] = *(ushort4*)l;
    }
}

// transpose-convert, 64x64 tile, vectorized: src fp32 [Kd][Nd] -> planes [Nd][Kd]
__global__ void k_cvtT(const float* __restrict__ src, bf* __restrict__ dh, bf* __restrict__ dl,
                       int Kd, int Nd, long long sSrc, long long sDst, int rowMul, int rowAdd)
{
    int z = blockIdx.z;
    src += (long long)z * sSrc; dh += (long long)z * sDst; dl += (long long)z * sDst;
    __shared__ float t[64][65];
    int k0 = blockIdx.y * 64, n0 = blockIdx.x * 64;
    int tx = threadIdx.x;   // 16
    int ty = threadIdx.y;   // 16
    #pragma unroll
    for (int i = 0; i < 4; i++) {
        int kk = k0 + ty + i * 16;
        float4 v = *(const float4*)&src[(long long)kk * Nd + n0 + tx * 4];
        t[ty + i * 16][tx * 4 + 0] = v.x;
        t[ty + i * 16][tx * 4 + 1] = v.y;
        t[ty + i * 16][tx * 4 + 2] = v.z;
        t[ty + i * 16][tx * 4 + 3] = v.w;
    }
    __syncthreads();
    #pragma unroll
    for (int j = 0; j < 4; j++) {
        int nn = n0 + ty + j * 16;
        bf h[4], l[4];
        #pragma unroll
        for (int c = 0; c < 4; c++) {
            float v = t[tx * 4 + c][ty + j * 16];
            h[c] = __float2bfloat16(v);
            l[c] = __float2bfloat16(v - __bfloat162float(h[c]));
        }
        long long dr = (long long)nn * rowMul + rowAdd;
        *(ushort4*)&dh[dr * Kd + k0 + tx * 4] = *(ushort4*)h;
        *(ushort4*)&dl[dr * Kd + k0 + tx * 4] = *(ushort4*)l;
    }
}

// ---------------- bf16-plane tensor-core GEMM (ldmatrix + 3-stage pipeline) ----------------
#define LDS_ 40
#define NSTG 3
#define OFFA(st, pl) (((st)*2 + (pl)) * 128 * LDS_ * 2)
#define OFFB(st, pl) (NSTG*2*128*LDS_*2 + ((st)*2 + (pl)) * 128 * LDS_ * 2)
#define BG_SROW (2 * NSTG*2*128*LDS_*2)
#define BG_SMEM (BG_SROW + 512 + 64)

__global__ void __launch_bounds__(256) k_bgemm(
    const bf* __restrict__ Ah, const bf* __restrict__ Al,
    const bf* __restrict__ Bh, const bf* __restrict__ Bl,
    float* __restrict__ C, bf* __restrict__ Ch, bf* __restrict__ Cl,
    int M, int N, int K, int lda, int ldb, int ldc,
    long long sA1, long long sA2, long long sB1, long long sB2,
    long long sC1, long long sC2, int bdiv, int zmaps, int swiglu,
    const float* __restrict__ bias,
    const int* __restrict__ rowmapA, const int* __restrict__ rowmapC,
    const float* __restrict__ rowscale, const int* __restrict__ cntPtr)
{
    int z = blockIdx.z;
    long long ao = (long long)(z / bdiv) * sA2 + (long long)(z % bdiv) * sA1;
    long long bo = (long long)(z / bdiv) * sB2 + (long long)(z % bdiv) * sB1;
    long long co = (long long)(z / bdiv) * sC2 + (long long)(z % bdiv) * sC1;
    const bf* Ahp = Ah + ao; const bf* Alp = Al + ao;
    const bf* Bhp = Bh + bo; const bf* Blp = Bl + bo;
    float* Cp = C ? C + co : nullptr;
    bf* Chp = Ch ? Ch + co : nullptr;
    bf* Clp = Cl ? Cl + co : nullptr;
    if (zmaps) {
        if (rowmapA) rowmapA += z * NTOK;
        if (rowmapC) rowmapC += z * NTOK;
        if (rowscale) rowscale += z * NTOK;
        if (cntPtr) cntPtr += z;
    }
    int Meff = M;
    if (cntPtr) { int c = *cntPtr; Meff = c < M ? c : M; }
    int m0 = blockIdx.y * 128;
    if (m0 >= Meff) return;
    int n0 = blockIdx.x * 128;

    extern __shared__ __align__(16) char dyn[];
    unsigned sb = smem_u32(dyn);
    int* sRow = (int*)(dyn + BG_SROW);

    int tid = threadIdx.x, lane = tid & 31, warp = tid >> 5;
    int warp_n = warp & 3, warp_m = warp >> 2;
    int lr = lane >> 2, lk = (lane & 3) * 2;
    int quad = lane >> 3, rin = lane & 7;

    for (int r = tid; r < 128; r += 256) {
        int gm = m0 + r;
        sRow[r] = (gm < Meff) ? (rowmapA ? rowmapA[gm] : gm) : 0;
    }
    __syncthreads();

    int a_r = rin + ((quad & 1) ? 8 : 0);
    int a_c = (quad & 2) ? 8 : 0;
    int b_r = rin + ((quad >> 1) ? 8 : 0);
    int b_c = (quad & 1) ? 8 : 0;
    int aoff[4], boff[2];
    #pragma unroll
    for (int tm = 0; tm < 4; tm++)
        aoff[tm] = ((warp_m * 64 + tm * 16 + a_r) * LDS_ + a_c) * 2;
    #pragma unroll
    for (int p = 0; p < 2; p++)
        boff[p] = ((warp_n * 32 + p * 16 + b_r) * LDS_ + b_c) * 2;

    auto loadStage = [&](int st, int k0) {
        #pragma unroll
        for (int i = 0; i < 2; i++) {
            int c = tid + i * 256;
            int row = c >> 2, q = c & 3;
            bool v = (m0 + row) < Meff;
            long long so = (long long)sRow[row] * lda + k0 + q * 8;
            unsigned ds = (row * LDS_ + q * 8) * 2;
            cp16(sb + OFFA(st, 0) + ds, Ahp + so, v);
            cp16(sb + OFFA(st, 1) + ds, Alp + so, v);
        }
        #pragma unroll
        for (int i = 0; i < 2; i++) {
            int c = tid + i * 256;
            int row = c >> 2, q = c & 3;
            long long so = (long long)(n0 + row) * ldb + k0 + q * 8;
            unsigned ds = (row * LDS_ + q * 8) * 2;
            cp16(sb + OFFB(st, 0) + ds, Bhp + so, true);
            cp16(sb + OFFB(st, 1) + ds, Blp + so, true);
        }
    };

    float acc[4][4][4];
    #pragma unroll
    for (int i = 0; i < 4; i++)
        #pragma unroll
        for (int j = 0; j < 4; j++)
            #pragma unroll
            for (int q = 0; q < 4; q++) acc[i][j][q] = 0.f;

    int KT = K >> 5;
    loadStage(0, 0); CP_COMMIT;
    loadStage(1, 32); CP_COMMIT;

    for (int kt = 0; kt < KT; kt++) {
        int s = kt % NSTG;
        if (kt + 1 < KT) { CP_WAIT1; } else { CP_WAIT0; }
        __syncthreads();
        if (kt + 2 < KT) { loadStage((kt + 2) % NSTG, (kt + 2) * 32); CP_COMMIT; }

        unsigned bAh = sb + OFFA(s, 0), bAl = sb + OFFA(s, 1);
        unsigned bBh = sb + OFFB(s, 0), bBl = sb + OFFB(s, 1);
        #pragma unroll
        for (int kc = 0; kc < 2; kc++) {
            unsigned afh[4][4], afl[4][4], bfh[4][2], bfl[4][2];
            #pragma unroll
            for (int tm = 0; tm < 4; tm++) {
                LDSM_X4(afh[tm][0], afh[tm][1], afh[tm][2], afh[tm][3], bAh + aoff[tm] + kc * 32);
                LDSM_X4(afl[tm][0], afl[tm][1], afl[tm][2], afl[tm][3], bAl + aoff[tm] + kc * 32);
            }
            #pragma unroll
            for (int p = 0; p < 2; p++) {
                LDSM_X4(bfh[2*p][0], bfh[2*p][1], bfh[2*p+1][0], bfh[2*p+1][1], bBh + boff[p] + kc * 32);
                LDSM_X4(bfl[2*p][0], bfl[2*p][1], bfl[2*p+1][0], bfl[2*p+1][1], bBl + boff[p] + kc * 32);
            }
            #pragma unroll
            for (int tm = 0; tm < 4; tm++)
                #pragma unroll
                for (int tn = 0; tn < 4; tn++) {
                    MMA_OP(acc[tm][tn], afh[tm], bfh[tn]);
                    MMA_OP(acc[tm][tn], afl[tm], bfh[tn]);
                    MMA_OP(acc[tm][tn], afh[tm], bfl[tn]);
                }
        }
    }

    #pragma unroll
    for (int tm = 0; tm < 4; tm++) {
        #pragma unroll
        for (int half = 0; half < 2; half++) {
            int gm = m0 + warp_m * 64 + tm * 16 + lr + half * 8;
            if (gm >= Meff) continue;
            float scale = rowscale ? rowscale[gm] : 1.f;
            long long crow = rowmapC ? (long long)rowmapC[gm] : (long long)gm;
            #pragma unroll
            for (int tn = 0; tn < 4; tn++) {
                int col = n0 + warp_n * 32 + tn * 8 + lk;
                float v0 = acc[tm][tn][half * 2 + 0];
                float v1 = acc[tm][tn][half * 2 + 1];
                if (swiglu) {
                    float g = v0 * v1 / (1.f + expf(-v0));
                    int j = col >> 1;
                    bf h = __float2bfloat16(g);
                    Chp[crow * ldc + j] = h;
                    Clp[crow * ldc + j] = __float2bfloat16(g - __bfloat162float(h));
                    continue;
                }
                v0 *= scale; v1 *= scale;
                if (bias) { v0 += bias[col]; v1 += bias[col + 1]; }
                if (Cp) *(float2*)&Cp[crow * ldc + col] = make_float2(v0, v1);
                if (Chp) {
                    unsigned hi, lo;
                    pack2(v0, v1, hi, lo);
                    *(unsigned*)&Chp[crow * ldc + col] = hi;
                    *(unsigned*)&Clp[crow * ldc + col] = lo;
                }
            }
        }
    }
}

// ---------------- fused flash attention (qkv buffer, V via ldmatrix.trans) ----------------
#define FATTN_SMEM (4*(2*128*72*2) + 1024)
__global__ void __launch_bounds__(256) k_fattn(
    const bf* __restrict__ qkvh, const bf* __restrict__ qkvl,
    bf* __restrict__ ohp, bf* __restrict__ olp,
    const unsigned char* __restrict__ mask)
{
    int m0 = blockIdx.x * 128;
    int h  = blockIdx.y;
    int b  = blockIdx.z;
    int tid = threadIdx.x, lane = tid & 31, warp = tid >> 5;
    int lr = lane >> 2, lk = (lane & 3) * 2;
    int quad = lane >> 3, rin = lane & 7;
    int b_r = rin + ((quad >> 1) ? 8 : 0);
    int b_c = (quad & 1) ? 8 : 0;
    // V trans-ldmatrix per-lane indices
    int vrow = rin + 8 * ((lane >> 3) & 1);
    int vcol = 8 * (lane >> 4);

    extern __shared__ __align__(16) char smem[];
    bf* sKh = (bf*)smem;                 // [2][128][72]
    bf* sKl = sKh + 2*128*72;
    bf* sVh = sKl + 2*128*72;            // [2][128 tok][72]
    bf* sVl = sVh + 2*128*72;
    unsigned char* smask = (unsigned char*)(sVl + 2*128*72);
    unsigned kh_a = smem_u32(sKh);
    unsigned kl_a = smem_u32(sKl);
    unsigned vh_a = smem_u32(sVh);
    unsigned vl_a = smem_u32(sVl);

    for (int j = tid; j < SLEN; j += 256) smask[j] = mask[b*SLEN + j];

    int qrow = b*SLEN + m0 + warp*16;
    unsigned qfh[4][4], qfl[4][4];
    #pragma unroll
    for (int kc = 0; kc < 4; kc++) {
        long long b0 = (long long)(qrow + lr) * QKVW + h*64 + kc*16 + lk;
        long long b1 = b0 + 8LL*QKVW;
        qfh[kc][0] = *(const unsigned*)&qkvh[b0];
        qfh[kc][1] = *(const unsigned*)&qkvh[b1];
        qfh[kc][2] = *(const unsigned*)&qkvh[b0 + 8];
        qfh[kc][3] = *(const unsigned*)&qkvh[b1 + 8];
        qfl[kc][0] = *(const unsigned*)&qkvl[b0];
        qfl[kc][1] = *(const unsigned*)&qkvl[b1];
        qfl[kc][2] = *(const unsigned*)&qkvl[b0 + 8];
        qfl[kc][3] = *(const unsigned*)&qkvl[b1 + 8];
    }

    auto loadChunk = [&](int st, int c) {
        int t0 = c * 128;
        #pragma unroll
        for (int i = 0; i < 4; i++) {
            int idx = tid + i*256;
            int r = idx >> 3, q = idx & 7;
            long long srcK = (long long)(b*SLEN + t0 + r) * QKVW + INNERD + h*64 + q*8;
            long long srcV = srcK + INNERD;
            unsigned ds = ((st*128 + r)*72 + q*8)*2;
            cp16(kh_a + ds, qkvh + srcK, true);
            cp16(kl_a + ds, qkvl + srcK, true);
            cp16(vh_a + ds, qkvh + srcV, true);
            cp16(vl_a + ds, qkvl + srcV, true);
        }
    };

    float m0_ = -1e30f, m1_ = -1e30f, l0_ = 0.f, l1_ = 0.f;
    float o[8][4];
    #pragma unroll
    for (int i = 0; i < 8; i++) { o[i][0]=0.f; o[i][1]=0.f; o[i][2]=0.f; o[i][3]=0.f; }

    loadChunk(0, 0); CP_COMMIT;

    for (int c = 0; c < 8; c++) {
        int st = c & 1;
        CP_WAIT0; __syncthreads();
        if (c + 1 < 8) { loadChunk(st ^ 1, c + 1); CP_COMMIT; }

        float s[16][4];
        #pragma unroll
        for (int t = 0; t < 16; t++) { s[t][0]=0.f; s[t][1]=0.f; s[t][2]=0.f; s[t][3]=0.f; }
        #pragma unroll
        for (int kc = 0; kc < 4; kc++) {
            #pragma unroll
            for (int p = 0; p < 8; p++) {
                unsigned off = ((unsigned)(st*128 + p*16 + b_r)*72 + kc*16 + b_c)*2;
                unsigned bh[4], bl[4];
                LDSM_X4(bh[0], bh[1], bh[2], bh[3], kh_a + off);
                LDSM_X4(bl[0], bl[1], bl[2], bl[3], kl_a + off);
                MMA_OP(s[2*p],   qfh[kc], bh);
                MMA_OP(s[2*p],   qfl[kc], bh);
                MMA_OP(s[2*p],   qfh[kc], bl);
                MMA_OP(s[2*p+1], qfh[kc], bh + 2);
                MMA_OP(s[2*p+1], qfl[kc], bh + 2);
                MMA_OP(s[2*p+1], qfh[kc], bl + 2);
            }
        }
        #pragma unroll
        for (int t = 0; t < 16; t++) {
            int col = c*128 + t*8 + lk;
            bool k0m = smask[col] != 0;
            bool k1m = smask[col + 1] != 0;
            s[t][0] = k0m ? -1e30f : s[t][0] * SCL2;
            s[t][1] = k1m ? -1e30f : s[t][1] * SCL2;
            s[t][2] = k0m ? -1e30f : s[t][2] * SCL2;
            s[t][3] = k1m ? -1e30f : s[t][3] * SCL2;
        }
        float mx0 = -1e30f, mx1 = -1e30f;
        #pragma unroll
        for (int t = 0; t < 16; t++) {
            mx0 = fmaxf(mx0, fmaxf(s[t][0], s[t][1]));
            mx1 = fmaxf(mx1, fmaxf(s[t][2], s[t][3]));
        }
        mx0 = fmaxf(mx0, __shfl_xor_sync(0xffffffffu, mx0, 1));
        mx0 = fmaxf(mx0, __shfl_xor_sync(0xffffffffu, mx0, 2));
        mx1 = fmaxf(mx1, __shfl_xor_sync(0xffffffffu, mx1, 1));
        mx1 = fmaxf(mx1, __shfl_xor_sync(0xffffffffu, mx1, 2));
        float mn0 = fmaxf(m0_, mx0), mn1 = fmaxf(m1_, mx1);
        float a0 = exp2f(m0_ - mn0), a1 = exp2f(m1_ - mn1);
        m0_ = mn0; m1_ = mn1;
        float rs0 = 0.f, rs1 = 0.f;
        #pragma unroll
        for (int t = 0; t < 16; t++) {
            s[t][0] = exp2f(s[t][0] - mn0);
            s[t][1] = exp2f(s[t][1] - mn0);
            s[t][2] = exp2f(s[t][2] - mn1);
            s[t][3] = exp2f(s[t][3] - mn1);
            rs0 += s[t][0] + s[t][1];
            rs1 += s[t][2] + s[t][3];
        }
        l0_ = l0_ * a0 + rs0;
        l1_ = l1_ * a1 + rs1;
        #pragma unroll
        for (int dt = 0; dt < 8; dt++) {
            o[dt][0] *= a0; o[dt][1] *= a0; o[dt][2] *= a1; o[dt][3] *= a1;
        }
        #pragma unroll
        for (int kc = 0; kc < 8; kc++) {
            unsigned pah[4], pal[4];
            pack2(s[2*kc][0],   s[2*kc][1],   pah[0], pal[0]);
            pack2(s[2*kc][2],   s[2*kc][3],   pah[1], pal[1]);
            pack2(s[2*kc+1][0], s[2*kc+1][1], pah[2], pal[2]);
            pack2(s[2*kc+1][2], s[2*kc+1][3], pah[3], pal[3]);
            unsigned vbase = ((unsigned)(st*128 + kc*16 + vrow)*72 + vcol)*2;
            #pragma unroll
            for (int pp = 0; pp < 4; pp++) {
                unsigned off = vbase + pp * 32;   // pp*16 cols * 2B
                unsigned bh[4], bl[4];
                LDSM_X4T(bh[0], bh[1], bh[2], bh[3], vh_a + off);
                LDSM_X4T(bl[0], bl[1], bl[2], bl[3], vl_a + off);
                MMA_OP(o[2*pp],   pah, bh);
                MMA_OP(o[2*pp],   pal, bh);
                MMA_OP(o[2*pp],   pah, bl);
                MMA_OP(o[2*pp+1], pah, bh + 2);
                MMA_OP(o[2*pp+1], pal, bh + 2);
                MMA_OP(o[2*pp+1], pah, bl + 2);
            }
        }
        __syncthreads();
    }

    l0_ += __shfl_xor_sync(0xffffffffu, l0_, 1);
    l0_ += __shfl_xor_sync(0xffffffffu, l0_, 2);
    l1_ += __shfl_xor_sync(0xffffffffu, l1_, 1);
    l1_ += __shfl_xor_sync(0xffffffffu, l1_, 2);
    float i0 = 1.f / l0_, i1 = 1.f / l1_;
    int row0 = qrow + lr, row1 = qrow + lr + 8;
    #pragma unroll
    for (int dt = 0; dt < 8; dt++) {
        int col = h*64 + dt*8 + lk;
        float v0 = o[dt][0]*i0, v1 = o[dt][1]*i0;
        float v2 = o[dt][2]*i1, v3 = o[dt][3]*i1;
        unsigned h01, l01, h23, l23;
        pack2(v0, v1, h01, l01);
        pack2(v2, v3, h23, l23);
        *(unsigned*)&ohp[(long long)row0*INNERD + col] = h01;
        *(unsigned*)&olp[(long long)row0*INNERD + col] = l01;
        *(unsigned*)&ohp[(long long)row1*INNERD + col] = h23;
        *(unsigned*)&olp[(long long)row1*INNERD + col] = l23;
    }
}

// ---------------- residual + layernorm ----------------
__global__ void k_addln(const float* __restrict__ x, const float* __restrict__ r,
                        const float* __restrict__ g, const float* __restrict__ bb,
                        float* __restrict__ out, bf* __restrict__ oh, bf* __restrict__ ol)
{
    int row = blockIdx.x;
    int tid = threadIdx.x;
    __shared__ float buf[DIMD];
    __shared__ float r1[256], r2[256];
    const float* xp = x + (size_t)row * DIMD;
    const float* rp = r + (size_t)row * DIMD;
    float s = 0.f, ss = 0.f;
    #pragma unroll
    for (int i = 0; i < 4; i++) {
        int j = tid + i * 256;
        float v = xp[j] + rp[j];
        buf[j] = v; s += v; ss += v * v;
    }
    r1[tid] = s; r2[tid] = ss; __syncthreads();
    for (int st = 128; st > 0; st >>= 1) {
        if (tid < st) { r1[tid] += r1[tid+st]; r2[tid] += r2[tid+st]; }
        __syncthreads();
    }
    float mean = r1[0] * (1.f / DIMD);
    float var  = r2[0] * (1.f / DIMD) - mean * mean;
    float inv  = rsqrtf(var + 1e-5f);
    #pragma unroll
    for (int i = 0; i < 4; i++) {
        int j = tid + i * 256;
        float v = (buf[j] - mean) * inv * g[j] + bb[j];
        out[(size_t)row * DIMD + j] = v;
        bf h = __float2bfloat16(v);
        oh[(size_t)row * DIMD + j] = h;
        ol[(size_t)row * DIMD + j] = __float2bfloat16(v - __bfloat162float(h));
    }
}

// ---------------- MoE router ----------------
__global__ void k_route(const float* __restrict__ xf, const float* __restrict__ gw,
                        float* __restrict__ probs_out)
{
    int tok = blockIdx.x;
    int tid = threadIdx.x;
    const float* xp = xf + (size_t)tok * DIMD;
    float part[NEXP] = {};
    for (int d = tid; d < DIMD; d += 256) {
        float xv = xp[d];
        #pragma unroll
        for (int e = 0; e < NEXP; e++) part[e] = fmaf(xv, gw[d*NEXP + e], part[e]);
    }
    __shared__ float sm[NEXP * 256];
    #pragma unroll
    for (int e = 0; e < NEXP; e++) sm[e*256 + tid] = part[e];
    __syncthreads();
    for (int s = 128; s > 0; s >>= 1) {
        if (tid < s) {
            #pragma unroll
            for (int e = 0; e < NEXP; e++) sm[e*256 + tid] += sm[e*256 + tid + s];
        }
        __syncthreads();
    }
    if (tid == 0) {
        float lg[NEXP], p[NEXP];
        float mx = NEGMIN;
        #pragma unroll
        for (int e = 0; e < NEXP; e++) { lg[e] = sm[e*256]; mx = fmaxf(mx, lg[e]); }
        float sum = 0.f;
        #pragma unroll
        for (int e = 0; e < NEXP; e++) { p[e] = expf(lg[e] - mx); sum += p[e]; }
        float inv = 1.f / sum;
        #pragma unroll
        for (int e = 0; e < NEXP; e++) { p[e] *= inv; probs_out[(size_t)tok*NEXP + e] = p[e]; }
        int i0 = 0;
        #pragma unroll
        for (int e = 1; e < NEXP; e++) if (p[e] > p[i0]) i0 = e;
        int i1 = (i0 == 0) ? 1 : 0;
        #pragma unroll
        for (int e = 0; e < NEXP; e++) if (e != i0 && p[e] > p[i1]) i1 = e;
        float w0 = p[i0], w1 = p[i1];
        float sw = 1.f / (w0 + w1);
        w0 *= sw; w1 *= sw;
        int pos = atomicAdd(&g_cnt[i0], 1);
        g_tok[i0*NTOK + pos] = tok; g_wslot[i0*NTOK + pos] = w0;
        g_inv[tok*2] = i0*NTOK + pos;
        pos = atomicAdd(&g_cnt[i1], 1);
        g_tok[i1*NTOK + pos] = tok; g_wslot[i1*NTOK + pos] = w1;
        g_inv[tok*2+1] = i1*NTOK + pos;
    }
}

// ---------------- final: 2 contribs + residual + LN3 ----------------
__global__ void k_moe_final(const float* __restrict__ x2, const float* __restrict__ g,
                            const float* __restrict__ bb, float* __restrict__ out)
{
    int tok = blockIdx.x;
    int tid = threadIdx.x;
    __shared__ float buf[DIMD];
    __shared__ float r1[256], r2[256];
    const float* xp = x2 + (size_t)tok * DIMD;
    int iv0 = g_inv[tok*2], iv1 = g_inv[tok*2+1];
    const float* c0 = g_contrib + (size_t)iv0 * DIMD;
    const float* c1 = g_contrib + (size_t)iv1 * DIMD;
    float s = 0.f, ss = 0.f;
    #pragma unroll
    for (int i = 0; i < 4; i++) {
        int j = tid + i * 256;
        float v = xp[j] + c0[j] + c1[j];
        buf[j] = v; s += v; ss += v * v;
    }
    r1[tid] = s; r2[tid] = ss; __syncthreads();
    for (int st = 128; st > 0; st >>= 1) {
        if (tid < st) { r1[tid] += r1[tid+st]; r2[tid] += r2[tid+st]; }
        __syncthreads();
    }
    float mean = r1[0] * (1.f / DIMD);
    float var  = r2[0] * (1.f / DIMD) - mean * mean;
    float inv  = rsqrtf(var + 1e-5f);
    float* op = out + (size_t)tok * DIMD;
    #pragma unroll
    for (int i = 0; i < 4; i++) {
        int j = tid + i * 256;
        op[j] = (buf[j] - mean) * inv * g[j] + bb[j];
    }
}

// ---------------- per-expert masked token sums (partitioned) ----------------
__global__ void k_tsum()
{
    int part = blockIdx.x % TSPART;
    int b = (blockIdx.x / TSPART) % NB;
    int e = blockIdx.x / (TSPART * NB);
    int tid = threadIdx.x;
    const int CH = SLEN / TSPART;
    __shared__ int sslot[SLEN / TSPART];
    for (int j = tid; j < CH; j += 256) {
        int t = b*SLEN + part*CH + j;
        int s = -1;
        if (!(g_mtgt[t] | g_mmid[t])) {
            int a = g_inv[2*t], c = g_inv[2*t+1];
            if ((a >> 11) == e) s = a;
            else if ((c >> 11) == e) s = c;
        }
        sslot[j] = s;
    }
    __syncthreads();
    for (int d = tid; d < DIMD; d += 256) {
        float acc = 0.f;
        for (int j = 0; j < CH; j++) {
            int s = sslot[j];
            if (s >= 0) acc += g_contrib[(size_t)s * DIMD + d];
        }
        g_tsumP[(((e*NB + b)*TSPART) + part)*DIMD + d] = acc;
    }
}

// ---------------- expert logits ----------------
__global__ void k_logits(const float* __restrict__ cls_w, const float* __restrict__ cls_b,
                         float* __restrict__ out_logits)
{
    int tid = threadIdx.x;
    __shared__ float red[256];
    __shared__ float dss[NEXP*NB];
    __shared__ float den[NB];
    for (int b = 0; b < NB; b++) {
        float c = 0.f;
        for (int j = tid; j < SLEN; j += 256)
            c += (!(g_mtgt[b*SLEN+j] | g_mmid[b*SLEN+j])) ? 1.f : 0.f;
        red[tid] = c; __syncthreads();
        for (int s = 128; s > 0; s >>= 1) { if (tid < s) red[tid] += red[tid+s]; __syncthreads(); }
        if (tid == 0) den[b] = fmaxf(red[0], 1.f);
        __syncthreads();
    }
    for (int eb = 0; eb < NEXP*NB; eb++) {
        float c = 0.f;
        for (int j = tid; j < DIMD; j += 256) {
            float t = 0.f;
            #pragma unroll
            for (int part = 0; part < TSPART; part++)
                t += g_tsumP[(eb*TSPART + part)*DIMD + j];
            c += t * cls_w[j];
        }
        red[tid] = c; __syncthreads();
        for (int s = 128; s > 0; s >>= 1) { if (tid < s) red[tid] += red[tid+s]; __syncthreads(); }
        if (tid == 0) dss[eb] = red[0];
        __syncthreads();
    }
    if (tid == 0) {
        for (int b = 0; b < NB; b++) {
            float pre = 0.f;
            for (int e = 0; e < NEXP; e++) {
                pre += dss[e*NB + b];
                out_logits[e*NB + b] = pre / den[b] + cls_b[0];
            }
        }
    }
}

// ---------------- host ----------------
struct GArg {
    const bf *Ah, *Al, *Bh, *Bl;
    float* C; bf *Ch, *Cl;
    int M, N, K, lda, ldb, ldc;
    long long sA1, sA2, sB1, sB2, sC1, sC2;
    int gz, bdiv, zmaps, swig;
    const float* bias; const int* rmA; const int* rmC;
    const float* rs; const int* cnt;
};

static void BG(const GArg& a)
{
    dim3 grid(a.N / 128, (a.M + 127) / 128, a.gz);
    k_bgemm<<<grid, 256, BG_SMEM>>>(
        a.Ah, a.Al, a.Bh, a.Bl, a.C, a.Ch, a.Cl, a.M, a.N, a.K, a.lda, a.ldb, a.ldc,
        a.sA1, a.sA2, a.sB1, a.sB2, a.sC1, a.sC2, a.bdiv, a.zmaps, a.swig,
        a.bias, a.rmA, a.rmC, a.rs, a.cnt);
}

extern "C" void kernel_launch(void* const* d_in, const int* in_sizes, int n_in,
                              void* d_out, int out_size)
{
    const float* x       = (const float*)d_in[0];
    const float* enc     = (const float*)d_in[1];
    const void*  src_mask_raw = d_in[2];
    const void*  tgt_mask_raw = d_in[3];
    const void*  tgt_mid_raw  = d_in[4];
    const float* ln1_g = (const float*)d_in[5];
    const float* ln1_b = (const float*)d_in[6];
    const float* ln2_g = (const float*)d_in[7];
    const float* ln2_b = (const float*)d_in[8];
    const float* ln3_g = (const float*)d_in[9];
    const float* ln3_b = (const float*)d_in[10];
    const float* sa_wq = (const float*)d_in[11];
    const float* sa_wk = (const float*)d_in[12];
    const float* sa_wv = (const float*)d_in[13];
    const float* sa_wo = (const float*)d_in[14];
    const float* sa_bo = (const float*)d_in[15];
    const float* ca_wq = (const float*)d_in[16];
    const float* ca_wk = (const float*)d_in[17];
    const float* ca_wv = (const float*)d_in[18];
    const float* ca_wo = (const float*)d_in[19];
    const float* ca_bo = (const float*)d_in[20];
    const float* gate_w = (const float*)d_in[21];
    const float* cls_w  = (const float*)d_in[22];
    const float* cls_b  = (const float*)d_in[23];
    const float* moe_w1 = (const float*)d_in[24];
    const float* moe_w2 = (const float*)d_in[25];
    const float* moe_w3 = (const float*)d_in[26];

    float* out = (float*)d_out;
    float* out_x      = out;
    float* out_logits = out + (size_t)NTOK * DIMD;
    float* out_probs  = out_logits + NEXP * NB;

    cudaFuncSetAttribute(k_bgemm, cudaFuncAttributeMaxDynamicSharedMemorySize, BG_SMEM);
    cudaFuncSetAttribute(k_fattn, cudaFuncAttributeMaxDynamicSharedMemorySize, FATTN_SMEM);

    float *pproj, *px1, *px2, *pcontrib, *pwslot;
    int *ptok, *pcnt;
    unsigned char *pmsrc, *pmtgt;
    bf *pxh,*pxl,*pawh,*pawl,*pw13h,*pw13l,*pw2h,*pw2l;
    bf *pqkvh,*pqkvl,*path,*patl,*px1h,*px1l,*px2h,*px2l,*pgh,*pgl;
    cudaGetSymbolAddress((void**)&pproj, g_proj);
    cudaGetSymbolAddress((void**)&px1, g_x1);
    cudaGetSymbolAddress((void**)&px2, g_x2);
    cudaGetSymbolAddress((void**)&pcontrib, g_contrib);
    cudaGetSymbolAddress((void**)&pwslot, g_wslot);
    cudaGetSymbolAddress((void**)&ptok, g_tok);
    cudaGetSymbolAddress((void**)&pcnt, g_cnt);
    cudaGetSymbolAddress((void**)&pmsrc, g_msrc);
    cudaGetSymbolAddress((void**)&pmtgt, g_mtgt);
    cudaGetSymbolAddress((void**)&pxh, g_xh);   cudaGetSymbolAddress((void**)&pxl, g_xl);
    cudaGetSymbolAddress((void**)&pawh, g_awh); cudaGetSymbolAddress((void**)&pawl, g_awl);
    cudaGetSymbolAddress((void**)&pw13h, g_w13h); cudaGetSymbolAddress((void**)&pw13l, g_w13l);
    cudaGetSymbolAddress((void**)&pw2h, g_w2h); cudaGetSymbolAddress((void**)&pw2l, g_w2l);
    cudaGetSymbolAddress((void**)&pqkvh, g_qkvh); cudaGetSymbolAddress((void**)&pqkvl, g_qkvl);
    cudaGetSymbolAddress((void**)&path, g_ath); cudaGetSymbolAddress((void**)&patl, g_atl);
    cudaGetSymbolAddress((void**)&px1h, g_x1h); cudaGetSymbolAddress((void**)&px1l, g_x1l);
    cudaGetSymbolAddress((void**)&px2h, g_x2h); cudaGetSymbolAddress((void**)&px2l, g_x2l);
    cudaGetSymbolAddress((void**)&pgh, g_gh);   cudaGetSymbolAddress((void**)&pgl, g_gl);

    bf* peh = px1h + (size_t)NTOK * DIMD;
    bf* pel = px1l + (size_t)NTOK * DIMD;

    const long long WMOE = (long long)DIMD * HIDD;
    const long long MM   = (long long)DIMD * INNERD;
    const long long W13  = 2LL * HIDD * DIMD;

    k_detect<<<1, 256>>>((const unsigned char*)tgt_mask_raw);
    k_cvtmask<<<8, 256>>>(src_mask_raw, tgt_mask_raw, tgt_mid_raw);

    k_cvtA<<<512, 256>>>(x,   pxh, pxl, NTOK*DIMD/4);
    k_cvtA<<<512, 256>>>(enc, peh, pel, NTOK*DIMD/4);
    const float* aw[8] = {sa_wq, sa_wk, sa_wv, sa_wo, ca_wq, ca_wk, ca_wv, ca_wo};
    for (int i = 0; i < 8; i++)
        k_cvtT<<<dim3(INNERD/64, DIMD/64, 1), dim3(16,16)>>>(aw[i], pawh + i*MM, pawl + i*MM, DIMD, INNERD, 0, 0, 1, 0);
    k_cvtT<<<dim3(HIDD/64, DIMD/64, NEXP), dim3(16,16)>>>(moe_w1, pw13h, pw13l, DIMD, HIDD, WMOE, W13, 2, 0);
    k_cvtT<<<dim3(HIDD/64, DIMD/64, NEXP), dim3(16,16)>>>(moe_w3, pw13h, pw13l, DIMD, HIDD, WMOE, W13, 2, 1);
    k_cvtT<<<dim3(DIMD/64, HIDD/64, NEXP), dim3(16,16)>>>(moe_w2, pw2h, pw2l, HIDD, DIMD, WMOE, WMOE, 1, 0);

    GArg a{};

    for (int lam = 0; lam < 2; lam++) {
        int wb = lam * 4;
        const float* bo = lam ? ca_bo : sa_bo;
        unsigned char* msk = lam ? pmsrc : pmtgt;

        if (lam == 0) {
            // self: Q|K|V in one N=3072 launch (wq,wk,wv contiguous)
            a = GArg{}; a.gz = 1; a.bdiv = 1;
            a.Ah = pxh; a.Al = pxl; a.Bh = pawh; a.Bl = pawl;
            a.Ch = pqkvh; a.Cl = pqkvl;
            a.M = NTOK; a.N = QKVW; a.K = DIMD; a.lda = DIMD; a.ldb = DIMD; a.ldc = QKVW;
            BG(a);
        } else {
            // cross: Q (A=x1), K (A=enc), V (A=enc) z-batched via bdiv=2 stride trick
            a = GArg{}; a.gz = 3; a.bdiv = 2;
            a.Ah = px1h; a.Al = px1l;
            a.Bh = pawh + 4*MM; a.Bl = pawl + 4*MM;
            a.Ch = pqkvh; a.Cl = pqkvl;
            a.M = NTOK; a.N = INNERD; a.K = DIMD; a.lda = DIMD; a.ldb = DIMD; a.ldc = QKVW;
            a.sA1 = (long long)NTOK * DIMD;  a.sA2 = (long long)NTOK * DIMD;  // z1,z2 -> enc
            a.sB1 = MM;  a.sB2 = 2*MM;       // z1 -> ca_wk, z2 -> ca_wv
            a.sC1 = INNERD; a.sC2 = 2*INNERD; // z1 -> K cols, z2 -> V cols
            BG(a);
        }
        k_fattn<<<dim3(SLEN/128, HEADS, NB), 256, FATTN_SMEM>>>(
            pqkvh, pqkvl, path, patl, msk);
        a = GArg{}; a.gz = 1; a.bdiv = 1;
        a.Ah = path; a.Al = patl; a.Bh = pawh + (wb+3)*MM; a.Bl = pawl + (wb+3)*MM;
        a.C = pproj; a.bias = bo;
        a.M = NTOK; a.N = DIMD; a.K = INNERD; a.lda = INNERD; a.ldb = INNERD; a.ldc = DIMD;
        BG(a);
        if (lam == 0)
            k_addln<<<NTOK, 256>>>(x, pproj, ln1_g, ln1_b, px1, px1h, px1l);
        else
            k_addln<<<NTOK, 256>>>(px1, pproj, ln2_g, ln2_b, px2, px2h, px2l);
    }

    k_route<<<NTOK, 256>>>(px2, gate_w, out_probs);
    a = GArg{}; a.gz = NEXP; a.bdiv = NEXP; a.zmaps = 1; a.swig = 1;
    a.Ah = px2h; a.Al = px2l; a.Bh = pw13h; a.Bl = pw13l;
    a.Ch = pgh; a.Cl = pgl;
    a.M = NTOK; a.N = 2*HIDD; a.K = DIMD; a.lda = DIMD; a.ldb = DIMD; a.ldc = HIDD;
    a.sB1 = W13; a.sC1 = (long long)NTOK*HIDD;
    a.rmA = ptok; a.cnt = pcnt;
    BG(a);
    a = GArg{}; a.gz = NEXP; a.bdiv = NEXP; a.zmaps = 1;
    a.Ah = pgh; a.Al = pgl; a.Bh = pw2h; a.Bl = pw2l; a.C = pcontrib;
    a.M = NTOK; a.N = DIMD; a.K = HIDD; a.lda = HIDD; a.ldb = HIDD; a.ldc = DIMD;
    a.sA1 = (long long)NTOK*HIDD; a.sB1 = WMOE; a.sC1 = (long long)NTOK*DIMD;
    a.rs = pwslot; a.cnt = pcnt;
    BG(a);

    k_moe_final<<<NTOK, 256>>>(px2, ln3_g, ln3_b, out_x);
    k_tsum<<<NEXP*NB*TSPART, 256>>>();
    k_logits<<<1, 256>>>(cls_w, cls_b, out_logits);
}

// round 14
// speedup vs baseline: 1.0517x; 1.0173x over previous
#include <cuda_runtime.h>
#include <cuda_bf16.h>
#include <math.h>

#define DIMD   1024
#define HEADS  16
#define DHEAD  64
#define HIDD   2048
#define NEXP   8
#define NB     2
#define SLEN   1024
#define NTOK   (NB*SLEN)
#define INNERD (HEADS*DHEAD)
#define QKVW   (3*INNERD)
#define NEGMIN (-3.402823466e38f)
#define SCL2   0.18033688011112042f   // 0.125 * log2(e)
#define TSPART 8

typedef __nv_bfloat16 bf;

// ---------------- device scratch ----------------
__device__ float g_proj[NTOK*DIMD];
__device__ float g_x1[NTOK*DIMD];
__device__ float g_x2[NTOK*DIMD];
__device__ float g_contrib[(size_t)NEXP*NTOK*DIMD];
__device__ float g_wslot[NEXP*NTOK];
__device__ int   g_tok[NEXP*NTOK];
__device__ int   g_inv[NTOK*2];
__device__ int   g_cnt[NEXP];
__device__ float g_tsumP[NEXP*NB*TSPART*DIMD];
__device__ bf g_xh[NTOK*DIMD],  g_xl[NTOK*DIMD];
__device__ bf g_x1h[2*NTOK*DIMD], g_x1l[2*NTOK*DIMD];   // x1 | enc planes
__device__ bf g_awh[8*DIMD*INNERD], g_awl[8*DIMD*INNERD];
__device__ bf g_w13h[(size_t)NEXP*2*HIDD*DIMD], g_w13l[(size_t)NEXP*2*HIDD*DIMD];
__device__ bf g_w2h[(size_t)NEXP*HIDD*DIMD], g_w2l[(size_t)NEXP*HIDD*DIMD];
__device__ bf g_qkvh[(size_t)NTOK*QKVW], g_qkvl[(size_t)NTOK*QKVW];  // [tok][q|k|v]
__device__ bf g_ath[NTOK*INNERD], g_atl[NTOK*INNERD];
__device__ bf g_x2h[NTOK*DIMD], g_x2l[NTOK*DIMD];
__device__ bf g_gh[(size_t)NEXP*NTOK*HIDD], g_gl[(size_t)NEXP*NTOK*HIDD];
__device__ unsigned char g_msrc[NTOK];
__device__ unsigned char g_mtgt[NTOK];
__device__ unsigned char g_mmid[NTOK];
__device__ int g_mtype;

// ---------------- PTX helpers ----------------
__device__ __forceinline__ unsigned smem_u32(const void* p) {
    return (unsigned)__cvta_generic_to_shared(p);
}
__device__ __forceinline__ void cp16(unsigned d, const void* s, bool v) {
    if (v) asm volatile("cp.async.ca.shared.global [%0], [%1], 16;\n" :: "r"(d), "l"(s) : "memory");
    else   asm volatile("cp.async.ca.shared.global [%0], [%1], 16, 0;\n" :: "r"(d), "l"(s) : "memory");
}
#define CP_COMMIT asm volatile("cp.async.commit_group;\n" ::: "memory")
#define CP_WAIT0  asm volatile("cp.async.wait_group 0;\n" ::: "memory")
#define CP_WAIT1  asm volatile("cp.async.wait_group 1;\n" ::: "memory")

#define LDSM_X4(d0, d1, d2, d3, a) \
    asm volatile("ldmatrix.sync.aligned.m8n8.x4.shared.b16 {%0,%1,%2,%3}, [%4];" \
                 : "=r"(d0), "=r"(d1), "=r"(d2), "=r"(d3) : "r"(a))

#define LDSM_X4T(d0, d1, d2, d3, a) \
    asm volatile("ldmatrix.sync.aligned.m8n8.x4.trans.shared.b16 {%0,%1,%2,%3}, [%4];" \
                 : "=r"(d0), "=r"(d1), "=r"(d2), "=r"(d3) : "r"(a))

#define MMA_OP(c, a, b) \
    asm volatile("mma.sync.aligned.m16n8k16.row.col.f32.bf16.bf16.f32 " \
                 "{%0,%1,%2,%3},{%4,%5,%6,%7},{%8,%9},{%0,%1,%2,%3};" \
                 : "+f"((c)[0]), "+f"((c)[1]), "+f"((c)[2]), "+f"((c)[3]) \
                 : "r"((a)[0]), "r"((a)[1]), "r"((a)[2]), "r"((a)[3]), \
                   "r"((b)[0]), "r"((b)[1]))

__device__ __forceinline__ void pack2(float x, float y, unsigned& hi, unsigned& lo) {
    bf hx = __float2bfloat16(x), hy = __float2bfloat16(y);
    __nv_bfloat162 th; th.x = hx; th.y = hy;
    hi = *(unsigned*)&th;
    __nv_bfloat162 tl;
    tl.x = __float2bfloat16(x - __bfloat162float(hx));
    tl.y = __float2bfloat16(y - __bfloat162float(hy));
    lo = *(unsigned*)&tl;
}

// ---------------- mask detection / conversion ----------------
__global__ void k_detect(const unsigned char* __restrict__ tgt) {
    __shared__ int has_gt1, has_off;
    if (threadIdx.x == 0) { has_gt1 = 0; has_off = 0; }
    if (threadIdx.x < NEXP) g_cnt[threadIdx.x] = 0;
    __syncthreads();
    for (int j = threadIdx.x; j < NTOK; j += blockDim.x) {
        unsigned char v = tgt[j];
        if (v > 1) atomicOr(&has_gt1, 1);
        else if (v && (j & 3)) atomicOr(&has_off, 1);
    }
    __syncthreads();
    if (threadIdx.x == 0)
        g_mtype = has_gt1 ? 2 : (has_off ? 0 : 1);
}

__global__ void k_cvtmask(const void* __restrict__ s0, const void* __restrict__ s1,
                          const void* __restrict__ s2) {
    int t = g_mtype;
    int stride = gridDim.x * blockDim.x;
    for (int j = blockIdx.x * blockDim.x + threadIdx.x; j < NTOK; j += stride) {
        unsigned char a, b, c;
        if (t == 1) {
            a = ((const int*)s0)[j] != 0;
            b = ((const int*)s1)[j] != 0;
            c = ((const int*)s2)[j] != 0;
        } else if (t == 2) {
            a = ((const float*)s0)[j] != 0.f;
            b = ((const float*)s1)[j] != 0.f;
            c = ((const float*)s2)[j] != 0.f;
        } else {
            a = ((const unsigned char*)s0)[j];
            b = ((const unsigned char*)s1)[j];
            c = ((const unsigned char*)s2)[j];
        }
        g_msrc[j] = a; g_mtgt[j] = b; g_mmid[j] = c;
    }
}

// ---------------- conversion kernels ----------------
__global__ void k_cvtA(const float* __restrict__ s, bf* __restrict__ dh, bf* __restrict__ dl, int n4)
{
    int stride = gridDim.x * blockDim.x;
    for (int i = blockIdx.x * blockDim.x + threadIdx.x; i < n4; i += stride) {
        float4 v = ((const float4*)s)[i];
        float vv[4] = {v.x, v.y, v.z, v.w};
        bf h[4], l[4];
        #pragma unroll
        for (int j = 0; j < 4; j++) {
            h[j] = __float2bfloat16(vv[j]);
            l[j] = __float2bfloat16(vv[j] - __bfloat162float(h[j]));
        }
        ((ushort4*)dh)[i] = *(ushort4*)h;
        ((ushort4*)dl)[i] = *(ushort4*)l;
    }
}

// transpose-convert, 64x64 tile, vectorized: src fp32 [Kd][Nd] -> planes [Nd][Kd]
__global__ void k_cvtT(const float* __restrict__ src, bf* __restrict__ dh, bf* __restrict__ dl,
                       int Kd, int Nd, long long sSrc, long long sDst, int rowMul, int rowAdd)
{
    int z = blockIdx.z;
    src += (long long)z * sSrc; dh += (long long)z * sDst; dl += (long long)z * sDst;
    __shared__ float t[64][65];
    int k0 = blockIdx.y * 64, n0 = blockIdx.x * 64;
    int tx = threadIdx.x;   // 16
    int ty = threadIdx.y;   // 16
    #pragma unroll
    for (int i = 0; i < 4; i++) {
        int kk = k0 + ty + i * 16;
        float4 v = *(const float4*)&src[(long long)kk * Nd + n0 + tx * 4];
        t[ty + i * 16][tx * 4 + 0] = v.x;
        t[ty + i * 16][tx * 4 + 1] = v.y;
        t[ty + i * 16][tx * 4 + 2] = v.z;
        t[ty + i * 16][tx * 4 + 3] = v.w;
    }
    __syncthreads();
    #pragma unroll
    for (int j = 0; j < 4; j++) {
        int nn = n0 + ty + j * 16;
        bf h[4], l[4];
        #pragma unroll
        for (int c = 0; c < 4; c++) {
            float v = t[tx * 4 + c][ty + j * 16];
            h[c] = __float2bfloat16(v);
            l[c] = __float2bfloat16(v - __bfloat162float(h[c]));
        }
        long long dr = (long long)nn * rowMul + rowAdd;
        *(ushort4*)&dh[dr * Kd + k0 + tx * 4] = *(ushort4*)h;
        *(ushort4*)&dl[dr * Kd + k0 + tx * 4] = *(ushort4*)l;
    }
}

// ---------------- bf16-plane tensor-core GEMM (ldmatrix + 3-stage pipeline) ----------------
#define LDS_ 40
#define NSTG 3
#define OFFA(st, pl) (((st)*2 + (pl)) * 128 * LDS_ * 2)
#define OFFB(st, pl) (NSTG*2*128*LDS_*2 + ((st)*2 + (pl)) * 128 * LDS_ * 2)
#define BG_SROW (2 * NSTG*2*128*LDS_*2)
#define BG_SMEM (BG_SROW + 512 + 64)

__global__ void __launch_bounds__(256) k_bgemm(
    const bf* __restrict__ Ah, const bf* __restrict__ Al,
    const bf* __restrict__ Bh, const bf* __restrict__ Bl,
    float* __restrict__ C, bf* __restrict__ Ch, bf* __restrict__ Cl,
    int M, int N, int K, int lda, int ldb, int ldc,
    long long sA1, long long sA2, long long sB1, long long sB2,
    long long sC1, long long sC2, int bdiv, int zmaps, int swiglu,
    const float* __restrict__ bias,
    const int* __restrict__ rowmapA, const int* __restrict__ rowmapC,
    const float* __restrict__ rowscale, const int* __restrict__ cntPtr)
{
    int z = blockIdx.z;
    long long ao = (long long)(z / bdiv) * sA2 + (long long)(z % bdiv) * sA1;
    long long bo = (long long)(z / bdiv) * sB2 + (long long)(z % bdiv) * sB1;
    long long co = (long long)(z / bdiv) * sC2 + (long long)(z % bdiv) * sC1;
    const bf* Ahp = Ah + ao; const bf* Alp = Al + ao;
    const bf* Bhp = Bh + bo; const bf* Blp = Bl + bo;
    float* Cp = C ? C + co : nullptr;
    bf* Chp = Ch ? Ch + co : nullptr;
    bf* Clp = Cl ? Cl + co : nullptr;
    if (zmaps) {
        if (rowmapA) rowmapA += z * NTOK;
        if (rowmapC) rowmapC += z * NTOK;
        if (rowscale) rowscale += z * NTOK;
        if (cntPtr) cntPtr += z;
    }
    int Meff = M;
    if (cntPtr) { int c = *cntPtr; Meff = c < M ? c : M; }
    int m0 = blockIdx.y * 128;
    if (m0 >= Meff) return;
    int n0 = blockIdx.x * 128;

    extern __shared__ __align__(16) char dyn[];
    unsigned sb = smem_u32(dyn);
    int* sRow = (int*)(dyn + BG_SROW);

    int tid = threadIdx.x, lane = tid & 31, warp = tid >> 5;
    int warp_n = warp & 3, warp_m = warp >> 2;
    int lr = lane >> 2, lk = (lane & 3) * 2;
    int quad = lane >> 3, rin = lane & 7;

    for (int r = tid; r < 128; r += 256) {
        int gm = m0 + r;
        sRow[r] = (gm < Meff) ? (rowmapA ? rowmapA[gm] : gm) : 0;
    }
    __syncthreads();

    int a_r = rin + ((quad & 1) ? 8 : 0);
    int a_c = (quad & 2) ? 8 : 0;
    int b_r = rin + ((quad >> 1) ? 8 : 0);
    int b_c = (quad & 1) ? 8 : 0;
    int aoff[4], boff[2];
    #pragma unroll
    for (int tm = 0; tm < 4; tm++)
        aoff[tm] = ((warp_m * 64 + tm * 16 + a_r) * LDS_ + a_c) * 2;
    #pragma unroll
    for (int p = 0; p < 2; p++)
        boff[p] = ((warp_n * 32 + p * 16 + b_r) * LDS_ + b_c) * 2;

    auto loadStage = [&](int st, int k0) {
        #pragma unroll
        for (int i = 0; i < 2; i++) {
            int c = tid + i * 256;
            int row = c >> 2, q = c & 3;
            bool v = (m0 + row) < Meff;
            long long so = (long long)sRow[row] * lda + k0 + q * 8;
            unsigned ds = (row * LDS_ + q * 8) * 2;
            cp16(sb + OFFA(st, 0) + ds, Ahp + so, v);
            cp16(sb + OFFA(st, 1) + ds, Alp + so, v);
        }
        #pragma unroll
        for (int i = 0; i < 2; i++) {
            int c = tid + i * 256;
            int row = c >> 2, q = c & 3;
            long long so = (long long)(n0 + row) * ldb + k0 + q * 8;
            unsigned ds = (row * LDS_ + q * 8) * 2;
            cp16(sb + OFFB(st, 0) + ds, Bhp + so, true);
            cp16(sb + OFFB(st, 1) + ds, Blp + so, true);
        }
    };

    float acc[4][4][4];
    #pragma unroll
    for (int i = 0; i < 4; i++)
        #pragma unroll
        for (int j = 0; j < 4; j++)
            #pragma unroll
            for (int q = 0; q < 4; q++) acc[i][j][q] = 0.f;

    int KT = K >> 5;
    loadStage(0, 0); CP_COMMIT;
    loadStage(1, 32); CP_COMMIT;

    for (int kt = 0; kt < KT; kt++) {
        int s = kt % NSTG;
        if (kt + 1 < KT) { CP_WAIT1; } else { CP_WAIT0; }
        __syncthreads();
        if (kt + 2 < KT) { loadStage((kt + 2) % NSTG, (kt + 2) * 32); CP_COMMIT; }

        unsigned bAh = sb + OFFA(s, 0), bAl = sb + OFFA(s, 1);
        unsigned bBh = sb + OFFB(s, 0), bBl = sb + OFFB(s, 1);
        #pragma unroll
        for (int kc = 0; kc < 2; kc++) {
            unsigned afh[4][4], afl[4][4], bfh[4][2], bfl[4][2];
            #pragma unroll
            for (int tm = 0; tm < 4; tm++) {
                LDSM_X4(afh[tm][0], afh[tm][1], afh[tm][2], afh[tm][3], bAh + aoff[tm] + kc * 32);
                LDSM_X4(afl[tm][0], afl[tm][1], afl[tm][2], afl[tm][3], bAl + aoff[tm] + kc * 32);
            }
            #pragma unroll
            for (int p = 0; p < 2; p++) {
                LDSM_X4(bfh[2*p][0], bfh[2*p][1], bfh[2*p+1][0], bfh[2*p+1][1], bBh + boff[p] + kc * 32);
                LDSM_X4(bfl[2*p][0], bfl[2*p][1], bfl[2*p+1][0], bfl[2*p+1][1], bBl + boff[p] + kc * 32);
            }
            #pragma unroll
            for (int tm = 0; tm < 4; tm++)
                #pragma unroll
                for (int tn = 0; tn < 4; tn++) {
                    MMA_OP(acc[tm][tn], afh[tm], bfh[tn]);
                    MMA_OP(acc[tm][tn], afl[tm], bfh[tn]);
                    MMA_OP(acc[tm][tn], afh[tm], bfl[tn]);
                }
        }
    }

    #pragma unroll
    for (int tm = 0; tm < 4; tm++) {
        #pragma unroll
        for (int half = 0; half < 2; half++) {
            int gm = m0 + warp_m * 64 + tm * 16 + lr + half * 8;
            if (gm >= Meff) continue;
            float scale = rowscale ? rowscale[gm] : 1.f;
            long long crow = rowmapC ? (long long)rowmapC[gm] : (long long)gm;
            #pragma unroll
            for (int tn = 0; tn < 4; tn++) {
                int col = n0 + warp_n * 32 + tn * 8 + lk;
                float v0 = acc[tm][tn][half * 2 + 0];
                float v1 = acc[tm][tn][half * 2 + 1];
                if (swiglu) {
                    float g = v0 * v1 / (1.f + expf(-v0));
                    int j = col >> 1;
                    bf h = __float2bfloat16(g);
                    Chp[crow * ldc + j] = h;
                    Clp[crow * ldc + j] = __float2bfloat16(g - __bfloat162float(h));
                    continue;
                }
                v0 *= scale; v1 *= scale;
                if (bias) { v0 += bias[col]; v1 += bias[col + 1]; }
                if (Cp) *(float2*)&Cp[crow * ldc + col] = make_float2(v0, v1);
                if (Chp) {
                    unsigned hi, lo;
                    pack2(v0, v1, hi, lo);
                    *(unsigned*)&Chp[crow * ldc + col] = hi;
                    *(unsigned*)&Clp[crow * ldc + col] = lo;
                }
            }
        }
    }
}

// ---------------- fused flash attention (qkv buffer, V via ldmatrix.trans) ----------------
#define FATTN_SMEM (4*(2*128*72*2) + 1024)
__global__ void __launch_bounds__(256) k_fattn(
    const bf* __restrict__ qkvh, const bf* __restrict__ qkvl,
    bf* __restrict__ ohp, bf* __restrict__ olp,
    const unsigned char* __restrict__ mask)
{
    int m0 = blockIdx.x * 128;
    int h  = blockIdx.y;
    int b  = blockIdx.z;
    int tid = threadIdx.x, lane = tid & 31, warp = tid >> 5;
    int lr = lane >> 2, lk = (lane & 3) * 2;
    int quad = lane >> 3, rin = lane & 7;
    int b_r = rin + ((quad >> 1) ? 8 : 0);
    int b_c = (quad & 1) ? 8 : 0;
    int vrow = rin + 8 * ((lane >> 3) & 1);
    int vcol = 8 * (lane >> 4);

    extern __shared__ __align__(16) char smem[];
    bf* sKh = (bf*)smem;
    bf* sKl = sKh + 2*128*72;
    bf* sVh = sKl + 2*128*72;
    bf* sVl = sVh + 2*128*72;
    unsigned char* smask = (unsigned char*)(sVl + 2*128*72);
    unsigned kh_a = smem_u32(sKh);
    unsigned kl_a = smem_u32(sKl);
    unsigned vh_a = smem_u32(sVh);
    unsigned vl_a = smem_u32(sVl);

    for (int j = tid; j < SLEN; j += 256) smask[j] = mask[b*SLEN + j];

    int qrow = b*SLEN + m0 + warp*16;
    unsigned qfh[4][4], qfl[4][4];
    #pragma unroll
    for (int kc = 0; kc < 4; kc++) {
        long long b0 = (long long)(qrow + lr) * QKVW + h*64 + kc*16 + lk;
        long long b1 = b0 + 8LL*QKVW;
        qfh[kc][0] = *(const unsigned*)&qkvh[b0];
        qfh[kc][1] = *(const unsigned*)&qkvh[b1];
        qfh[kc][2] = *(const unsigned*)&qkvh[b0 + 8];
        qfh[kc][3] = *(const unsigned*)&qkvh[b1 + 8];
        qfl[kc][0] = *(const unsigned*)&qkvl[b0];
        qfl[kc][1] = *(const unsigned*)&qkvl[b1];
        qfl[kc][2] = *(const unsigned*)&qkvl[b0 + 8];
        qfl[kc][3] = *(const unsigned*)&qkvl[b1 + 8];
    }

    auto loadChunk = [&](int st, int c) {
        int t0 = c * 128;
        #pragma unroll
        for (int i = 0; i < 4; i++) {
            int idx = tid + i*256;
            int r = idx >> 3, q = idx & 7;
            long long srcK = (long long)(b*SLEN + t0 + r) * QKVW + INNERD + h*64 + q*8;
            long long srcV = srcK + INNERD;
            unsigned ds = ((st*128 + r)*72 + q*8)*2;
            cp16(kh_a + ds, qkvh + srcK, true);
            cp16(kl_a + ds, qkvl + srcK, true);
            cp16(vh_a + ds, qkvh + srcV, true);
            cp16(vl_a + ds, qkvl + srcV, true);
        }
    };

    float m0_ = -1e30f, m1_ = -1e30f, l0_ = 0.f, l1_ = 0.f;
    float o[8][4];
    #pragma unroll
    for (int i = 0; i < 8; i++) { o[i][0]=0.f; o[i][1]=0.f; o[i][2]=0.f; o[i][3]=0.f; }

    loadChunk(0, 0); CP_COMMIT;

    for (int c = 0; c < 8; c++) {
        int st = c & 1;
        CP_WAIT0; __syncthreads();
        if (c + 1 < 8) { loadChunk(st ^ 1, c + 1); CP_COMMIT; }

        float s[16][4];
        #pragma unroll
        for (int t = 0; t < 16; t++) { s[t][0]=0.f; s[t][1]=0.f; s[t][2]=0.f; s[t][3]=0.f; }
        #pragma unroll
        for (int kc = 0; kc < 4; kc++) {
            #pragma unroll
            for (int p = 0; p < 8; p++) {
                unsigned off = ((unsigned)(st*128 + p*16 + b_r)*72 + kc*16 + b_c)*2;
                unsigned bh[4], bl[4];
                LDSM_X4(bh[0], bh[1], bh[2], bh[3], kh_a + off);
                LDSM_X4(bl[0], bl[1], bl[2], bl[3], kl_a + off);
                MMA_OP(s[2*p],   qfh[kc], bh);
                MMA_OP(s[2*p],   qfl[kc], bh);
                MMA_OP(s[2*p],   qfh[kc], bl);
                MMA_OP(s[2*p+1], qfh[kc], bh + 2);
                MMA_OP(s[2*p+1], qfl[kc], bh + 2);
                MMA_OP(s[2*p+1], qfh[kc], bl + 2);
            }
        }
        #pragma unroll
        for (int t = 0; t < 16; t++) {
            int col = c*128 + t*8 + lk;
            bool k0m = smask[col] != 0;
            bool k1m = smask[col + 1] != 0;
            s[t][0] = k0m ? -1e30f : s[t][0] * SCL2;
            s[t][1] = k1m ? -1e30f : s[t][1] * SCL2;
            s[t][2] = k0m ? -1e30f : s[t][2] * SCL2;
            s[t][3] = k1m ? -1e30f : s[t][3] * SCL2;
        }
        float mx0 = -1e30f, mx1 = -1e30f;
        #pragma unroll
        for (int t = 0; t < 16; t++) {
            mx0 = fmaxf(mx0, fmaxf(s[t][0], s[t][1]));
            mx1 = fmaxf(mx1, fmaxf(s[t][2], s[t][3]));
        }
        mx0 = fmaxf(mx0, __shfl_xor_sync(0xffffffffu, mx0, 1));
        mx0 = fmaxf(mx0, __shfl_xor_sync(0xffffffffu, mx0, 2));
        mx1 = fmaxf(mx1, __shfl_xor_sync(0xffffffffu, mx1, 1));
        mx1 = fmaxf(mx1, __shfl_xor_sync(0xffffffffu, mx1, 2));
        float mn0 = fmaxf(m0_, mx0), mn1 = fmaxf(m1_, mx1);
        float a0 = exp2f(m0_ - mn0), a1 = exp2f(m1_ - mn1);
        m0_ = mn0; m1_ = mn1;
        float rs0 = 0.f, rs1 = 0.f;
        #pragma unroll
        for (int t = 0; t < 16; t++) {
            s[t][0] = exp2f(s[t][0] - mn0);
            s[t][1] = exp2f(s[t][1] - mn0);
            s[t][2] = exp2f(s[t][2] - mn1);
            s[t][3] = exp2f(s[t][3] - mn1);
            rs0 += s[t][0] + s[t][1];
            rs1 += s[t][2] + s[t][3];
        }
        l0_ = l0_ * a0 + rs0;
        l1_ = l1_ * a1 + rs1;
        #pragma unroll
        for (int dt = 0; dt < 8; dt++) {
            o[dt][0] *= a0; o[dt][1] *= a0; o[dt][2] *= a1; o[dt][3] *= a1;
        }
        #pragma unroll
        for (int kc = 0; kc < 8; kc++) {
            unsigned pah[4], pal[4];
            pack2(s[2*kc][0],   s[2*kc][1],   pah[0], pal[0]);
            pack2(s[2*kc][2],   s[2*kc][3],   pah[1], pal[1]);
            pack2(s[2*kc+1][0], s[2*kc+1][1], pah[2], pal[2]);
            pack2(s[2*kc+1][2], s[2*kc+1][3], pah[3], pal[3]);
            unsigned vbase = ((unsigned)(st*128 + kc*16 + vrow)*72 + vcol)*2;
            #pragma unroll
            for (int pp = 0; pp < 4; pp++) {
                unsigned off = vbase + pp * 32;
                unsigned bh[4], bl[4];
                LDSM_X4T(bh[0], bh[1], bh[2], bh[3], vh_a + off);
                LDSM_X4T(bl[0], bl[1], bl[2], bl[3], vl_a + off);
                MMA_OP(o[2*pp],   pah, bh);
                MMA_OP(o[2*pp],   pal, bh);
                MMA_OP(o[2*pp],   pah, bl);
                MMA_OP(o[2*pp+1], pah, bh + 2);
                MMA_OP(o[2*pp+1], pal, bh + 2);
                MMA_OP(o[2*pp+1], pah, bl + 2);
            }
        }
        __syncthreads();
    }

    l0_ += __shfl_xor_sync(0xffffffffu, l0_, 1);
    l0_ += __shfl_xor_sync(0xffffffffu, l0_, 2);
    l1_ += __shfl_xor_sync(0xffffffffu, l1_, 1);
    l1_ += __shfl_xor_sync(0xffffffffu, l1_, 2);
    float i0 = 1.f / l0_, i1 = 1.f / l1_;
    int row0 = qrow + lr, row1 = qrow + lr + 8;
    #pragma unroll
    for (int dt = 0; dt < 8; dt++) {
        int col = h*64 + dt*8 + lk;
        float v0 = o[dt][0]*i0, v1 = o[dt][1]*i0;
        float v2 = o[dt][2]*i1, v3 = o[dt][3]*i1;
        unsigned h01, l01, h23, l23;
        pack2(v0, v1, h01, l01);
        pack2(v2, v3, h23, l23);
        *(unsigned*)&ohp[(long long)row0*INNERD + col] = h01;
        *(unsigned*)&olp[(long long)row0*INNERD + col] = l01;
        *(unsigned*)&ohp[(long long)row1*INNERD + col] = h23;
        *(unsigned*)&olp[(long long)row1*INNERD + col] = l23;
    }
}

// ---------------- residual + layernorm ----------------
__global__ void k_addln(const float* __restrict__ x, const float* __restrict__ r,
                        const float* __restrict__ g, const float* __restrict__ bb,
                        float* __restrict__ out, bf* __restrict__ oh, bf* __restrict__ ol)
{
    int row = blockIdx.x;
    int tid = threadIdx.x;
    __shared__ float buf[DIMD];
    __shared__ float r1[256], r2[256];
    const float* xp = x + (size_t)row * DIMD;
    const float* rp = r + (size_t)row * DIMD;
    float s = 0.f, ss = 0.f;
    #pragma unroll
    for (int i = 0; i < 4; i++) {
        int j = tid + i * 256;
        float v = xp[j] + rp[j];
        buf[j] = v; s += v; ss += v * v;
    }
    r1[tid] = s; r2[tid] = ss; __syncthreads();
    for (int st = 128; st > 0; st >>= 1) {
        if (tid < st) { r1[tid] += r1[tid+st]; r2[tid] += r2[tid+st]; }
        __syncthreads();
    }
    float mean = r1[0] * (1.f / DIMD);
    float var  = r2[0] * (1.f / DIMD) - mean * mean;
    float inv  = rsqrtf(var + 1e-5f);
    #pragma unroll
    for (int i = 0; i < 4; i++) {
        int j = tid + i * 256;
        float v = (buf[j] - mean) * inv * g[j] + bb[j];
        out[(size_t)row * DIMD + j] = v;
        bf h = __float2bfloat16(v);
        oh[(size_t)row * DIMD + j] = h;
        ol[(size_t)row * DIMD + j] = __float2bfloat16(v - __bfloat162float(h));
    }
}

// ---------------- MoE router ----------------
__global__ void k_route(const float* __restrict__ xf, const float* __restrict__ gw,
                        float* __restrict__ probs_out)
{
    int tok = blockIdx.x;
    int tid = threadIdx.x;
    const float* xp = xf + (size_t)tok * DIMD;
    float part[NEXP] = {};
    for (int d = tid; d < DIMD; d += 256) {
        float xv = xp[d];
        #pragma unroll
        for (int e = 0; e < NEXP; e++) part[e] = fmaf(xv, gw[d*NEXP + e], part[e]);
    }
    __shared__ float sm[NEXP * 256];
    #pragma unroll
    for (int e = 0; e < NEXP; e++) sm[e*256 + tid] = part[e];
    __syncthreads();
    for (int s = 128; s > 0; s >>= 1) {
        if (tid < s) {
            #pragma unroll
            for (int e = 0; e < NEXP; e++) sm[e*256 + tid] += sm[e*256 + tid + s];
        }
        __syncthreads();
    }
    if (tid == 0) {
        float lg[NEXP], p[NEXP];
        float mx = NEGMIN;
        #pragma unroll
        for (int e = 0; e < NEXP; e++) { lg[e] = sm[e*256]; mx = fmaxf(mx, lg[e]); }
        float sum = 0.f;
        #pragma unroll
        for (int e = 0; e < NEXP; e++) { p[e] = expf(lg[e] - mx); sum += p[e]; }
        float inv = 1.f / sum;
        #pragma unroll
        for (int e = 0; e < NEXP; e++) { p[e] *= inv; probs_out[(size_t)tok*NEXP + e] = p[e]; }
        int i0 = 0;
        #pragma unroll
        for (int e = 1; e < NEXP; e++) if (p[e] > p[i0]) i0 = e;
        int i1 = (i0 == 0) ? 1 : 0;
        #pragma unroll
        for (int e = 0; e < NEXP; e++) if (e != i0 && p[e] > p[i1]) i1 = e;
        float w0 = p[i0], w1 = p[i1];
        float sw = 1.f / (w0 + w1);
        w0 *= sw; w1 *= sw;
        int pos = atomicAdd(&g_cnt[i0], 1);
        g_tok[i0*NTOK + pos] = tok; g_wslot[i0*NTOK + pos] = w0;
        g_inv[tok*2] = i0*NTOK + pos;
        pos = atomicAdd(&g_cnt[i1], 1);
        g_tok[i1*NTOK + pos] = tok; g_wslot[i1*NTOK + pos] = w1;
        g_inv[tok*2+1] = i1*NTOK + pos;
    }
}

// ---------------- final: 2 contribs + residual + LN3 ----------------
__global__ void k_moe_final(const float* __restrict__ x2, const float* __restrict__ g,
                            const float* __restrict__ bb, float* __restrict__ out)
{
    int tok = blockIdx.x;
    int tid = threadIdx.x;
    __shared__ float buf[DIMD];
    __shared__ float r1[256], r2[256];
    const float* xp = x2 + (size_t)tok * DIMD;
    int iv0 = g_inv[tok*2], iv1 = g_inv[tok*2+1];
    const float* c0 = g_contrib + (size_t)iv0 * DIMD;
    const float* c1 = g_contrib + (size_t)iv1 * DIMD;
    float s = 0.f, ss = 0.f;
    #pragma unroll
    for (int i = 0; i < 4; i++) {
        int j = tid + i * 256;
        float v = xp[j] + c0[j] + c1[j];
        buf[j] = v; s += v; ss += v * v;
    }
    r1[tid] = s; r2[tid] = ss; __syncthreads();
    for (int st = 128; st > 0; st >>= 1) {
        if (tid < st) { r1[tid] += r1[tid+st]; r2[tid] += r2[tid+st]; }
        __syncthreads();
    }
    float mean = r1[0] * (1.f / DIMD);
    float var  = r2[0] * (1.f / DIMD) - mean * mean;
    float inv  = rsqrtf(var + 1e-5f);
    float* op = out + (size_t)tok * DIMD;
    #pragma unroll
    for (int i = 0; i < 4; i++) {
        int j = tid + i * 256;
        op[j] = (buf[j] - mean) * inv * g[j] + bb[j];
    }
}

// ---------------- per-expert masked token sums (partitioned) ----------------
__global__ void k_tsum()
{
    int part = blockIdx.x % TSPART;
    int b = (blockIdx.x / TSPART) % NB;
    int e = blockIdx.x / (TSPART * NB);
    int tid = threadIdx.x;
    const int CH = SLEN / TSPART;
    __shared__ int sslot[SLEN / TSPART];
    for (int j = tid; j < CH; j += 256) {
        int t = b*SLEN + part*CH + j;
        int s = -1;
        if (!(g_mtgt[t] | g_mmid[t])) {
            int a = g_inv[2*t], c = g_inv[2*t+1];
            if ((a >> 11) == e) s = a;
            else if ((c >> 11) == e) s = c;
        }
        sslot[j] = s;
    }
    __syncthreads();
    for (int d = tid; d < DIMD; d += 256) {
        float acc = 0.f;
        for (int j = 0; j < CH; j++) {
            int s = sslot[j];
            if (s >= 0) acc += g_contrib[(size_t)s * DIMD + d];
        }
        g_tsumP[(((e*NB + b)*TSPART) + part)*DIMD + d] = acc;
    }
}

// ---------------- expert logits ----------------
__global__ void k_logits(const float* __restrict__ cls_w, const float* __restrict__ cls_b,
                         float* __restrict__ out_logits)
{
    int tid = threadIdx.x;
    __shared__ float red[256];
    __shared__ float dss[NEXP*NB];
    __shared__ float den[NB];
    for (int b = 0; b < NB; b++) {
        float c = 0.f;
        for (int j = tid; j < SLEN; j += 256)
            c += (!(g_mtgt[b*SLEN+j] | g_mmid[b*SLEN+j])) ? 1.f : 0.f;
        red[tid] = c; __syncthreads();
        for (int s = 128; s > 0; s >>= 1) { if (tid < s) red[tid] += red[tid+s]; __syncthreads(); }
        if (tid == 0) den[b] = fmaxf(red[0], 1.f);
        __syncthreads();
    }
    for (int eb = 0; eb < NEXP*NB; eb++) {
        float c = 0.f;
        for (int j = tid; j < DIMD; j += 256) {
            float t = 0.f;
            #pragma unroll
            for (int part = 0; part < TSPART; part++)
                t += g_tsumP[(eb*TSPART + part)*DIMD + j];
            c += t * cls_w[j];
        }
        red[tid] = c; __syncthreads();
        for (int s = 128; s > 0; s >>= 1) { if (tid < s) red[tid] += red[tid+s]; __syncthreads(); }
        if (tid == 0) dss[eb] = red[0];
        __syncthreads();
    }
    if (tid == 0) {
        for (int b = 0; b < NB; b++) {
            float pre = 0.f;
            for (int e = 0; e < NEXP; e++) {
                pre += dss[e*NB + b];
                out_logits[e*NB + b] = pre / den[b] + cls_b[0];
            }
        }
    }
}

// ---------------- host ----------------
struct GArg {
    const bf *Ah, *Al, *Bh, *Bl;
    float* C; bf *Ch, *Cl;
    int M, N, K, lda, ldb, ldc;
    long long sA1, sA2, sB1, sB2, sC1, sC2;
    int gz, bdiv, zmaps, swig;
    const float* bias; const int* rmA; const int* rmC;
    const float* rs; const int* cnt;
};

static void BG(const GArg& a)
{
    dim3 grid(a.N / 128, (a.M + 127) / 128, a.gz);
    k_bgemm<<<grid, 256, BG_SMEM>>>(
        a.Ah, a.Al, a.Bh, a.Bl, a.C, a.Ch, a.Cl, a.M, a.N, a.K, a.lda, a.ldb, a.ldc,
        a.sA1, a.sA2, a.sB1, a.sB2, a.sC1, a.sC2, a.bdiv, a.zmaps, a.swig,
        a.bias, a.rmA, a.rmC, a.rs, a.cnt);
}

extern "C" void kernel_launch(void* const* d_in, const int* in_sizes, int n_in,
                              void* d_out, int out_size)
{
    const float* x       = (const float*)d_in[0];
    const float* enc     = (const float*)d_in[1];
    const void*  src_mask_raw = d_in[2];
    const void*  tgt_mask_raw = d_in[3];
    const void*  tgt_mid_raw  = d_in[4];
    const float* ln1_g = (const float*)d_in[5];
    const float* ln1_b = (const float*)d_in[6];
    const float* ln2_g = (const float*)d_in[7];
    const float* ln2_b = (const float*)d_in[8];
    const float* ln3_g = (const float*)d_in[9];
    const float* ln3_b = (const float*)d_in[10];
    const float* sa_wq = (const float*)d_in[11];
    const float* sa_wk = (const float*)d_in[12];
    const float* sa_wv = (const float*)d_in[13];
    const float* sa_wo = (const float*)d_in[14];
    const float* sa_bo = (const float*)d_in[15];
    const float* ca_wq = (const float*)d_in[16];
    const float* ca_wk = (const float*)d_in[17];
    const float* ca_wv = (const float*)d_in[18];
    const float* ca_wo = (const float*)d_in[19];
    const float* ca_bo = (const float*)d_in[20];
    const float* gate_w = (const float*)d_in[21];
    const float* cls_w  = (const float*)d_in[22];
    const float* cls_b  = (const float*)d_in[23];
    const float* moe_w1 = (const float*)d_in[24];
    const float* moe_w2 = (const float*)d_in[25];
    const float* moe_w3 = (const float*)d_in[26];

    float* out = (float*)d_out;
    float* out_x      = out;
    float* out_logits = out + (size_t)NTOK * DIMD;
    float* out_probs  = out_logits + NEXP * NB;

    cudaFuncSetAttribute(k_bgemm, cudaFuncAttributeMaxDynamicSharedMemorySize, BG_SMEM);
    cudaFuncSetAttribute(k_fattn, cudaFuncAttributeMaxDynamicSharedMemorySize, FATTN_SMEM);

    // side stream + events (created once, on the uncaptured correctness call)
    static cudaStream_t s2 = nullptr;
    static cudaEvent_t evFork = nullptr, evCA = nullptr, evMOE = nullptr;
    if (!s2) {
        cudaStreamCreateWithFlags(&s2, cudaStreamNonBlocking);
        cudaEventCreateWithFlags(&evFork, cudaEventDisableTiming);
        cudaEventCreateWithFlags(&evCA,   cudaEventDisableTiming);
        cudaEventCreateWithFlags(&evMOE,  cudaEventDisableTiming);
    }

    float *pproj, *px1, *px2, *pcontrib, *pwslot;
    int *ptok, *pcnt;
    unsigned char *pmsrc, *pmtgt;
    bf *pxh,*pxl,*pawh,*pawl,*pw13h,*pw13l,*pw2h,*pw2l;
    bf *pqkvh,*pqkvl,*path,*patl,*px1h,*px1l,*px2h,*px2l,*pgh,*pgl;
    cudaGetSymbolAddress((void**)&pproj, g_proj);
    cudaGetSymbolAddress((void**)&px1, g_x1);
    cudaGetSymbolAddress((void**)&px2, g_x2);
    cudaGetSymbolAddress((void**)&pcontrib, g_contrib);
    cudaGetSymbolAddress((void**)&pwslot, g_wslot);
    cudaGetSymbolAddress((void**)&ptok, g_tok);
    cudaGetSymbolAddress((void**)&pcnt, g_cnt);
    cudaGetSymbolAddress((void**)&pmsrc, g_msrc);
    cudaGetSymbolAddress((void**)&pmtgt, g_mtgt);
    cudaGetSymbolAddress((void**)&pxh, g_xh);   cudaGetSymbolAddress((void**)&pxl, g_xl);
    cudaGetSymbolAddress((void**)&pawh, g_awh); cudaGetSymbolAddress((void**)&pawl, g_awl);
    cudaGetSymbolAddress((void**)&pw13h, g_w13h); cudaGetSymbolAddress((void**)&pw13l, g_w13l);
    cudaGetSymbolAddress((void**)&pw2h, g_w2h); cudaGetSymbolAddress((void**)&pw2l, g_w2l);
    cudaGetSymbolAddress((void**)&pqkvh, g_qkvh); cudaGetSymbolAddress((void**)&pqkvl, g_qkvl);
    cudaGetSymbolAddress((void**)&path, g_ath); cudaGetSymbolAddress((void**)&patl, g_atl);
    cudaGetSymbolAddress((void**)&px1h, g_x1h); cudaGetSymbolAddress((void**)&px1l, g_x1l);
    cudaGetSymbolAddress((void**)&px2h, g_x2h); cudaGetSymbolAddress((void**)&px2l, g_x2l);
    cudaGetSymbolAddress((void**)&pgh, g_gh);   cudaGetSymbolAddress((void**)&pgl, g_gl);

    bf* peh = px1h + (size_t)NTOK * DIMD;
    bf* pel = px1l + (size_t)NTOK * DIMD;

    const long long WMOE = (long long)DIMD * HIDD;
    const long long MM   = (long long)DIMD * INNERD;
    const long long W13  = 2LL * HIDD * DIMD;

    k_detect<<<1, 256>>>((const unsigned char*)tgt_mask_raw);
    // fork side stream
    cudaEventRecord(evFork, 0);
    cudaStreamWaitEvent(s2, evFork, 0);

    k_cvtmask<<<8, 256>>>(src_mask_raw, tgt_mask_raw, tgt_mid_raw);
    k_cvtA<<<512, 256>>>(x,   pxh, pxl, NTOK*DIMD/4);
    k_cvtA<<<512, 256>>>(enc, peh, pel, NTOK*DIMD/4);
    const float* aw[8] = {sa_wq, sa_wk, sa_wv, sa_wo, ca_wq, ca_wk, ca_wv, ca_wo};
    // self-attn weights on main stream (needed first)
    for (int i = 0; i < 4; i++)
        k_cvtT<<<dim3(INNERD/64, DIMD/64, 1), dim3(16,16)>>>(aw[i], pawh + i*MM, pawl + i*MM, DIMD, INNERD, 0, 0, 1, 0);
    // cross-attn weights + MoE weights on side stream (overlap with self-attn compute)
    for (int i = 4; i < 8; i++)
        k_cvtT<<<dim3(INNERD/64, DIMD/64, 1), dim3(16,16), 0, s2>>>(aw[i], pawh + i*MM, pawl + i*MM, DIMD, INNERD, 0, 0, 1, 0);
    cudaEventRecord(evCA, s2);
    k_cvtT<<<dim3(HIDD/64, DIMD/64, NEXP), dim3(16,16), 0, s2>>>(moe_w1, pw13h, pw13l, DIMD, HIDD, WMOE, W13, 2, 0);
    k_cvtT<<<dim3(HIDD/64, DIMD/64, NEXP), dim3(16,16), 0, s2>>>(moe_w3, pw13h, pw13l, DIMD, HIDD, WMOE, W13, 2, 1);
    k_cvtT<<<dim3(DIMD/64, HIDD/64, NEXP), dim3(16,16), 0, s2>>>(moe_w2, pw2h, pw2l, HIDD, DIMD, WMOE, WMOE, 1, 0);
    cudaEventRecord(evMOE, s2);

    GArg a{};

    for (int lam = 0; lam < 2; lam++) {
        int wb = lam * 4;
        const float* bo = lam ? ca_bo : sa_bo;
        unsigned char* msk = lam ? pmsrc : pmtgt;

        if (lam == 0) {
            // self: Q|K|V in one N=3072 launch
            a = GArg{}; a.gz = 1; a.bdiv = 1;
            a.Ah = pxh; a.Al = pxl; a.Bh = pawh; a.Bl = pawl;
            a.Ch = pqkvh; a.Cl = pqkvl;
            a.M = NTOK; a.N = QKVW; a.K = DIMD; a.lda = DIMD; a.ldb = DIMD; a.ldc = QKVW;
            BG(a);
        } else {
            // join: cross weights must be converted
            cudaStreamWaitEvent(0, evCA, 0);
            a = GArg{}; a.gz = 3; a.bdiv = 2;
            a.Ah = px1h; a.Al = px1l;
            a.Bh = pawh + 4*MM; a.Bl = pawl + 4*MM;
            a.Ch = pqkvh; a.Cl = pqkvl;
            a.M = NTOK; a.N = INNERD; a.K = DIMD; a.lda = DIMD; a.ldb = DIMD; a.ldc = QKVW;
            a.sA1 = (long long)NTOK * DIMD;  a.sA2 = (long long)NTOK * DIMD;
            a.sB1 = MM;  a.sB2 = 2*MM;
            a.sC1 = INNERD; a.sC2 = 2*INNERD;
            BG(a);
        }
        k_fattn<<<dim3(SLEN/128, HEADS, NB), 256, FATTN_SMEM>>>(
            pqkvh, pqkvl, path, patl, msk);
        a = GArg{}; a.gz = 1; a.bdiv = 1;
        a.Ah = path; a.Al = patl; a.Bh = pawh + (wb+3)*MM; a.Bl = pawl + (wb+3)*MM;
        a.C = pproj; a.bias = bo;
        a.M = NTOK; a.N = DIMD; a.K = INNERD; a.lda = INNERD; a.ldb = INNERD; a.ldc = DIMD;
        BG(a);
        if (lam == 0)
            k_addln<<<NTOK, 256>>>(x, pproj, ln1_g, ln1_b, px1, px1h, px1l);
        else
            k_addln<<<NTOK, 256>>>(px1, pproj, ln2_g, ln2_b, px2, px2h, px2l);
    }

    k_route<<<NTOK, 256>>>(px2, gate_w, out_probs);
    // join: MoE weights must be converted
    cudaStreamWaitEvent(0, evMOE, 0);
    a = GArg{}; a.gz = NEXP; a.bdiv = NEXP; a.zmaps = 1; a.swig = 1;
    a.Ah = px2h; a.Al = px2l; a.Bh = pw13h; a.Bl = pw13l;
    a.Ch = pgh; a.Cl = pgl;
    a.M = NTOK; a.N = 2*HIDD; a.K = DIMD; a.lda = DIMD; a.ldb = DIMD; a.ldc = HIDD;
    a.sB1 = W13; a.sC1 = (long long)NTOK*HIDD;
    a.rmA = ptok; a.cnt = pcnt;
    BG(a);
    a = GArg{}; a.gz = NEXP; a.bdiv = NEXP; a.zmaps = 1;
    a.Ah = pgh; a.Al = pgl; a.Bh = pw2h; a.Bl = pw2l; a.C = pcontrib;
    a.M = NTOK; a.N = DIMD; a.K = HIDD; a.lda = HIDD; a.ldb = HIDD; a.ldc = DIMD;
    a.sA1 = (long long)NTOK*HIDD; a.sB1 = WMOE; a.sC1 = (long long)NTOK*DIMD;
    a.rs = pwslot; a.cnt = pcnt;
    BG(a);

    k_moe_final<<<NTOK, 256>>>(px2, ln3_g, ln3_b, out_x);
    k_tsum<<<NEXP*NB*TSPART, 256>>>();
    k_logits<<<1, 256>>>(cls_w, cls_b, out_logits);
}

// round 15
// speedup vs baseline: 1.0815x; 1.0284x over previous
#include <cuda_runtime.h>
#include <cuda_bf16.h>
#include <math.h>

#define DIMD   1024
#define HEADS  16
#define DHEAD  64
#define HIDD   2048
#define NEXP   8
#define NB     2
#define SLEN   1024
#define NTOK   (NB*SLEN)
#define INNERD (HEADS*DHEAD)
#define QKVW   (3*INNERD)
#define NEGMIN (-3.402823466e38f)
#define SCL2   0.18033688011112042f   // 0.125 * log2(e)
#define TSPART 8

typedef __nv_bfloat16 bf;

// ---------------- device scratch ----------------
__device__ float g_proj[NTOK*DIMD];
__device__ float g_x1[NTOK*DIMD];
__device__ float g_x2[NTOK*DIMD];
__device__ float g_contrib[(size_t)NEXP*NTOK*DIMD];
__device__ float g_wslot[NEXP*NTOK];
__device__ int   g_tok[NEXP*NTOK];
__device__ int   g_inv[NTOK*2];
__device__ int   g_cnt[NEXP];
__device__ float g_tsumP[NEXP*NB*TSPART*DIMD];
__device__ bf g_xh[NTOK*DIMD],  g_xl[NTOK*DIMD];
__device__ bf g_x1h[2*NTOK*DIMD], g_x1l[2*NTOK*DIMD];   // x1 | enc planes
__device__ bf g_awh[8*DIMD*INNERD], g_awl[8*DIMD*INNERD];
__device__ bf g_w13h[(size_t)NEXP*2*HIDD*DIMD], g_w13l[(size_t)NEXP*2*HIDD*DIMD];
__device__ bf g_w2h[(size_t)NEXP*HIDD*DIMD], g_w2l[(size_t)NEXP*HIDD*DIMD];
__device__ bf g_qkvh[(size_t)NTOK*QKVW], g_qkvl[(size_t)NTOK*QKVW];  // [tok][q|k|v]
__device__ bf g_ath[NTOK*INNERD], g_atl[NTOK*INNERD];
__device__ bf g_x2h[NTOK*DIMD], g_x2l[NTOK*DIMD];
__device__ bf g_gh[(size_t)NEXP*NTOK*HIDD], g_gl[(size_t)NEXP*NTOK*HIDD];
__device__ unsigned char g_msrc[NTOK];
__device__ unsigned char g_mtgt[NTOK];
__device__ unsigned char g_mmid[NTOK];
__device__ int g_mtype;

// ---------------- PTX helpers ----------------
__device__ __forceinline__ unsigned smem_u32(const void* p) {
    return (unsigned)__cvta_generic_to_shared(p);
}
__device__ __forceinline__ void cp16(unsigned d, const void* s, bool v) {
    if (v) asm volatile("cp.async.ca.shared.global [%0], [%1], 16;\n" :: "r"(d), "l"(s) : "memory");
    else   asm volatile("cp.async.ca.shared.global [%0], [%1], 16, 0;\n" :: "r"(d), "l"(s) : "memory");
}
#define CP_COMMIT asm volatile("cp.async.commit_group;\n" ::: "memory")
#define CP_WAIT0  asm volatile("cp.async.wait_group 0;\n" ::: "memory")
#define CP_WAIT1  asm volatile("cp.async.wait_group 1;\n" ::: "memory")

#define LDSM_X4(d0, d1, d2, d3, a) \
    asm volatile("ldmatrix.sync.aligned.m8n8.x4.shared.b16 {%0,%1,%2,%3}, [%4];" \
                 : "=r"(d0), "=r"(d1), "=r"(d2), "=r"(d3) : "r"(a))

#define LDSM_X4T(d0, d1, d2, d3, a) \
    asm volatile("ldmatrix.sync.aligned.m8n8.x4.trans.shared.b16 {%0,%1,%2,%3}, [%4];" \
                 : "=r"(d0), "=r"(d1), "=r"(d2), "=r"(d3) : "r"(a))

#define MMA_OP(c, a, b) \
    asm volatile("mma.sync.aligned.m16n8k16.row.col.f32.bf16.bf16.f32 " \
                 "{%0,%1,%2,%3},{%4,%5,%6,%7},{%8,%9},{%0,%1,%2,%3};" \
                 : "+f"((c)[0]), "+f"((c)[1]), "+f"((c)[2]), "+f"((c)[3]) \
                 : "r"((a)[0]), "r"((a)[1]), "r"((a)[2]), "r"((a)[3]), \
                   "r"((b)[0]), "r"((b)[1]))

__device__ __forceinline__ void pack2(float x, float y, unsigned& hi, unsigned& lo) {
    bf hx = __float2bfloat16(x), hy = __float2bfloat16(y);
    __nv_bfloat162 th; th.x = hx; th.y = hy;
    hi = *(unsigned*)&th;
    __nv_bfloat162 tl;
    tl.x = __float2bfloat16(x - __bfloat162float(hx));
    tl.y = __float2bfloat16(y - __bfloat162float(hy));
    lo = *(unsigned*)&tl;
}

// ---------------- mask detection / conversion ----------------
__global__ void k_detect(const unsigned char* __restrict__ tgt) {
    __shared__ int has_gt1, has_off;
    if (threadIdx.x == 0) { has_gt1 = 0; has_off = 0; }
    if (threadIdx.x < NEXP) g_cnt[threadIdx.x] = 0;
    __syncthreads();
    for (int j = threadIdx.x; j < NTOK; j += blockDim.x) {
        unsigned char v = tgt[j];
        if (v > 1) atomicOr(&has_gt1, 1);
        else if (v && (j & 3)) atomicOr(&has_off, 1);
    }
    __syncthreads();
    if (threadIdx.x == 0)
        g_mtype = has_gt1 ? 2 : (has_off ? 0 : 1);
}

__global__ void k_cvtmask(const void* __restrict__ s0, const void* __restrict__ s1,
                          const void* __restrict__ s2) {
    int t = g_mtype;
    int stride = gridDim.x * blockDim.x;
    for (int j = blockIdx.x * blockDim.x + threadIdx.x; j < NTOK; j += stride) {
        unsigned char a, b, c;
        if (t == 1) {
            a = ((const int*)s0)[j] != 0;
            b = ((const int*)s1)[j] != 0;
            c = ((const int*)s2)[j] != 0;
        } else if (t == 2) {
            a = ((const float*)s0)[j] != 0.f;
            b = ((const float*)s1)[j] != 0.f;
            c = ((const float*)s2)[j] != 0.f;
        } else {
            a = ((const unsigned char*)s0)[j];
            b = ((const unsigned char*)s1)[j];
            c = ((const unsigned char*)s2)[j];
        }
        g_msrc[j] = a; g_mtgt[j] = b; g_mmid[j] = c;
    }
}

// ---------------- conversion kernels ----------------
__global__ void k_cvtA(const float* __restrict__ s, bf* __restrict__ dh, bf* __restrict__ dl, int n4)
{
    int stride = gridDim.x * blockDim.x;
    for (int i = blockIdx.x * blockDim.x + threadIdx.x; i < n4; i += stride) {
        float4 v = ((const float4*)s)[i];
        float vv[4] = {v.x, v.y, v.z, v.w};
        bf h[4], l[4];
        #pragma unroll
        for (int j = 0; j < 4; j++) {
            h[j] = __float2bfloat16(vv[j]);
            l[j] = __float2bfloat16(vv[j] - __bfloat162float(h[j]));
        }
        ((ushort4*)dh)[i] = *(ushort4*)h;
        ((ushort4*)dl)[i] = *(ushort4*)l;
    }
}

// transpose-convert, 64x64 tile, vectorized: src fp32 [Kd][Nd] -> planes [Nd][Kd]
__global__ void k_cvtT(const float* __restrict__ src, bf* __restrict__ dh, bf* __restrict__ dl,
                       int Kd, int Nd, long long sSrc, long long sDst, int rowMul, int rowAdd)
{
    int z = blockIdx.z;
    src += (long long)z * sSrc; dh += (long long)z * sDst; dl += (long long)z * sDst;
    __shared__ float t[64][65];
    int k0 = blockIdx.y * 64, n0 = blockIdx.x * 64;
    int tx = threadIdx.x;   // 16
    int ty = threadIdx.y;   // 16
    #pragma unroll
    for (int i = 0; i < 4; i++) {
        int kk = k0 + ty + i * 16;
        float4 v = *(const float4*)&src[(long long)kk * Nd + n0 + tx * 4];
        t[ty + i * 16][tx * 4 + 0] = v.x;
        t[ty + i * 16][tx * 4 + 1] = v.y;
        t[ty + i * 16][tx * 4 + 2] = v.z;
        t[ty + i * 16][tx * 4 + 3] = v.w;
    }
    __syncthreads();
    #pragma unroll
    for (int j = 0; j < 4; j++) {
        int nn = n0 + ty + j * 16;
        bf h[4], l[4];
        #pragma unroll
        for (int c = 0; c < 4; c++) {
            float v = t[tx * 4 + c][ty + j * 16];
            h[c] = __float2bfloat16(v);
            l[c] = __float2bfloat16(v - __bfloat162float(h[c]));
        }
        long long dr = (long long)nn * rowMul + rowAdd;
        *(ushort4*)&dh[dr * Kd + k0 + tx * 4] = *(ushort4*)h;
        *(ushort4*)&dl[dr * Kd + k0 + tx * 4] = *(ushort4*)l;
    }
}

// ---------------- bf16-plane tensor-core GEMM (ldmatrix + 3-stage pipeline) ----------------
#define LDS_ 40
#define NSTG 3
#define OFFA(st, pl) (((st)*2 + (pl)) * 128 * LDS_ * 2)
#define OFFB(st, pl) (NSTG*2*128*LDS_*2 + ((st)*2 + (pl)) * 128 * LDS_ * 2)
#define BG_SROW (2 * NSTG*2*128*LDS_*2)
#define BG_SMEM (BG_SROW + 512 + 64)

__global__ void __launch_bounds__(256) k_bgemm(
    const bf* __restrict__ Ah, const bf* __restrict__ Al,
    const bf* __restrict__ Bh, const bf* __restrict__ Bl,
    float* __restrict__ C, bf* __restrict__ Ch, bf* __restrict__ Cl,
    int M, int N, int K, int lda, int ldb, int ldc,
    long long sA1, long long sA2, long long sB1, long long sB2,
    long long sC1, long long sC2, int bdiv, int zmaps, int swiglu,
    const float* __restrict__ bias,
    const int* __restrict__ rowmapA, const int* __restrict__ rowmapC,
    const float* __restrict__ rowscale, const int* __restrict__ cntPtr)
{
    int z = blockIdx.z;
    long long ao = (long long)(z / bdiv) * sA2 + (long long)(z % bdiv) * sA1;
    long long bo = (long long)(z / bdiv) * sB2 + (long long)(z % bdiv) * sB1;
    long long co = (long long)(z / bdiv) * sC2 + (long long)(z % bdiv) * sC1;
    const bf* Ahp = Ah + ao; const bf* Alp = Al + ao;
    const bf* Bhp = Bh + bo; const bf* Blp = Bl + bo;
    float* Cp = C ? C + co : nullptr;
    bf* Chp = Ch ? Ch + co : nullptr;
    bf* Clp = Cl ? Cl + co : nullptr;
    if (zmaps) {
        if (rowmapA) rowmapA += z * NTOK;
        if (rowmapC) rowmapC += z * NTOK;
        if (rowscale) rowscale += z * NTOK;
        if (cntPtr) cntPtr += z;
    }
    int Meff = M;
    if (cntPtr) { int c = *cntPtr; Meff = c < M ? c : M; }
    int m0 = blockIdx.y * 128;
    if (m0 >= Meff) return;
    int n0 = blockIdx.x * 128;

    extern __shared__ __align__(16) char dyn[];
    unsigned sb = smem_u32(dyn);
    int* sRow = (int*)(dyn + BG_SROW);

    int tid = threadIdx.x, lane = tid & 31, warp = tid >> 5;
    int warp_n = warp & 3, warp_m = warp >> 2;
    int lr = lane >> 2, lk = (lane & 3) * 2;
    int quad = lane >> 3, rin = lane & 7;

    for (int r = tid; r < 128; r += 256) {
        int gm = m0 + r;
        sRow[r] = (gm < Meff) ? (rowmapA ? rowmapA[gm] : gm) : 0;
    }
    __syncthreads();

    int a_r = rin + ((quad & 1) ? 8 : 0);
    int a_c = (quad & 2) ? 8 : 0;
    int b_r = rin + ((quad >> 1) ? 8 : 0);
    int b_c = (quad & 1) ? 8 : 0;
    int aoff[4], boff[2];
    #pragma unroll
    for (int tm = 0; tm < 4; tm++)
        aoff[tm] = ((warp_m * 64 + tm * 16 + a_r) * LDS_ + a_c) * 2;
    #pragma unroll
    for (int p = 0; p < 2; p++)
        boff[p] = ((warp_n * 32 + p * 16 + b_r) * LDS_ + b_c) * 2;

    auto loadStage = [&](int st, int k0) {
        #pragma unroll
        for (int i = 0; i < 2; i++) {
            int c = tid + i * 256;
            int row = c >> 2, q = c & 3;
            bool v = (m0 + row) < Meff;
            long long so = (long long)sRow[row] * lda + k0 + q * 8;
            unsigned ds = (row * LDS_ + q * 8) * 2;
            cp16(sb + OFFA(st, 0) + ds, Ahp + so, v);
            cp16(sb + OFFA(st, 1) + ds, Alp + so, v);
        }
        #pragma unroll
        for (int i = 0; i < 2; i++) {
            int c = tid + i * 256;
            int row = c >> 2, q = c & 3;
            long long so = (long long)(n0 + row) * ldb + k0 + q * 8;
            unsigned ds = (row * LDS_ + q * 8) * 2;
            cp16(sb + OFFB(st, 0) + ds, Bhp + so, true);
            cp16(sb + OFFB(st, 1) + ds, Blp + so, true);
        }
    };

    float acc[4][4][4];
    #pragma unroll
    for (int i = 0; i < 4; i++)
        #pragma unroll
        for (int j = 0; j < 4; j++)
            #pragma unroll
            for (int q = 0; q < 4; q++) acc[i][j][q] = 0.f;

    int KT = K >> 5;
    loadStage(0, 0); CP_COMMIT;
    loadStage(1, 32); CP_COMMIT;

    for (int kt = 0; kt < KT; kt++) {
        int s = kt % NSTG;
        if (kt + 1 < KT) { CP_WAIT1; } else { CP_WAIT0; }
        __syncthreads();
        if (kt + 2 < KT) { loadStage((kt + 2) % NSTG, (kt + 2) * 32); CP_COMMIT; }

        unsigned bAh = sb + OFFA(s, 0), bAl = sb + OFFA(s, 1);
        unsigned bBh = sb + OFFB(s, 0), bBl = sb + OFFB(s, 1);
        #pragma unroll
        for (int kc = 0; kc < 2; kc++) {
            unsigned afh[4][4], afl[4][4], bfh[4][2], bfl[4][2];
            #pragma unroll
            for (int tm = 0; tm < 4; tm++) {
                LDSM_X4(afh[tm][0], afh[tm][1], afh[tm][2], afh[tm][3], bAh + aoff[tm] + kc * 32);
                LDSM_X4(afl[tm][0], afl[tm][1], afl[tm][2], afl[tm][3], bAl + aoff[tm] + kc * 32);
            }
            #pragma unroll
            for (int p = 0; p < 2; p++) {
                LDSM_X4(bfh[2*p][0], bfh[2*p][1], bfh[2*p+1][0], bfh[2*p+1][1], bBh + boff[p] + kc * 32);
                LDSM_X4(bfl[2*p][0], bfl[2*p][1], bfl[2*p+1][0], bfl[2*p+1][1], bBl + boff[p] + kc * 32);
            }
            #pragma unroll
            for (int tm = 0; tm < 4; tm++)
                #pragma unroll
                for (int tn = 0; tn < 4; tn++) {
                    MMA_OP(acc[tm][tn], afh[tm], bfh[tn]);
                    MMA_OP(acc[tm][tn], afl[tm], bfh[tn]);
                    MMA_OP(acc[tm][tn], afh[tm], bfl[tn]);
                }
        }
    }

    #pragma unroll
    for (int tm = 0; tm < 4; tm++) {
        #pragma unroll
        for (int half = 0; half < 2; half++) {
            int gm = m0 + warp_m * 64 + tm * 16 + lr + half * 8;
            if (gm >= Meff) continue;
            float scale = rowscale ? rowscale[gm] : 1.f;
            long long crow = rowmapC ? (long long)rowmapC[gm] : (long long)gm;
            #pragma unroll
            for (int tn = 0; tn < 4; tn++) {
                int col = n0 + warp_n * 32 + tn * 8 + lk;
                float v0 = acc[tm][tn][half * 2 + 0];
                float v1 = acc[tm][tn][half * 2 + 1];
                if (swiglu) {
                    float g = v0 * v1 / (1.f + expf(-v0));
                    int j = col >> 1;
                    bf h = __float2bfloat16(g);
                    Chp[crow * ldc + j] = h;
                    Clp[crow * ldc + j] = __float2bfloat16(g - __bfloat162float(h));
                    continue;
                }
                v0 *= scale; v1 *= scale;
                if (bias) { v0 += bias[col]; v1 += bias[col + 1]; }
                if (Cp) *(float2*)&Cp[crow * ldc + col] = make_float2(v0, v1);
                if (Chp) {
                    unsigned hi, lo;
                    pack2(v0, v1, hi, lo);
                    *(unsigned*)&Chp[crow * ldc + col] = hi;
                    *(unsigned*)&Clp[crow * ldc + col] = lo;
                }
            }
        }
    }
}

// ---------------- fused flash attention (qkv buffer, V via ldmatrix.trans) ----------------
#define FATTN_SMEM (4*(2*128*72*2) + 1024)
__global__ void __launch_bounds__(256) k_fattn(
    const bf* __restrict__ qkvh, const bf* __restrict__ qkvl,
    bf* __restrict__ ohp, bf* __restrict__ olp,
    const unsigned char* __restrict__ mask)
{
    int m0 = blockIdx.x * 128;
    int h  = blockIdx.y;
    int b  = blockIdx.z;
    int tid = threadIdx.x, lane = tid & 31, warp = tid >> 5;
    int lr = lane >> 2, lk = (lane & 3) * 2;
    int quad = lane >> 3, rin = lane & 7;
    int b_r = rin + ((quad >> 1) ? 8 : 0);
    int b_c = (quad & 1) ? 8 : 0;
    int vrow = rin + 8 * ((lane >> 3) & 1);
    int vcol = 8 * (lane >> 4);

    extern __shared__ __align__(16) char smem[];
    bf* sKh = (bf*)smem;
    bf* sKl = sKh + 2*128*72;
    bf* sVh = sKl + 2*128*72;
    bf* sVl = sVh + 2*128*72;
    unsigned char* smask = (unsigned char*)(sVl + 2*128*72);
    unsigned kh_a = smem_u32(sKh);
    unsigned kl_a = smem_u32(sKl);
    unsigned vh_a = smem_u32(sVh);
    unsigned vl_a = smem_u32(sVl);

    for (int j = tid; j < SLEN; j += 256) smask[j] = mask[b*SLEN + j];

    int qrow = b*SLEN + m0 + warp*16;
    unsigned qfh[4][4], qfl[4][4];
    #pragma unroll
    for (int kc = 0; kc < 4; kc++) {
        long long b0 = (long long)(qrow + lr) * QKVW + h*64 + kc*16 + lk;
        long long b1 = b0 + 8LL*QKVW;
        qfh[kc][0] = *(const unsigned*)&qkvh[b0];
        qfh[kc][1] = *(const unsigned*)&qkvh[b1];
        qfh[kc][2] = *(const unsigned*)&qkvh[b0 + 8];
        qfh[kc][3] = *(const unsigned*)&qkvh[b1 + 8];
        qfl[kc][0] = *(const unsigned*)&qkvl[b0];
        qfl[kc][1] = *(const unsigned*)&qkvl[b1];
        qfl[kc][2] = *(const unsigned*)&qkvl[b0 + 8];
        qfl[kc][3] = *(const unsigned*)&qkvl[b1 + 8];
    }

    auto loadChunk = [&](int st, int c) {
        int t0 = c * 128;
        #pragma unroll
        for (int i = 0; i < 4; i++) {
            int idx = tid + i*256;
            int r = idx >> 3, q = idx & 7;
            long long srcK = (long long)(b*SLEN + t0 + r) * QKVW + INNERD + h*64 + q*8;
            long long srcV = srcK + INNERD;
            unsigned ds = ((st*128 + r)*72 + q*8)*2;
            cp16(kh_a + ds, qkvh + srcK, true);
            cp16(kl_a + ds, qkvl + srcK, true);
            cp16(vh_a + ds, qkvh + srcV, true);
            cp16(vl_a + ds, qkvl + srcV, true);
        }
    };

    float m0_ = -1e30f, m1_ = -1e30f, l0_ = 0.f, l1_ = 0.f;
    float o[8][4];
    #pragma unroll
    for (int i = 0; i < 8; i++) { o[i][0]=0.f; o[i][1]=0.f; o[i][2]=0.f; o[i][3]=0.f; }

    loadChunk(0, 0); CP_COMMIT;

    for (int c = 0; c < 8; c++) {
        int st = c & 1;
        CP_WAIT0; __syncthreads();
        if (c + 1 < 8) { loadChunk(st ^ 1, c + 1); CP_COMMIT; }

        float s[16][4];
        #pragma unroll
        for (int t = 0; t < 16; t++) { s[t][0]=0.f; s[t][1]=0.f; s[t][2]=0.f; s[t][3]=0.f; }
        #pragma unroll
        for (int kc = 0; kc < 4; kc++) {
            #pragma unroll
            for (int p = 0; p < 8; p++) {
                unsigned off = ((unsigned)(st*128 + p*16 + b_r)*72 + kc*16 + b_c)*2;
                unsigned bh[4], bl[4];
                LDSM_X4(bh[0], bh[1], bh[2], bh[3], kh_a + off);
                LDSM_X4(bl[0], bl[1], bl[2], bl[3], kl_a + off);
                MMA_OP(s[2*p],   qfh[kc], bh);
                MMA_OP(s[2*p],   qfl[kc], bh);
                MMA_OP(s[2*p],   qfh[kc], bl);
                MMA_OP(s[2*p+1], qfh[kc], bh + 2);
                MMA_OP(s[2*p+1], qfl[kc], bh + 2);
                MMA_OP(s[2*p+1], qfh[kc], bl + 2);
            }
        }
        #pragma unroll
        for (int t = 0; t < 16; t++) {
            int col = c*128 + t*8 + lk;
            bool k0m = smask[col] != 0;
            bool k1m = smask[col + 1] != 0;
            s[t][0] = k0m ? -1e30f : s[t][0] * SCL2;
            s[t][1] = k1m ? -1e30f : s[t][1] * SCL2;
            s[t][2] = k0m ? -1e30f : s[t][2] * SCL2;
            s[t][3] = k1m ? -1e30f : s[t][3] * SCL2;
        }
        float mx0 = -1e30f, mx1 = -1e30f;
        #pragma unroll
        for (int t = 0; t < 16; t++) {
            mx0 = fmaxf(mx0, fmaxf(s[t][0], s[t][1]));
            mx1 = fmaxf(mx1, fmaxf(s[t][2], s[t][3]));
        }
        mx0 = fmaxf(mx0, __shfl_xor_sync(0xffffffffu, mx0, 1));
        mx0 = fmaxf(mx0, __shfl_xor_sync(0xffffffffu, mx0, 2));
        mx1 = fmaxf(mx1, __shfl_xor_sync(0xffffffffu, mx1, 1));
        mx1 = fmaxf(mx1, __shfl_xor_sync(0xffffffffu, mx1, 2));
        float mn0 = fmaxf(m0_, mx0), mn1 = fmaxf(m1_, mx1);
        float a0 = exp2f(m0_ - mn0), a1 = exp2f(m1_ - mn1);
        m0_ = mn0; m1_ = mn1;
        float rs0 = 0.f, rs1 = 0.f;
        #pragma unroll
        for (int t = 0; t < 16; t++) {
            s[t][0] = exp2f(s[t][0] - mn0);
            s[t][1] = exp2f(s[t][1] - mn0);
            s[t][2] = exp2f(s[t][2] - mn1);
            s[t][3] = exp2f(s[t][3] - mn1);
            rs0 += s[t][0] + s[t][1];
            rs1 += s[t][2] + s[t][3];
        }
        l0_ = l0_ * a0 + rs0;
        l1_ = l1_ * a1 + rs1;
        #pragma unroll
        for (int dt = 0; dt < 8; dt++) {
            o[dt][0] *= a0; o[dt][1] *= a0; o[dt][2] *= a1; o[dt][3] *= a1;
        }
        #pragma unroll
        for (int kc = 0; kc < 8; kc++) {
            unsigned pah[4], pal[4];
            pack2(s[2*kc][0],   s[2*kc][1],   pah[0], pal[0]);
            pack2(s[2*kc][2],   s[2*kc][3],   pah[1], pal[1]);
            pack2(s[2*kc+1][0], s[2*kc+1][1], pah[2], pal[2]);
            pack2(s[2*kc+1][2], s[2*kc+1][3], pah[3], pal[3]);
            unsigned vbase = ((unsigned)(st*128 + kc*16 + vrow)*72 + vcol)*2;
            #pragma unroll
            for (int pp = 0; pp < 4; pp++) {
                unsigned off = vbase + pp * 32;
                unsigned bh[4], bl[4];
                LDSM_X4T(bh[0], bh[1], bh[2], bh[3], vh_a + off);
                LDSM_X4T(bl[0], bl[1], bl[2], bl[3], vl_a + off);
                MMA_OP(o[2*pp],   pah, bh);
                MMA_OP(o[2*pp],   pal, bh);
                MMA_OP(o[2*pp],   pah, bl);
                MMA_OP(o[2*pp+1], pah, bh + 2);
                MMA_OP(o[2*pp+1], pal, bh + 2);
                MMA_OP(o[2*pp+1], pah, bl + 2);
            }
        }
        __syncthreads();
    }

    l0_ += __shfl_xor_sync(0xffffffffu, l0_, 1);
    l0_ += __shfl_xor_sync(0xffffffffu, l0_, 2);
    l1_ += __shfl_xor_sync(0xffffffffu, l1_, 1);
    l1_ += __shfl_xor_sync(0xffffffffu, l1_, 2);
    float i0 = 1.f / l0_, i1 = 1.f / l1_;
    int row0 = qrow + lr, row1 = qrow + lr + 8;
    #pragma unroll
    for (int dt = 0; dt < 8; dt++) {
        int col = h*64 + dt*8 + lk;
        float v0 = o[dt][0]*i0, v1 = o[dt][1]*i0;
        float v2 = o[dt][2]*i1, v3 = o[dt][3]*i1;
        unsigned h01, l01, h23, l23;
        pack2(v0, v1, h01, l01);
        pack2(v2, v3, h23, l23);
        *(unsigned*)&ohp[(long long)row0*INNERD + col] = h01;
        *(unsigned*)&olp[(long long)row0*INNERD + col] = l01;
        *(unsigned*)&ohp[(long long)row1*INNERD + col] = h23;
        *(unsigned*)&olp[(long long)row1*INNERD + col] = l23;
    }
}

// ---------------- residual + layernorm ----------------
__global__ void k_addln(const float* __restrict__ x, const float* __restrict__ r,
                        const float* __restrict__ g, const float* __restrict__ bb,
                        float* __restrict__ out, bf* __restrict__ oh, bf* __restrict__ ol)
{
    int row = blockIdx.x;
    int tid = threadIdx.x;
    __shared__ float buf[DIMD];
    __shared__ float r1[256], r2[256];
    const float* xp = x + (size_t)row * DIMD;
    const float* rp = r + (size_t)row * DIMD;
    float s = 0.f, ss = 0.f;
    #pragma unroll
    for (int i = 0; i < 4; i++) {
        int j = tid + i * 256;
        float v = xp[j] + rp[j];
        buf[j] = v; s += v; ss += v * v;
    }
    r1[tid] = s; r2[tid] = ss; __syncthreads();
    for (int st = 128; st > 0; st >>= 1) {
        if (tid < st) { r1[tid] += r1[tid+st]; r2[tid] += r2[tid+st]; }
        __syncthreads();
    }
    float mean = r1[0] * (1.f / DIMD);
    float var  = r2[0] * (1.f / DIMD) - mean * mean;
    float inv  = rsqrtf(var + 1e-5f);
    #pragma unroll
    for (int i = 0; i < 4; i++) {
        int j = tid + i * 256;
        float v = (buf[j] - mean) * inv * g[j] + bb[j];
        out[(size_t)row * DIMD + j] = v;
        bf h = __float2bfloat16(v);
        oh[(size_t)row * DIMD + j] = h;
        ol[(size_t)row * DIMD + j] = __float2bfloat16(v - __bfloat162float(h));
    }
}

// ---------------- MoE router ----------------
__global__ void k_route(const float* __restrict__ xf, const float* __restrict__ gw,
                        float* __restrict__ probs_out)
{
    int tok = blockIdx.x;
    int tid = threadIdx.x;
    const float* xp = xf + (size_t)tok * DIMD;
    float part[NEXP] = {};
    for (int d = tid; d < DIMD; d += 256) {
        float xv = xp[d];
        #pragma unroll
        for (int e = 0; e < NEXP; e++) part[e] = fmaf(xv, gw[d*NEXP + e], part[e]);
    }
    __shared__ float sm[NEXP * 256];
    #pragma unroll
    for (int e = 0; e < NEXP; e++) sm[e*256 + tid] = part[e];
    __syncthreads();
    for (int s = 128; s > 0; s >>= 1) {
        if (tid < s) {
            #pragma unroll
            for (int e = 0; e < NEXP; e++) sm[e*256 + tid] += sm[e*256 + tid + s];
        }
        __syncthreads();
    }
    if (tid == 0) {
        float lg[NEXP], p[NEXP];
        float mx = NEGMIN;
        #pragma unroll
        for (int e = 0; e < NEXP; e++) { lg[e] = sm[e*256]; mx = fmaxf(mx, lg[e]); }
        float sum = 0.f;
        #pragma unroll
        for (int e = 0; e < NEXP; e++) { p[e] = expf(lg[e] - mx); sum += p[e]; }
        float inv = 1.f / sum;
        #pragma unroll
        for (int e = 0; e < NEXP; e++) { p[e] *= inv; probs_out[(size_t)tok*NEXP + e] = p[e]; }
        int i0 = 0;
        #pragma unroll
        for (int e = 1; e < NEXP; e++) if (p[e] > p[i0]) i0 = e;
        int i1 = (i0 == 0) ? 1 : 0;
        #pragma unroll
        for (int e = 0; e < NEXP; e++) if (e != i0 && p[e] > p[i1]) i1 = e;
        float w0 = p[i0], w1 = p[i1];
        float sw = 1.f / (w0 + w1);
        w0 *= sw; w1 *= sw;
        int pos = atomicAdd(&g_cnt[i0], 1);
        g_tok[i0*NTOK + pos] = tok; g_wslot[i0*NTOK + pos] = w0;
        g_inv[tok*2] = i0*NTOK + pos;
        pos = atomicAdd(&g_cnt[i1], 1);
        g_tok[i1*NTOK + pos] = tok; g_wslot[i1*NTOK + pos] = w1;
        g_inv[tok*2+1] = i1*NTOK + pos;
    }
}

// ---------------- final: 2 contribs + residual + LN3 ----------------
__global__ void k_moe_final(const float* __restrict__ x2, const float* __restrict__ g,
                            const float* __restrict__ bb, float* __restrict__ out)
{
    int tok = blockIdx.x;
    int tid = threadIdx.x;
    __shared__ float buf[DIMD];
    __shared__ float r1[256], r2[256];
    const float* xp = x2 + (size_t)tok * DIMD;
    int iv0 = g_inv[tok*2], iv1 = g_inv[tok*2+1];
    const float* c0 = g_contrib + (size_t)iv0 * DIMD;
    const float* c1 = g_contrib + (size_t)iv1 * DIMD;
    float s = 0.f, ss = 0.f;
    #pragma unroll
    for (int i = 0; i < 4; i++) {
        int j = tid + i * 256;
        float v = xp[j] + c0[j] + c1[j];
        buf[j] = v; s += v; ss += v * v;
    }
    r1[tid] = s; r2[tid] = ss; __syncthreads();
    for (int st = 128; st > 0; st >>= 1) {
        if (tid < st) { r1[tid] += r1[tid+st]; r2[tid] += r2[tid+st]; }
        __syncthreads();
    }
    float mean = r1[0] * (1.f / DIMD);
    float var  = r2[0] * (1.f / DIMD) - mean * mean;
    float inv  = rsqrtf(var + 1e-5f);
    float* op = out + (size_t)tok * DIMD;
    #pragma unroll
    for (int i = 0; i < 4; i++) {
        int j = tid + i * 256;
        op[j] = (buf[j] - mean) * inv * g[j] + bb[j];
    }
}

// ---------------- per-expert masked token sums (partitioned) ----------------
__global__ void k_tsum()
{
    int part = blockIdx.x % TSPART;
    int b = (blockIdx.x / TSPART) % NB;
    int e = blockIdx.x / (TSPART * NB);
    int tid = threadIdx.x;
    const int CH = SLEN / TSPART;
    __shared__ int sslot[SLEN / TSPART];
    for (int j = tid; j < CH; j += 256) {
        int t = b*SLEN + part*CH + j;
        int s = -1;
        if (!(g_mtgt[t] | g_mmid[t])) {
            int a = g_inv[2*t], c = g_inv[2*t+1];
            if ((a >> 11) == e) s = a;
            else if ((c >> 11) == e) s = c;
        }
        sslot[j] = s;
    }
    __syncthreads();
    for (int d = tid; d < DIMD; d += 256) {
        float acc = 0.f;
        for (int j = 0; j < CH; j++) {
            int s = sslot[j];
            if (s >= 0) acc += g_contrib[(size_t)s * DIMD + d];
        }
        g_tsumP[(((e*NB + b)*TSPART) + part)*DIMD + d] = acc;
    }
}

// ---------------- expert logits ----------------
__global__ void k_logits(const float* __restrict__ cls_w, const float* __restrict__ cls_b,
                         float* __restrict__ out_logits)
{
    int tid = threadIdx.x;
    __shared__ float red[256];
    __shared__ float dss[NEXP*NB];
    __shared__ float den[NB];
    for (int b = 0; b < NB; b++) {
        float c = 0.f;
        for (int j = tid; j < SLEN; j += 256)
            c += (!(g_mtgt[b*SLEN+j] | g_mmid[b*SLEN+j])) ? 1.f : 0.f;
        red[tid] = c; __syncthreads();
        for (int s = 128; s > 0; s >>= 1) { if (tid < s) red[tid] += red[tid+s]; __syncthreads(); }
        if (tid == 0) den[b] = fmaxf(red[0], 1.f);
        __syncthreads();
    }
    for (int eb = 0; eb < NEXP*NB; eb++) {
        float c = 0.f;
        for (int j = tid; j < DIMD; j += 256) {
            float t = 0.f;
            #pragma unroll
            for (int part = 0; part < TSPART; part++)
                t += g_tsumP[(eb*TSPART + part)*DIMD + j];
            c += t * cls_w[j];
        }
        red[tid] = c; __syncthreads();
        for (int s = 128; s > 0; s >>= 1) { if (tid < s) red[tid] += red[tid+s]; __syncthreads(); }
        if (tid == 0) dss[eb] = red[0];
        __syncthreads();
    }
    if (tid == 0) {
        for (int b = 0; b < NB; b++) {
            float pre = 0.f;
            for (int e = 0; e < NEXP; e++) {
                pre += dss[e*NB + b];
                out_logits[e*NB + b] = pre / den[b] + cls_b[0];
            }
        }
    }
}

// ---------------- host ----------------
struct GArg {
    const bf *Ah, *Al, *Bh, *Bl;
    float* C; bf *Ch, *Cl;
    int M, N, K, lda, ldb, ldc;
    long long sA1, sA2, sB1, sB2, sC1, sC2;
    int gz, bdiv, zmaps, swig;
    const float* bias; const int* rmA; const int* rmC;
    const float* rs; const int* cnt;
};

static void BG(const GArg& a)
{
    dim3 grid(a.N / 128, (a.M + 127) / 128, a.gz);
    k_bgemm<<<grid, 256, BG_SMEM>>>(
        a.Ah, a.Al, a.Bh, a.Bl, a.C, a.Ch, a.Cl, a.M, a.N, a.K, a.lda, a.ldb, a.ldc,
        a.sA1, a.sA2, a.sB1, a.sB2, a.sC1, a.sC2, a.bdiv, a.zmaps, a.swig,
        a.bias, a.rmA, a.rmC, a.rs, a.cnt);
}

extern "C" void kernel_launch(void* const* d_in, const int* in_sizes, int n_in,
                              void* d_out, int out_size)
{
    const float* x       = (const float*)d_in[0];
    const float* enc     = (const float*)d_in[1];
    const void*  src_mask_raw = d_in[2];
    const void*  tgt_mask_raw = d_in[3];
    const void*  tgt_mid_raw  = d_in[4];
    const float* ln1_g = (const float*)d_in[5];
    const float* ln1_b = (const float*)d_in[6];
    const float* ln2_g = (const float*)d_in[7];
    const float* ln2_b = (const float*)d_in[8];
    const float* ln3_g = (const float*)d_in[9];
    const float* ln3_b = (const float*)d_in[10];
    const float* sa_wq = (const float*)d_in[11];
    const float* sa_wk = (const float*)d_in[12];
    const float* sa_wv = (const float*)d_in[13];
    const float* sa_wo = (const float*)d_in[14];
    const float* sa_bo = (const float*)d_in[15];
    const float* ca_wq = (const float*)d_in[16];
    const float* ca_wk = (const float*)d_in[17];
    const float* ca_wv = (const float*)d_in[18];
    const float* ca_wo = (const float*)d_in[19];
    const float* ca_bo = (const float*)d_in[20];
    const float* gate_w = (const float*)d_in[21];
    const float* cls_w  = (const float*)d_in[22];
    const float* cls_b  = (const float*)d_in[23];
    const float* moe_w1 = (const float*)d_in[24];
    const float* moe_w2 = (const float*)d_in[25];
    const float* moe_w3 = (const float*)d_in[26];

    float* out = (float*)d_out;
    float* out_x      = out;
    float* out_logits = out + (size_t)NTOK * DIMD;
    float* out_probs  = out_logits + NEXP * NB;

    cudaFuncSetAttribute(k_bgemm, cudaFuncAttributeMaxDynamicSharedMemorySize, BG_SMEM);
    cudaFuncSetAttribute(k_fattn, cudaFuncAttributeMaxDynamicSharedMemorySize, FATTN_SMEM);

    // side stream + events (created once, on the uncaptured correctness call)
    static cudaStream_t s2 = nullptr;
    static cudaEvent_t evFork = nullptr, evCA = nullptr, evMOE = nullptr;
    static cudaEvent_t evCtr = nullptr, evTail = nullptr;
    if (!s2) {
        cudaStreamCreateWithFlags(&s2, cudaStreamNonBlocking);
        cudaEventCreateWithFlags(&evFork, cudaEventDisableTiming);
        cudaEventCreateWithFlags(&evCA,   cudaEventDisableTiming);
        cudaEventCreateWithFlags(&evMOE,  cudaEventDisableTiming);
        cudaEventCreateWithFlags(&evCtr,  cudaEventDisableTiming);
        cudaEventCreateWithFlags(&evTail, cudaEventDisableTiming);
    }

    float *pproj, *px1, *px2, *pcontrib, *pwslot;
    int *ptok, *pcnt;
    unsigned char *pmsrc, *pmtgt;
    bf *pxh,*pxl,*pawh,*pawl,*pw13h,*pw13l,*pw2h,*pw2l;
    bf *pqkvh,*pqkvl,*path,*patl,*px1h,*px1l,*px2h,*px2l,*pgh,*pgl;
    cudaGetSymbolAddress((void**)&pproj, g_proj);
    cudaGetSymbolAddress((void**)&px1, g_x1);
    cudaGetSymbolAddress((void**)&px2, g_x2);
    cudaGetSymbolAddress((void**)&pcontrib, g_contrib);
    cudaGetSymbolAddress((void**)&pwslot, g_wslot);
    cudaGetSymbolAddress((void**)&ptok, g_tok);
    cudaGetSymbolAddress((void**)&pcnt, g_cnt);
    cudaGetSymbolAddress((void**)&pmsrc, g_msrc);
    cudaGetSymbolAddress((void**)&pmtgt, g_mtgt);
    cudaGetSymbolAddress((void**)&pxh, g_xh);   cudaGetSymbolAddress((void**)&pxl, g_xl);
    cudaGetSymbolAddress((void**)&pawh, g_awh); cudaGetSymbolAddress((void**)&pawl, g_awl);
    cudaGetSymbolAddress((void**)&pw13h, g_w13h); cudaGetSymbolAddress((void**)&pw13l, g_w13l);
    cudaGetSymbolAddress((void**)&pw2h, g_w2h); cudaGetSymbolAddress((void**)&pw2l, g_w2l);
    cudaGetSymbolAddress((void**)&pqkvh, g_qkvh); cudaGetSymbolAddress((void**)&pqkvl, g_qkvl);
    cudaGetSymbolAddress((void**)&path, g_ath); cudaGetSymbolAddress((void**)&patl, g_atl);
    cudaGetSymbolAddress((void**)&px1h, g_x1h); cudaGetSymbolAddress((void**)&px1l, g_x1l);
    cudaGetSymbolAddress((void**)&px2h, g_x2h); cudaGetSymbolAddress((void**)&px2l, g_x2l);
    cudaGetSymbolAddress((void**)&pgh, g_gh);   cudaGetSymbolAddress((void**)&pgl, g_gl);

    bf* peh = px1h + (size_t)NTOK * DIMD;
    bf* pel = px1l + (size_t)NTOK * DIMD;

    const long long WMOE = (long long)DIMD * HIDD;
    const long long MM   = (long long)DIMD * INNERD;
    const long long W13  = 2LL * HIDD * DIMD;

    k_detect<<<1, 256>>>((const unsigned char*)tgt_mask_raw);
    // fork side stream
    cudaEventRecord(evFork, 0);
    cudaStreamWaitEvent(s2, evFork, 0);

    k_cvtmask<<<8, 256>>>(src_mask_raw, tgt_mask_raw, tgt_mid_raw);
    k_cvtA<<<512, 256>>>(x, pxh, pxl, NTOK*DIMD/4);
    const float* aw[8] = {sa_wq, sa_wk, sa_wv, sa_wo, ca_wq, ca_wk, ca_wv, ca_wo};
    // self-attn weights on main stream (needed first)
    for (int i = 0; i < 4; i++)
        k_cvtT<<<dim3(INNERD/64, DIMD/64, 1), dim3(16,16)>>>(aw[i], pawh + i*MM, pawl + i*MM, DIMD, INNERD, 0, 0, 1, 0);
    // enc conversion + cross-attn weights + MoE weights on side stream
    k_cvtA<<<512, 256, 0, s2>>>(enc, peh, pel, NTOK*DIMD/4);
    for (int i = 4; i < 8; i++)
        k_cvtT<<<dim3(INNERD/64, DIMD/64, 1), dim3(16,16), 0, s2>>>(aw[i], pawh + i*MM, pawl + i*MM, DIMD, INNERD, 0, 0, 1, 0);
    cudaEventRecord(evCA, s2);
    k_cvtT<<<dim3(HIDD/64, DIMD/64, NEXP), dim3(16,16), 0, s2>>>(moe_w1, pw13h, pw13l, DIMD, HIDD, WMOE, W13, 2, 0);
    k_cvtT<<<dim3(HIDD/64, DIMD/64, NEXP), dim3(16,16), 0, s2>>>(moe_w3, pw13h, pw13l, DIMD, HIDD, WMOE, W13, 2, 1);
    k_cvtT<<<dim3(DIMD/64, HIDD/64, NEXP), dim3(16,16), 0, s2>>>(moe_w2, pw2h, pw2l, HIDD, DIMD, WMOE, WMOE, 1, 0);
    cudaEventRecord(evMOE, s2);

    GArg a{};

    for (int lam = 0; lam < 2; lam++) {
        int wb = lam * 4;
        const float* bo = lam ? ca_bo : sa_bo;
        unsigned char* msk = lam ? pmsrc : pmtgt;

        if (lam == 0) {
            // self: Q|K|V in one N=3072 launch
            a = GArg{}; a.gz = 1; a.bdiv = 1;
            a.Ah = pxh; a.Al = pxl; a.Bh = pawh; a.Bl = pawl;
            a.Ch = pqkvh; a.Cl = pqkvl;
            a.M = NTOK; a.N = QKVW; a.K = DIMD; a.lda = DIMD; a.ldb = DIMD; a.ldc = QKVW;
            BG(a);
        } else {
            // join: cross weights + enc planes must be ready
            cudaStreamWaitEvent(0, evCA, 0);
            a = GArg{}; a.gz = 3; a.bdiv = 2;
            a.Ah = px1h; a.Al = px1l;
            a.Bh = pawh + 4*MM; a.Bl = pawl + 4*MM;
            a.Ch = pqkvh; a.Cl = pqkvl;
            a.M = NTOK; a.N = INNERD; a.K = DIMD; a.lda = DIMD; a.ldb = DIMD; a.ldc = QKVW;
            a.sA1 = (long long)NTOK * DIMD;  a.sA2 = (long long)NTOK * DIMD;
            a.sB1 = MM;  a.sB2 = 2*MM;
            a.sC1 = INNERD; a.sC2 = 2*INNERD;
            BG(a);
        }
        k_fattn<<<dim3(SLEN/128, HEADS, NB), 256, FATTN_SMEM>>>(
            pqkvh, pqkvl, path, patl, msk);
        a = GArg{}; a.gz = 1; a.bdiv = 1;
        a.Ah = path; a.Al = patl; a.Bh = pawh + (wb+3)*MM; a.Bl = pawl + (wb+3)*MM;
        a.C = pproj; a.bias = bo;
        a.M = NTOK; a.N = DIMD; a.K = INNERD; a.lda = INNERD; a.ldb = INNERD; a.ldc = DIMD;
        BG(a);
        if (lam == 0)
            k_addln<<<NTOK, 256>>>(x, pproj, ln1_g, ln1_b, px1, px1h, px1l);
        else
            k_addln<<<NTOK, 256>>>(px1, pproj, ln2_g, ln2_b, px2, px2h, px2l);
    }

    k_route<<<NTOK, 256>>>(px2, gate_w, out_probs);
    // join: MoE weights must be converted
    cudaStreamWaitEvent(0, evMOE, 0);
    a = GArg{}; a.gz = NEXP; a.bdiv = NEXP; a.zmaps = 1; a.swig = 1;
    a.Ah = px2h; a.Al = px2l; a.Bh = pw13h; a.Bl = pw13l;
    a.Ch = pgh; a.Cl = pgl;
    a.M = NTOK; a.N = 2*HIDD; a.K = DIMD; a.lda = DIMD; a.ldb = DIMD; a.ldc = HIDD;
    a.sB1 = W13; a.sC1 = (long long)NTOK*HIDD;
    a.rmA = ptok; a.cnt = pcnt;
    BG(a);
    a = GArg{}; a.gz = NEXP; a.bdiv = NEXP; a.zmaps = 1;
    a.Ah = pgh; a.Al = pgl; a.Bh = pw2h; a.Bl = pw2l; a.C = pcontrib;
    a.M = NTOK; a.N = DIMD; a.K = HIDD; a.lda = HIDD; a.ldb = HIDD; a.ldc = DIMD;
    a.sA1 = (long long)NTOK*HIDD; a.sB1 = WMOE; a.sC1 = (long long)NTOK*DIMD;
    a.rs = pwslot; a.cnt = pcnt;
    BG(a);

    // tail fork: tsum+logits (out_logits) on s2 concurrent with moe_final (out_x)
    cudaEventRecord(evCtr, 0);
    cudaStreamWaitEvent(s2, evCtr, 0);
    k_tsum<<<NEXP*NB*TSPART, 256, 0, s2>>>();
    k_logits<<<1, 256, 0, s2>>>(cls_w, cls_b, out_logits);
    cudaEventRecord(evTail, s2);

    k_moe_final<<<NTOK, 256>>>(px2, ln3_g, ln3_b, out_x);
    cudaStreamWaitEvent(0, evTail, 0);
}

// round 17
// speedup vs baseline: 1.1052x; 1.0218x over previous
#include <cuda_runtime.h>
#include <cuda_bf16.h>
#include <math.h>

#define DIMD   1024
#define HEADS  16
#define DHEAD  64
#define HIDD   2048
#define NEXP   8
#define NB     2
#define SLEN   1024
#define NTOK   (NB*SLEN)
#define INNERD (HEADS*DHEAD)
#define QKVW   (3*INNERD)
#define NEGMIN (-3.402823466e38f)
#define SCL2   0.18033688011112042f   // 0.125 * log2(e)
#define TSPART 8

typedef __nv_bfloat16 bf;

// ---------------- device scratch ----------------
__device__ float g_proj[NTOK*DIMD];
__device__ float g_x1[NTOK*DIMD];
__device__ float g_x2[NTOK*DIMD];
__device__ float g_contrib[(size_t)NEXP*NTOK*DIMD];
__device__ float g_wslot[NEXP*NTOK];
__device__ int   g_tok[NEXP*NTOK];
__device__ int   g_inv[NTOK*2];
__device__ int   g_cnt[NEXP];
__device__ float g_tsumP[NEXP*NB*TSPART*DIMD];
__device__ bf g_xh[NTOK*DIMD],  g_xl[NTOK*DIMD];
__device__ bf g_x1h[2*NTOK*DIMD], g_x1l[2*NTOK*DIMD];   // x1 | enc planes
__device__ bf g_awh[8*DIMD*INNERD], g_awl[8*DIMD*INNERD];
__device__ bf g_w13h[(size_t)NEXP*2*HIDD*DIMD], g_w13l[(size_t)NEXP*2*HIDD*DIMD];
__device__ bf g_w2h[(size_t)NEXP*HIDD*DIMD], g_w2l[(size_t)NEXP*HIDD*DIMD];
__device__ bf g_qkvh[2*(size_t)NTOK*QKVW], g_qkvl[2*(size_t)NTOK*QKVW];  // [layer][tok][q|k|v]
__device__ bf g_ath[NTOK*INNERD], g_atl[NTOK*INNERD];
__device__ bf g_x2h[NTOK*DIMD], g_x2l[NTOK*DIMD];
__device__ bf g_gh[(size_t)NEXP*NTOK*HIDD], g_gl[(size_t)NEXP*NTOK*HIDD];
__device__ unsigned char g_msrc[NTOK];
__device__ unsigned char g_mtgt[NTOK];
__device__ unsigned char g_mmid[NTOK];
__device__ int g_mtype;

// ---------------- PTX helpers ----------------
__device__ __forceinline__ unsigned smem_u32(const void* p) {
    return (unsigned)__cvta_generic_to_shared(p);
}
__device__ __forceinline__ void cp16(unsigned d, const void* s, bool v) {
    if (v) asm volatile("cp.async.ca.shared.global [%0], [%1], 16;\n" :: "r"(d), "l"(s) : "memory");
    else   asm volatile("cp.async.ca.shared.global [%0], [%1], 16, 0;\n" :: "r"(d), "l"(s) : "memory");
}
#define CP_COMMIT asm volatile("cp.async.commit_group;\n" ::: "memory")
#define CP_WAIT0  asm volatile("cp.async.wait_group 0;\n" ::: "memory")
#define CP_WAIT1  asm volatile("cp.async.wait_group 1;\n" ::: "memory")

#define LDSM_X4(d0, d1, d2, d3, a) \
    asm volatile("ldmatrix.sync.aligned.m8n8.x4.shared.b16 {%0,%1,%2,%3}, [%4];" \
                 : "=r"(d0), "=r"(d1), "=r"(d2), "=r"(d3) : "r"(a))

#define LDSM_X4T(d0, d1, d2, d3, a) \
    asm volatile("ldmatrix.sync.aligned.m8n8.x4.trans.shared.b16 {%0,%1,%2,%3}, [%4];" \
                 : "=r"(d0), "=r"(d1), "=r"(d2), "=r"(d3) : "r"(a))

#define MMA_OP(c, a, b) \
    asm volatile("mma.sync.aligned.m16n8k16.row.col.f32.bf16.bf16.f32 " \
                 "{%0,%1,%2,%3},{%4,%5,%6,%7},{%8,%9},{%0,%1,%2,%3};" \
                 : "+f"((c)[0]), "+f"((c)[1]), "+f"((c)[2]), "+f"((c)[3]) \
                 : "r"((a)[0]), "r"((a)[1]), "r"((a)[2]), "r"((a)[3]), \
                   "r"((b)[0]), "r"((b)[1]))

__device__ __forceinline__ void pack2(float x, float y, unsigned& hi, unsigned& lo) {
    bf hx = __float2bfloat16(x), hy = __float2bfloat16(y);
    __nv_bfloat162 th; th.x = hx; th.y = hy;
    hi = *(unsigned*)&th;
    __nv_bfloat162 tl;
    tl.x = __float2bfloat16(x - __bfloat162float(hx));
    tl.y = __float2bfloat16(y - __bfloat162float(hy));
    lo = *(unsigned*)&tl;
}

// ---------------- mask detection / conversion ----------------
__global__ void k_detect(const unsigned char* __restrict__ tgt) {
    __shared__ int has_gt1, has_off;
    if (threadIdx.x == 0) { has_gt1 = 0; has_off = 0; }
    if (threadIdx.x < NEXP) g_cnt[threadIdx.x] = 0;
    __syncthreads();
    for (int j = threadIdx.x; j < NTOK; j += blockDim.x) {
        unsigned char v = tgt[j];
        if (v > 1) atomicOr(&has_gt1, 1);
        else if (v && (j & 3)) atomicOr(&has_off, 1);
    }
    __syncthreads();
    if (threadIdx.x == 0)
        g_mtype = has_gt1 ? 2 : (has_off ? 0 : 1);
}

__global__ void k_cvtmask(const void* __restrict__ s0, const void* __restrict__ s1,
                          const void* __restrict__ s2) {
    int t = g_mtype;
    int stride = gridDim.x * blockDim.x;
    for (int j = blockIdx.x * blockDim.x + threadIdx.x; j < NTOK; j += stride) {
        unsigned char a, b, c;
        if (t == 1) {
            a = ((const int*)s0)[j] != 0;
            b = ((const int*)s1)[j] != 0;
            c = ((const int*)s2)[j] != 0;
        } else if (t == 2) {
            a = ((const float*)s0)[j] != 0.f;
            b = ((const float*)s1)[j] != 0.f;
            c = ((const float*)s2)[j] != 0.f;
        } else {
            a = ((const unsigned char*)s0)[j];
            b = ((const unsigned char*)s1)[j];
            c = ((const unsigned char*)s2)[j];
        }
        g_msrc[j] = a; g_mtgt[j] = b; g_mmid[j] = c;
    }
}

// ---------------- conversion kernels ----------------
__global__ void k_cvtA(const float* __restrict__ s, bf* __restrict__ dh, bf* __restrict__ dl, int n4)
{
    int stride = gridDim.x * blockDim.x;
    for (int i = blockIdx.x * blockDim.x + threadIdx.x; i < n4; i += stride) {
        float4 v = ((const float4*)s)[i];
        float vv[4] = {v.x, v.y, v.z, v.w};
        bf h[4], l[4];
        #pragma unroll
        for (int j = 0; j < 4; j++) {
            h[j] = __float2bfloat16(vv[j]);
            l[j] = __float2bfloat16(vv[j] - __bfloat162float(h[j]));
        }
        ((ushort4*)dh)[i] = *(ushort4*)h;
        ((ushort4*)dl)[i] = *(ushort4*)l;
    }
}

// transpose-convert, 64x64 tile, vectorized: src fp32 [Kd][Nd] -> planes [Nd][Kd]
__global__ void k_cvtT(const float* __restrict__ src, bf* __restrict__ dh, bf* __restrict__ dl,
                       int Kd, int Nd, long long sSrc, long long sDst, int rowMul, int rowAdd)
{
    int z = blockIdx.z;
    src += (long long)z * sSrc; dh += (long long)z * sDst; dl += (long long)z * sDst;
    __shared__ float t[64][65];
    int k0 = blockIdx.y * 64, n0 = blockIdx.x * 64;
    int tx = threadIdx.x;   // 16
    int ty = threadIdx.y;   // 16
    #pragma unroll
    for (int i = 0; i < 4; i++) {
        int kk = k0 + ty + i * 16;
        float4 v = *(const float4*)&src[(long long)kk * Nd + n0 + tx * 4];
        t[ty + i * 16][tx * 4 + 0] = v.x;
        t[ty + i * 16][tx * 4 + 1] = v.y;
        t[ty + i * 16][tx * 4 + 2] = v.z;
        t[ty + i * 16][tx * 4 + 3] = v.w;
    }
    __syncthreads();
    #pragma unroll
    for (int j = 0; j < 4; j++) {
        int nn = n0 + ty + j * 16;
        bf h[4], l[4];
        #pragma unroll
        for (int c = 0; c < 4; c++) {
            float v = t[tx * 4 + c][ty + j * 16];
            h[c] = __float2bfloat16(v);
            l[c] = __float2bfloat16(v - __bfloat162float(h[c]));
        }
        long long dr = (long long)nn * rowMul + rowAdd;
        *(ushort4*)&dh[dr * Kd + k0 + tx * 4] = *(ushort4*)h;
        *(ushort4*)&dl[dr * Kd + k0 + tx * 4] = *(ushort4*)l;
    }
}

// ---------------- bf16-plane tensor-core GEMM (ldmatrix + 3-stage pipeline) ----------------
#define LDS_ 40
#define NSTG 3
#define OFFA(st, pl) (((st)*2 + (pl)) * 128 * LDS_ * 2)
#define OFFB(st, pl) (NSTG*2*128*LDS_*2 + ((st)*2 + (pl)) * 128 * LDS_ * 2)
#define BG_SROW (2 * NSTG*2*128*LDS_*2)
#define BG_SMEM (BG_SROW + 512 + 64)

__global__ void __launch_bounds__(256) k_bgemm(
    const bf* __restrict__ Ah, const bf* __restrict__ Al,
    const bf* __restrict__ Bh, const bf* __restrict__ Bl,
    float* __restrict__ C, bf* __restrict__ Ch, bf* __restrict__ Cl,
    int M, int N, int K, int lda, int ldb, int ldc,
    long long sA1, long long sA2, long long sB1, long long sB2,
    long long sC1, long long sC2, int bdiv, int zmaps, int swiglu,
    const float* __restrict__ bias,
    const int* __restrict__ rowmapA, const int* __restrict__ rowmapC,
    const float* __restrict__ rowscale, const int* __restrict__ cntPtr)
{
    int z = blockIdx.z;
    long long ao = (long long)(z / bdiv) * sA2 + (long long)(z % bdiv) * sA1;
    long long bo = (long long)(z / bdiv) * sB2 + (long long)(z % bdiv) * sB1;
    long long co = (long long)(z / bdiv) * sC2 + (long long)(z % bdiv) * sC1;
    const bf* Ahp = Ah + ao; const bf* Alp = Al + ao;
    const bf* Bhp = Bh + bo; const bf* Blp = Bl + bo;
    float* Cp = C ? C + co : nullptr;
    bf* Chp = Ch ? Ch + co : nullptr;
    bf* Clp = Cl ? Cl + co : nullptr;
    if (zmaps) {
        if (rowmapA) rowmapA += z * NTOK;
        if (rowmapC) rowmapC += z * NTOK;
        if (rowscale) rowscale += z * NTOK;
        if (cntPtr) cntPtr += z;
    }
    int Meff = M;
    if (cntPtr) { int c = *cntPtr; Meff = c < M ? c : M; }
    int m0 = blockIdx.y * 128;
    if (m0 >= Meff) return;
    int n0 = blockIdx.x * 128;

    extern __shared__ __align__(16) char dyn[];
    unsigned sb = smem_u32(dyn);
    int* sRow = (int*)(dyn + BG_SROW);

    int tid = threadIdx.x, lane = tid & 31, warp = tid >> 5;
    int warp_n = warp & 3, warp_m = warp >> 2;
    int lr = lane >> 2, lk = (lane & 3) * 2;
    int quad = lane >> 3, rin = lane & 7;

    for (int r = tid; r < 128; r += 256) {
        int gm = m0 + r;
        sRow[r] = (gm < Meff) ? (rowmapA ? rowmapA[gm] : gm) : 0;
    }
    __syncthreads();

    int a_r = rin + ((quad & 1) ? 8 : 0);
    int a_c = (quad & 2) ? 8 : 0;
    int b_r = rin + ((quad >> 1) ? 8 : 0);
    int b_c = (quad & 1) ? 8 : 0;
    int aoff[4], boff[2];
    #pragma unroll
    for (int tm = 0; tm < 4; tm++)
        aoff[tm] = ((warp_m * 64 + tm * 16 + a_r) * LDS_ + a_c) * 2;
    #pragma unroll
    for (int p = 0; p < 2; p++)
        boff[p] = ((warp_n * 32 + p * 16 + b_r) * LDS_ + b_c) * 2;

    auto loadStage = [&](int st, int k0) {
        #pragma unroll
        for (int i = 0; i < 2; i++) {
            int c = tid + i * 256;
            int row = c >> 2, q = c & 3;
            bool v = (m0 + row) < Meff;
            long long so = (long long)sRow[row] * lda + k0 + q * 8;
            unsigned ds = (row * LDS_ + q * 8) * 2;
            cp16(sb + OFFA(st, 0) + ds, Ahp + so, v);
            cp16(sb + OFFA(st, 1) + ds, Alp + so, v);
        }
        #pragma unroll
        for (int i = 0; i < 2; i++) {
            int c = tid + i * 256;
            int row = c >> 2, q = c & 3;
            long long so = (long long)(n0 + row) * ldb + k0 + q * 8;
            unsigned ds = (row * LDS_ + q * 8) * 2;
            cp16(sb + OFFB(st, 0) + ds, Bhp + so, true);
            cp16(sb + OFFB(st, 1) + ds, Blp + so, true);
        }
    };

    float acc[4][4][4];
    #pragma unroll
    for (int i = 0; i < 4; i++)
        #pragma unroll
        for (int j = 0; j < 4; j++)
            #pragma unroll
            for (int q = 0; q < 4; q++) acc[i][j][q] = 0.f;

    int KT = K >> 5;
    loadStage(0, 0); CP_COMMIT;
    loadStage(1, 32); CP_COMMIT;

    for (int kt = 0; kt < KT; kt++) {
        int s = kt % NSTG;
        if (kt + 1 < KT) { CP_WAIT1; } else { CP_WAIT0; }
        __syncthreads();
        if (kt + 2 < KT) { loadStage((kt + 2) % NSTG, (kt + 2) * 32); CP_COMMIT; }

        unsigned bAh = sb + OFFA(s, 0), bAl = sb + OFFA(s, 1);
        unsigned bBh = sb + OFFB(s, 0), bBl = sb + OFFB(s, 1);
        #pragma unroll
        for (int kc = 0; kc < 2; kc++) {
            unsigned afh[4][4], afl[4][4], bfh[4][2], bfl[4][2];
            #pragma unroll
            for (int tm = 0; tm < 4; tm++) {
                LDSM_X4(afh[tm][0], afh[tm][1], afh[tm][2], afh[tm][3], bAh + aoff[tm] + kc * 32);
                LDSM_X4(afl[tm][0], afl[tm][1], afl[tm][2], afl[tm][3], bAl + aoff[tm] + kc * 32);
            }
            #pragma unroll
            for (int p = 0; p < 2; p++) {
                LDSM_X4(bfh[2*p][0], bfh[2*p][1], bfh[2*p+1][0], bfh[2*p+1][1], bBh + boff[p] + kc * 32);
                LDSM_X4(bfl[2*p][0], bfl[2*p][1], bfl[2*p+1][0], bfl[2*p+1][1], bBl + boff[p] + kc * 32);
            }
            #pragma unroll
            for (int tm = 0; tm < 4; tm++)
                #pragma unroll
                for (int tn = 0; tn < 4; tn++) {
                    MMA_OP(acc[tm][tn], afh[tm], bfh[tn]);
                    MMA_OP(acc[tm][tn], afl[tm], bfh[tn]);
                    MMA_OP(acc[tm][tn], afh[tm], bfl[tn]);
                }
        }
    }

    #pragma unroll
    for (int tm = 0; tm < 4; tm++) {
        #pragma unroll
        for (int half = 0; half < 2; half++) {
            int gm = m0 + warp_m * 64 + tm * 16 + lr + half * 8;
            if (gm >= Meff) continue;
            float scale = rowscale ? rowscale[gm] : 1.f;
            long long crow = rowmapC ? (long long)rowmapC[gm] : (long long)gm;
            #pragma unroll
            for (int tn = 0; tn < 4; tn++) {
                int col = n0 + warp_n * 32 + tn * 8 + lk;
                float v0 = acc[tm][tn][half * 2 + 0];
                float v1 = acc[tm][tn][half * 2 + 1];
                if (swiglu) {
                    float g = v0 * v1 / (1.f + expf(-v0));
                    int j = col >> 1;
                    bf h = __float2bfloat16(g);
                    Chp[crow * ldc + j] = h;
                    Clp[crow * ldc + j] = __float2bfloat16(g - __bfloat162float(h));
                    continue;
                }
                v0 *= scale; v1 *= scale;
                if (bias) { v0 += bias[col]; v1 += bias[col + 1]; }
                if (Cp) *(float2*)&Cp[crow * ldc + col] = make_float2(v0, v1);
                if (Chp) {
                    unsigned hi, lo;
                    pack2(v0, v1, hi, lo);
                    *(unsigned*)&Chp[crow * ldc + col] = hi;
                    *(unsigned*)&Clp[crow * ldc + col] = lo;
                }
            }
        }
    }
}

// ---------------- fused flash attention (qkv buffer, V via ldmatrix.trans) ----------------
#define FATTN_SMEM (4*(2*128*72*2) + 1024)
__global__ void __launch_bounds__(256) k_fattn(
    const bf* __restrict__ qkvh, const bf* __restrict__ qkvl,
    bf* __restrict__ ohp, bf* __restrict__ olp,
    const unsigned char* __restrict__ mask)
{
    int m0 = blockIdx.x * 128;
    int h  = blockIdx.y;
    int b  = blockIdx.z;
    int tid = threadIdx.x, lane = tid & 31, warp = tid >> 5;
    int lr = lane >> 2, lk = (lane & 3) * 2;
    int quad = lane >> 3, rin = lane & 7;
    int b_r = rin + ((quad >> 1) ? 8 : 0);
    int b_c = (quad & 1) ? 8 : 0;
    int vrow = rin + 8 * ((lane >> 3) & 1);
    int vcol = 8 * (lane >> 4);

    extern __shared__ __align__(16) char smem[];
    bf* sKh = (bf*)smem;
    bf* sKl = sKh + 2*128*72;
    bf* sVh = sKl + 2*128*72;
    bf* sVl = sVh + 2*128*72;
    unsigned char* smask = (unsigned char*)(sVl + 2*128*72);
    unsigned kh_a = smem_u32(sKh);
    unsigned kl_a = smem_u32(sKl);
    unsigned vh_a = smem_u32(sVh);
    unsigned vl_a = smem_u32(sVl);

    for (int j = tid; j < SLEN; j += 256) smask[j] = mask[b*SLEN + j];

    int qrow = b*SLEN + m0 + warp*16;
    unsigned qfh[4][4], qfl[4][4];
    #pragma unroll
    for (int kc = 0; kc < 4; kc++) {
        long long b0 = (long long)(qrow + lr) * QKVW + h*64 + kc*16 + lk;
        long long b1 = b0 + 8LL*QKVW;
        qfh[kc][0] = *(const unsigned*)&qkvh[b0];
        qfh[kc][1] = *(const unsigned*)&qkvh[b1];
        qfh[kc][2] = *(const unsigned*)&qkvh[b0 + 8];
        qfh[kc][3] = *(const unsigned*)&qkvh[b1 + 8];
        qfl[kc][0] = *(const unsigned*)&qkvl[b0];
        qfl[kc][1] = *(const unsigned*)&qkvl[b1];
        qfl[kc][2] = *(const unsigned*)&qkvl[b0 + 8];
        qfl[kc][3] = *(const unsigned*)&qkvl[b1 + 8];
    }

    auto loadChunk = [&](int st, int c) {
        int t0 = c * 128;
        #pragma unroll
        for (int i = 0; i < 4; i++) {
            int idx = tid + i*256;
            int r = idx >> 3, q = idx & 7;
            long long srcK = (long long)(b*SLEN + t0 + r) * QKVW + INNERD + h*64 + q*8;
            long long srcV = srcK + INNERD;
            unsigned ds = ((st*128 + r)*72 + q*8)*2;
            cp16(kh_a + ds, qkvh + srcK, true);
            cp16(kl_a + ds, qkvl + srcK, true);
            cp16(vh_a + ds, qkvh + srcV, true);
            cp16(vl_a + ds, qkvl + srcV, true);
        }
    };

    float m0_ = -1e30f, m1_ = -1e30f, l0_ = 0.f, l1_ = 0.f;
    float o[8][4];
    #pragma unroll
    for (int i = 0; i < 8; i++) { o[i][0]=0.f; o[i][1]=0.f; o[i][2]=0.f; o[i][3]=0.f; }

    loadChunk(0, 0); CP_COMMIT;

    for (int c = 0; c < 8; c++) {
        int st = c & 1;
        CP_WAIT0; __syncthreads();
        if (c + 1 < 8) { loadChunk(st ^ 1, c + 1); CP_COMMIT; }

        float s[16][4];
        #pragma unroll
        for (int t = 0; t < 16; t++) { s[t][0]=0.f; s[t][1]=0.f; s[t][2]=0.f; s[t][3]=0.f; }
        #pragma unroll
        for (int kc = 0; kc < 4; kc++) {
            #pragma unroll
            for (int p = 0; p < 8; p++) {
                unsigned off = ((unsigned)(st*128 + p*16 + b_r)*72 + kc*16 + b_c)*2;
                unsigned bh[4], bl[4];
                LDSM_X4(bh[0], bh[1], bh[2], bh[3], kh_a + off);
                LDSM_X4(bl[0], bl[1], bl[2], bl[3], kl_a + off);
                MMA_OP(s[2*p],   qfh[kc], bh);
                MMA_OP(s[2*p],   qfl[kc], bh);
                MMA_OP(s[2*p],   qfh[kc], bl);
                MMA_OP(s[2*p+1], qfh[kc], bh + 2);
                MMA_OP(s[2*p+1], qfl[kc], bh + 2);
                MMA_OP(s[2*p+1], qfh[kc], bl + 2);
            }
        }
        #pragma unroll
        for (int t = 0; t < 16; t++) {
            int col = c*128 + t*8 + lk;
            bool k0m = smask[col] != 0;
            bool k1m = smask[col + 1] != 0;
            s[t][0] = k0m ? -1e30f : s[t][0] * SCL2;
            s[t][1] = k1m ? -1e30f : s[t][1] * SCL2;
            s[t][2] = k0m ? -1e30f : s[t][2] * SCL2;
            s[t][3] = k1m ? -1e30f : s[t][3] * SCL2;
        }
        float mx0 = -1e30f, mx1 = -1e30f;
        #pragma unroll
        for (int t = 0; t < 16; t++) {
            mx0 = fmaxf(mx0, fmaxf(s[t][0], s[t][1]));
            mx1 = fmaxf(mx1, fmaxf(s[t][2], s[t][3]));
        }
        mx0 = fmaxf(mx0, __shfl_xor_sync(0xffffffffu, mx0, 1));
        mx0 = fmaxf(mx0, __shfl_xor_sync(0xffffffffu, mx0, 2));
        mx1 = fmaxf(mx1, __shfl_xor_sync(0xffffffffu, mx1, 1));
        mx1 = fmaxf(mx1, __shfl_xor_sync(0xffffffffu, mx1, 2));
        float mn0 = fmaxf(m0_, mx0), mn1 = fmaxf(m1_, mx1);
        float a0 = exp2f(m0_ - mn0), a1 = exp2f(m1_ - mn1);
        m0_ = mn0; m1_ = mn1;
        float rs0 = 0.f, rs1 = 0.f;
        #pragma unroll
        for (int t = 0; t < 16; t++) {
            s[t][0] = exp2f(s[t][0] - mn0);
            s[t][1] = exp2f(s[t][1] - mn0);
            s[t][2] = exp2f(s[t][2] - mn1);
            s[t][3] = exp2f(s[t][3] - mn1);
            rs0 += s[t][0] + s[t][1];
            rs1 += s[t][2] + s[t][3];
        }
        l0_ = l0_ * a0 + rs0;
        l1_ = l1_ * a1 + rs1;
        #pragma unroll
        for (int dt = 0; dt < 8; dt++) {
            o[dt][0] *= a0; o[dt][1] *= a0; o[dt][2] *= a1; o[dt][3] *= a1;
        }
        #pragma unroll
        for (int kc = 0; kc < 8; kc++) {
            unsigned pah[4], pal[4];
            pack2(s[2*kc][0],   s[2*kc][1],   pah[0], pal[0]);
            pack2(s[2*kc][2],   s[2*kc][3],   pah[1], pal[1]);
            pack2(s[2*kc+1][0], s[2*kc+1][1], pah[2], pal[2]);
            pack2(s[2*kc+1][2], s[2*kc+1][3], pah[3], pal[3]);
            unsigned vbase = ((unsigned)(st*128 + kc*16 + vrow)*72 + vcol)*2;
            #pragma unroll
            for (int pp = 0; pp < 4; pp++) {
                unsigned off = vbase + pp * 32;
                unsigned bh[4], bl[4];
                LDSM_X4T(bh[0], bh[1], bh[2], bh[3], vh_a + off);
                LDSM_X4T(bl[0], bl[1], bl[2], bl[3], vl_a + off);
                MMA_OP(o[2*pp],   pah, bh);
                MMA_OP(o[2*pp],   pal, bh);
                MMA_OP(o[2*pp],   pah, bl);
                MMA_OP(o[2*pp+1], pah, bh + 2);
                MMA_OP(o[2*pp+1], pal, bh + 2);
                MMA_OP(o[2*pp+1], pah, bl + 2);
            }
        }
        __syncthreads();
    }

    l0_ += __shfl_xor_sync(0xffffffffu, l0_, 1);
    l0_ += __shfl_xor_sync(0xffffffffu, l0_, 2);
    l1_ += __shfl_xor_sync(0xffffffffu, l1_, 1);
    l1_ += __shfl_xor_sync(0xffffffffu, l1_, 2);
    float i0 = 1.f / l0_, i1 = 1.f / l1_;
    int row0 = qrow + lr, row1 = qrow + lr + 8;
    #pragma unroll
    for (int dt = 0; dt < 8; dt++) {
        int col = h*64 + dt*8 + lk;
        float v0 = o[dt][0]*i0, v1 = o[dt][1]*i0;
        float v2 = o[dt][2]*i1, v3 = o[dt][3]*i1;
        unsigned h01, l01, h23, l23;
        pack2(v0, v1, h01, l01);
        pack2(v2, v3, h23, l23);
        *(unsigned*)&ohp[(long long)row0*INNERD + col] = h01;
        *(unsigned*)&olp[(long long)row0*INNERD + col] = l01;
        *(unsigned*)&ohp[(long long)row1*INNERD + col] = h23;
        *(unsigned*)&olp[(long long)row1*INNERD + col] = l23;
    }
}

// ---------------- residual + layernorm ----------------
__global__ void k_addln(const float* __restrict__ x, const float* __restrict__ r,
                        const float* __restrict__ g, const float* __restrict__ bb,
                        float* __restrict__ out, bf* __restrict__ oh, bf* __restrict__ ol)
{
    int row = blockIdx.x;
    int tid = threadIdx.x;
    __shared__ float buf[DIMD];
    __shared__ float r1[256], r2[256];
    const float* xp = x + (size_t)row * DIMD;
    const float* rp = r + (size_t)row * DIMD;
    float s = 0.f, ss = 0.f;
    #pragma unroll
    for (int i = 0; i < 4; i++) {
        int j = tid + i * 256;
        float v = xp[j] + rp[j];
        buf[j] = v; s += v; ss += v * v;
    }
    r1[tid] = s; r2[tid] = ss; __syncthreads();
    for (int st = 128; st > 0; st >>= 1) {
        if (tid < st) { r1[tid] += r1[tid+st]; r2[tid] += r2[tid+st]; }
        __syncthreads();
    }
    float mean = r1[0] * (1.f / DIMD);
    float var  = r2[0] * (1.f / DIMD) - mean * mean;
    float inv  = rsqrtf(var + 1e-5f);
    #pragma unroll
    for (int i = 0; i < 4; i++) {
        int j = tid + i * 256;
        float v = (buf[j] - mean) * inv * g[j] + bb[j];
        out[(size_t)row * DIMD + j] = v;
        bf h = __float2bfloat16(v);
        oh[(size_t)row * DIMD + j] = h;
        ol[(size_t)row * DIMD + j] = __float2bfloat16(v - __bfloat162float(h));
    }
}

// ---------------- MoE router ----------------
__global__ void k_route(const float* __restrict__ xf, const float* __restrict__ gw,
                        float* __restrict__ probs_out)
{
    int tok = blockIdx.x;
    int tid = threadIdx.x;
    const float* xp = xf + (size_t)tok * DIMD;
    float part[NEXP] = {};
    for (int d = tid; d < DIMD; d += 256) {
        float xv = xp[d];
        #pragma unroll
        for (int e = 0; e < NEXP; e++) part[e] = fmaf(xv, gw[d*NEXP + e], part[e]);
    }
    __shared__ float sm[NEXP * 256];
    #pragma unroll
    for (int e = 0; e < NEXP; e++) sm[e*256 + tid] = part[e];
    __syncthreads();
    for (int s = 128; s > 0; s >>= 1) {
        if (tid < s) {
            #pragma unroll
            for (int e = 0; e < NEXP; e++) sm[e*256 + tid] += sm[e*256 + tid + s];
        }
        __syncthreads();
    }
    if (tid == 0) {
        float lg[NEXP], p[NEXP];
        float mx = NEGMIN;
        #pragma unroll
        for (int e = 0; e < NEXP; e++) { lg[e] = sm[e*256]; mx = fmaxf(mx, lg[e]); }
        float sum = 0.f;
        #pragma unroll
        for (int e = 0; e < NEXP; e++) { p[e] = expf(lg[e] - mx); sum += p[e]; }
        float inv = 1.f / sum;
        #pragma unroll
        for (int e = 0; e < NEXP; e++) { p[e] *= inv; probs_out[(size_t)tok*NEXP + e] = p[e]; }
        int i0 = 0;
        #pragma unroll
        for (int e = 1; e < NEXP; e++) if (p[e] > p[i0]) i0 = e;
        int i1 = (i0 == 0) ? 1 : 0;
        #pragma unroll
        for (int e = 0; e < NEXP; e++) if (e != i0 && p[e] > p[i1]) i1 = e;
        float w0 = p[i0], w1 = p[i1];
        float sw = 1.f / (w0 + w1);
        w0 *= sw; w1 *= sw;
        int pos = atomicAdd(&g_cnt[i0], 1);
        g_tok[i0*NTOK + pos] = tok; g_wslot[i0*NTOK + pos] = w0;
        g_inv[tok*2] = i0*NTOK + pos;
        pos = atomicAdd(&g_cnt[i1], 1);
        g_tok[i1*NTOK + pos] = tok; g_wslot[i1*NTOK + pos] = w1;
        g_inv[tok*2+1] = i1*NTOK + pos;
    }
}

// ---------------- final: 2 contribs + residual + LN3 ----------------
__global__ void k_moe_final(const float* __restrict__ x2, const float* __restrict__ g,
                            const float* __restrict__ bb, float* __restrict__ out)
{
    int tok = blockIdx.x;
    int tid = threadIdx.x;
    __shared__ float buf[DIMD];
    __shared__ float r1[256], r2[256];
    const float* xp = x2 + (size_t)tok * DIMD;
    int iv0 = g_inv[tok*2], iv1 = g_inv[tok*2+1];
    const float* c0 = g_contrib + (size_t)iv0 * DIMD;
    const float* c1 = g_contrib + (size_t)iv1 * DIMD;
    float s = 0.f, ss = 0.f;
    #pragma unroll
    for (int i = 0; i < 4; i++) {
        int j = tid + i * 256;
        float v = xp[j] + c0[j] + c1[j];
        buf[j] = v; s += v; ss += v * v;
    }
    r1[tid] = s; r2[tid] = ss; __syncthreads();
    for (int st = 128; st > 0; st >>= 1) {
        if (tid < st) { r1[tid] += r1[tid+st]; r2[tid] += r2[tid+st]; }
        __syncthreads();
    }
    float mean = r1[0] * (1.f / DIMD);
    float var  = r2[0] * (1.f / DIMD) - mean * mean;
    float inv  = rsqrtf(var + 1e-5f);
    float* op = out + (size_t)tok * DIMD;
    #pragma unroll
    for (int i = 0; i < 4; i++) {
        int j = tid + i * 256;
        op[j] = (buf[j] - mean) * inv * g[j] + bb[j];
    }
}

// ---------------- per-expert masked token sums (partitioned) ----------------
__global__ void k_tsum()
{
    int part = blockIdx.x % TSPART;
    int b = (blockIdx.x / TSPART) % NB;
    int e = blockIdx.x / (TSPART * NB);
    int tid = threadIdx.x;
    const int CH = SLEN / TSPART;
    __shared__ int sslot[SLEN / TSPART];
    for (int j = tid; j < CH; j += 256) {
        int t = b*SLEN + part*CH + j;
        int s = -1;
        if (!(g_mtgt[t] | g_mmid[t])) {
            int a = g_inv[2*t], c = g_inv[2*t+1];
            if ((a >> 11) == e) s = a;
            else if ((c >> 11) == e) s = c;
        }
        sslot[j] = s;
    }
    __syncthreads();
    for (int d = tid; d < DIMD; d += 256) {
        float acc = 0.f;
        for (int j = 0; j < CH; j++) {
            int s = sslot[j];
            if (s >= 0) acc += g_contrib[(size_t)s * DIMD + d];
        }
        g_tsumP[(((e*NB + b)*TSPART) + part)*DIMD + d] = acc;
    }
}

// ---------------- expert logits ----------------
__global__ void k_logits(const float* __restrict__ cls_w, const float* __restrict__ cls_b,
                         float* __restrict__ out_logits)
{
    int tid = threadIdx.x;
    __shared__ float red[256];
    __shared__ float dss[NEXP*NB];
    __shared__ float den[NB];
    for (int b = 0; b < NB; b++) {
        float c = 0.f;
        for (int j = tid; j < SLEN; j += 256)
            c += (!(g_mtgt[b*SLEN+j] | g_mmid[b*SLEN+j])) ? 1.f : 0.f;
        red[tid] = c; __syncthreads();
        for (int s = 128; s > 0; s >>= 1) { if (tid < s) red[tid] += red[tid+s]; __syncthreads(); }
        if (tid == 0) den[b] = fmaxf(red[0], 1.f);
        __syncthreads();
    }
    for (int eb = 0; eb < NEXP*NB; eb++) {
        float c = 0.f;
        for (int j = tid; j < DIMD; j += 256) {
            float t = 0.f;
            #pragma unroll
            for (int part = 0; part < TSPART; part++)
                t += g_tsumP[(eb*TSPART + part)*DIMD + j];
            c += t * cls_w[j];
        }
        red[tid] = c; __syncthreads();
        for (int s = 128; s > 0; s >>= 1) { if (tid < s) red[tid] += red[tid+s]; __syncthreads(); }
        if (tid == 0) dss[eb] = red[0];
        __syncthreads();
    }
    if (tid == 0) {
        for (int b = 0; b < NB; b++) {
            float pre = 0.f;
            for (int e = 0; e < NEXP; e++) {
                pre += dss[e*NB + b];
                out_logits[e*NB + b] = pre / den[b] + cls_b[0];
            }
        }
    }
}

// ---------------- host ----------------
struct GArg {
    const bf *Ah, *Al, *Bh, *Bl;
    float* C; bf *Ch, *Cl;
    int M, N, K, lda, ldb, ldc;
    long long sA1, sA2, sB1, sB2, sC1, sC2;
    int gz, bdiv, zmaps, swig;
    const float* bias; const int* rmA; const int* rmC;
    const float* rs; const int* cnt;
};

static void BG(const GArg& a, cudaStream_t st = 0)
{
    dim3 grid(a.N / 128, (a.M + 127) / 128, a.gz);
    k_bgemm<<<grid, 256, BG_SMEM, st>>>(
        a.Ah, a.Al, a.Bh, a.Bl, a.C, a.Ch, a.Cl, a.M, a.N, a.K, a.lda, a.ldb, a.ldc,
        a.sA1, a.sA2, a.sB1, a.sB2, a.sC1, a.sC2, a.bdiv, a.zmaps, a.swig,
        a.bias, a.rmA, a.rmC, a.rs, a.cnt);
}

extern "C" void kernel_launch(void* const* d_in, const int* in_sizes, int n_in,
                              void* d_out, int out_size)
{
    const float* x       = (const float*)d_in[0];
    const float* enc     = (const float*)d_in[1];
    const void*  src_mask_raw = d_in[2];
    const void*  tgt_mask_raw = d_in[3];
    const void*  tgt_mid_raw  = d_in[4];
    const float* ln1_g = (const float*)d_in[5];
    const float* ln1_b = (const float*)d_in[6];
    const float* ln2_g = (const float*)d_in[7];
    const float* ln2_b = (const float*)d_in[8];
    const float* ln3_g = (const float*)d_in[9];
    const float* ln3_b = (const float*)d_in[10];
    const float* sa_wq = (const float*)d_in[11];
    const float* sa_wk = (const float*)d_in[12];
    const float* sa_wv = (const float*)d_in[13];
    const float* sa_wo = (const float*)d_in[14];
    const float* sa_bo = (const float*)d_in[15];
    const float* ca_wq = (const float*)d_in[16];
    const float* ca_wk = (const float*)d_in[17];
    const float* ca_wv = (const float*)d_in[18];
    const float* ca_wo = (const float*)d_in[19];
    const float* ca_bo = (const float*)d_in[20];
    const float* gate_w = (const float*)d_in[21];
    const float* cls_w  = (const float*)d_in[22];
    const float* cls_b  = (const float*)d_in[23];
    const float* moe_w1 = (const float*)d_in[24];
    const float* moe_w2 = (const float*)d_in[25];
    const float* moe_w3 = (const float*)d_in[26];

    float* out = (float*)d_out;
    float* out_x      = out;
    float* out_logits = out + (size_t)NTOK * DIMD;
    float* out_probs  = out_logits + NEXP * NB;

    cudaFuncSetAttribute(k_bgemm, cudaFuncAttributeMaxDynamicSharedMemorySize, BG_SMEM);
    cudaFuncSetAttribute(k_fattn, cudaFuncAttributeMaxDynamicSharedMemorySize, FATTN_SMEM);

    // side stream + events (created once, on the uncaptured correctness call)
    static cudaStream_t s2 = nullptr;
    static cudaEvent_t evFork = nullptr, evCA = nullptr, evKV = nullptr, evMOE = nullptr;
    static cudaEvent_t evCtr = nullptr, evTail = nullptr;
    if (!s2) {
        cudaStreamCreateWithFlags(&s2, cudaStreamNonBlocking);
        cudaEventCreateWithFlags(&evFork, cudaEventDisableTiming);
        cudaEventCreateWithFlags(&evCA,   cudaEventDisableTiming);
        cudaEventCreateWithFlags(&evKV,   cudaEventDisableTiming);
        cudaEventCreateWithFlags(&evMOE,  cudaEventDisableTiming);
        cudaEventCreateWithFlags(&evCtr,  cudaEventDisableTiming);
        cudaEventCreateWithFlags(&evTail, cudaEventDisableTiming);
    }

    float *pproj, *px1, *px2, *pcontrib, *pwslot;
    int *ptok, *pcnt;
    unsigned char *pmsrc, *pmtgt;
    bf *pxh,*pxl,*pawh,*pawl,*pw13h,*pw13l,*pw2h,*pw2l;
    bf *pqkvh,*pqkvl,*path,*patl,*px1h,*px1l,*px2h,*px2l,*pgh,*pgl;
    cudaGetSymbolAddress((void**)&pproj, g_proj);
    cudaGetSymbolAddress((void**)&px1, g_x1);
    cudaGetSymbolAddress((void**)&px2, g_x2);
    cudaGetSymbolAddress((void**)&pcontrib, g_contrib);
    cudaGetSymbolAddress((void**)&pwslot, g_wslot);
    cudaGetSymbolAddress((void**)&ptok, g_tok);
    cudaGetSymbolAddress((void**)&pcnt, g_cnt);
    cudaGetSymbolAddress((void**)&pmsrc, g_msrc);
    cudaGetSymbolAddress((void**)&pmtgt, g_mtgt);
    cudaGetSymbolAddress((void**)&pxh, g_xh);   cudaGetSymbolAddress((void**)&pxl, g_xl);
    cudaGetSymbolAddress((void**)&pawh, g_awh); cudaGetSymbolAddress((void**)&pawl, g_awl);
    cudaGetSymbolAddress((void**)&pw13h, g_w13h); cudaGetSymbolAddress((void**)&pw13l, g_w13l);
    cudaGetSymbolAddress((void**)&pw2h, g_w2h); cudaGetSymbolAddress((void**)&pw2l, g_w2l);
    cudaGetSymbolAddress((void**)&pqkvh, g_qkvh); cudaGetSymbolAddress((void**)&pqkvl, g_qkvl);
    cudaGetSymbolAddress((void**)&path, g_ath); cudaGetSymbolAddress((void**)&patl, g_atl);
    cudaGetSymbolAddress((void**)&px1h, g_x1h); cudaGetSymbolAddress((void**)&px1l, g_x1l);
    cudaGetSymbolAddress((void**)&px2h, g_x2h); cudaGetSymbolAddress((void**)&px2l, g_x2l);
    cudaGetSymbolAddress((void**)&pgh, g_gh);   cudaGetSymbolAddress((void**)&pgl, g_gl);

    bf* peh = px1h + (size_t)NTOK * DIMD;
    bf* pel = px1l + (size_t)NTOK * DIMD;
    bf* pqkv2h = pqkvh + (size_t)NTOK * QKVW;   // cross-attn qkv slice
    bf* pqkv2l = pqkvl + (size_t)NTOK * QKVW;

    const long long WMOE = (long long)DIMD * HIDD;
    const long long MM   = (long long)DIMD * INNERD;
    const long long W13  = 2LL * HIDD * DIMD;

    k_detect<<<1, 256>>>((const unsigned char*)tgt_mask_raw);
    // fork side stream
    cudaEventRecord(evFork, 0);
    cudaStreamWaitEvent(s2, evFork, 0);

    k_cvtmask<<<8, 256>>>(src_mask_raw, tgt_mask_raw, tgt_mid_raw);
    k_cvtA<<<512, 256>>>(x, pxh, pxl, NTOK*DIMD/4);
    const float* aw[8] = {sa_wq, sa_wk, sa_wv, sa_wo, ca_wq, ca_wk, ca_wv, ca_wo};
    // self-attn weights on main stream (needed first)
    for (int i = 0; i < 4; i++)
        k_cvtT<<<dim3(INNERD/64, DIMD/64, 1), dim3(16,16)>>>(aw[i], pawh + i*MM, pawl + i*MM, DIMD, INNERD, 0, 0, 1, 0);
    // side stream: enc conversion + cross weights, then cross K/V projection, then MoE weights
    k_cvtA<<<512, 256, 0, s2>>>(enc, peh, pel, NTOK*DIMD/4);
    for (int i = 4; i < 8; i++)
        k_cvtT<<<dim3(INNERD/64, DIMD/64, 1), dim3(16,16), 0, s2>>>(aw[i], pawh + i*MM, pawl + i*MM, DIMD, INNERD, 0, 0, 1, 0);
    cudaEventRecord(evCA, s2);

    GArg a{};
    // cross K/V projection on s2 (z=0->K via ca_wk, z=1->V via ca_wv; A=enc for both)
    // NOTE: bdiv=1 means z advances via the *2 strides (z/bdiv == z, z%bdiv == 0).
    a = GArg{}; a.gz = 2; a.bdiv = 1;
    a.Ah = peh; a.Al = pel;
    a.Bh = pawh + 5*MM; a.Bl = pawl + 5*MM;
    a.Ch = pqkv2h + INNERD; a.Cl = pqkv2l + INNERD;
    a.M = NTOK; a.N = INNERD; a.K = DIMD; a.lda = DIMD; a.ldb = DIMD; a.ldc = QKVW;
    a.sB2 = MM; a.sC2 = INNERD;     // <-- FIX: use s*2 strides (z/1 path), not s*1
    BG(a, s2);
    cudaEventRecord(evKV, s2);

    k_cvtT<<<dim3(HIDD/64, DIMD/64, NEXP), dim3(16,16), 0, s2>>>(moe_w1, pw13h, pw13l, DIMD, HIDD, WMOE, W13, 2, 0);
    k_cvtT<<<dim3(HIDD/64, DIMD/64, NEXP), dim3(16,16), 0, s2>>>(moe_w3, pw13h, pw13l, DIMD, HIDD, WMOE, W13, 2, 1);
    k_cvtT<<<dim3(DIMD/64, HIDD/64, NEXP), dim3(16,16), 0, s2>>>(moe_w2, pw2h, pw2l, HIDD, DIMD, WMOE, WMOE, 1, 0);
    cudaEventRecord(evMOE, s2);

    // ===== self attention =====
    a = GArg{}; a.gz = 1; a.bdiv = 1;
    a.Ah = pxh; a.Al = pxl; a.Bh = pawh; a.Bl = pawl;
    a.Ch = pqkvh; a.Cl = pqkvl;
    a.M = NTOK; a.N = QKVW; a.K = DIMD; a.lda = DIMD; a.ldb = DIMD; a.ldc = QKVW;
    BG(a);
    k_fattn<<<dim3(SLEN/128, HEADS, NB), 256, FATTN_SMEM>>>(
        pqkvh, pqkvl, path, patl, pmtgt);
    a = GArg{}; a.gz = 1; a.bdiv = 1;
    a.Ah = path; a.Al = patl; a.Bh = pawh + 3*MM; a.Bl = pawl + 3*MM;
    a.C = pproj; a.bias = sa_bo;
    a.M = NTOK; a.N = DIMD; a.K = INNERD; a.lda = INNERD; a.ldb = INNERD; a.ldc = DIMD;
    BG(a);
    k_addln<<<NTOK, 256>>>(x, pproj, ln1_g, ln1_b, px1, px1h, px1l);

    // ===== cross attention =====
    cudaStreamWaitEvent(0, evCA, 0);   // ca_wq converted (s2)
    a = GArg{}; a.gz = 1; a.bdiv = 1;
    a.Ah = px1h; a.Al = px1l;
    a.Bh = pawh + 4*MM; a.Bl = pawl + 4*MM;
    a.Ch = pqkv2h; a.Cl = pqkv2l;
    a.M = NTOK; a.N = INNERD; a.K = DIMD; a.lda = DIMD; a.ldb = DIMD; a.ldc = QKVW;
    BG(a);
    cudaStreamWaitEvent(0, evKV, 0);   // cross K/V ready (s2)
    k_fattn<<<dim3(SLEN/128, HEADS, NB), 256, FATTN_SMEM>>>(
        pqkv2h, pqkv2l, path, patl, pmsrc);
    a = GArg{}; a.gz = 1; a.bdiv = 1;
    a.Ah = path; a.Al = patl; a.Bh = pawh + 7*MM; a.Bl = pawl + 7*MM;
    a.C = pproj; a.bias = ca_bo;
    a.M = NTOK; a.N = DIMD; a.K = INNERD; a.lda = INNERD; a.ldb = INNERD; a.ldc = DIMD;
    BG(a);
    k_addln<<<NTOK, 256>>>(px1, pproj, ln2_g, ln2_b, px2, px2h, px2l);

    // ===== MoE =====
    k_route<<<NTOK, 256>>>(px2, gate_w, out_probs);
    cudaStreamWaitEvent(0, evMOE, 0);
    a = GArg{}; a.gz = NEXP; a.bdiv = NEXP; a.zmaps = 1; a.swig = 1;
    a.Ah = px2h; a.Al = px2l; a.Bh = pw13h; a.Bl = pw13l;
    a.Ch = pgh; a.Cl = pgl;
    a.M = NTOK; a.N = 2*HIDD; a.K = DIMD; a.lda = DIMD; a.ldb = DIMD; a.ldc = HIDD;
    a.sB1 = W13; a.sC1 = (long long)NTOK*HIDD;
    a.rmA = ptok; a.cnt = pcnt;
    BG(a);
    a = GArg{}; a.gz = NEXP; a.bdiv = NEXP; a.zmaps = 1;
    a.Ah = pgh; a.Al = pgl; a.Bh = pw2h; a.Bl = pw2l; a.C = pcontrib;
    a.M = NTOK; a.N = DIMD; a.K = HIDD; a.lda = HIDD; a.ldb = HIDD; a.ldc = DIMD;
    a.sA1 = (long long)NTOK*HIDD; a.sB1 = WMOE; a.sC1 = (long long)NTOK*DIMD;
    a.rs = pwslot; a.cnt = pcnt;
    BG(a);

    // tail fork: tsum+logits (out_logits) on s2 concurrent with moe_final (out_x)
    cudaEventRecord(evCtr, 0);
    cudaStreamWaitEvent(s2, evCtr, 0);
    k_tsum<<<NEXP*NB*TSPART, 256, 0, s2>>>();
    k_logits<<<1, 256, 0, s2>>>(cls_w, cls_b, out_logits);
    cudaEventRecord(evTail, s2);

    k_moe_final<<<NTOK, 256>>>(px2, ln3_g, ln3_b, out_x);
    cudaStreamWaitEvent(0, evTail, 0);
}